// round 1
// baseline (speedup 1.0000x reference)
#include <cuda_runtime.h>

#define NG 50000
#define NP 20000
#define NV 10000
#define NT 80000
#define HID 128
#define EPER 250000
#define ETOT (4*EPER + NT)
#define CDIV(a,b) (((a)+(b)-1)/(b))

// ------------------------- device scratch (static, no allocs) -------------------------
__device__ float g_hg[NG*HID];
__device__ float g_hp[NP*HID];
__device__ float g_hv[NV*HID];
__device__ float g_oG[NG*HID];
__device__ float g_oP[NP*HID];
__device__ float g_s [NG*HID];
__device__ float g_h0[NT*HID];
__device__ float g_zb[NT*HID];
__device__ float g_wt[256*HID];      // transposed weight staging (max K=256)
__device__ int   g_degi[NT];
__device__ float g_dinv[NT];
__device__ int   g_off[NT+1];
__device__ int   g_cur[NT];
__device__ int   g_csrc[ETOT];
__device__ float g_cnorm[ETOT];
__device__ int   g_roff_tg[NG+1];
__device__ int   g_roff_in[NP+1];
__device__ int   g_roff_ct[NG+1];
__device__ int   g_roff_ii[NG+1];
__device__ int   g_rsrc[4*EPER];
__device__ int   g_tmp[NG];

// ------------------------- small utility kernels -------------------------
__global__ void k_set_ones(int* p, int n) {
    int i = blockIdx.x * blockDim.x + threadIdx.x;
    if (i < n) p[i] = 1;
}

__global__ void k_hist(const int* __restrict__ dst, int E, int* __restrict__ degi, int off) {
    int e = blockIdx.x * blockDim.x + threadIdx.x;
    if (e < E) atomicAdd(&degi[off + dst[e]], 1);
}

__global__ void k_dinv(const int* __restrict__ degi, float* __restrict__ dinv, int n) {
    int i = blockIdx.x * blockDim.x + threadIdx.x;
    if (i < n) dinv[i] = rsqrtf((float)degi[i]);
}

// single-block exclusive scan (n up to 80000), off has n+1 entries
__global__ void k_scan_excl(const int* __restrict__ cnt, int* __restrict__ off, int n) {
    __shared__ int sh[1024];
    __shared__ int carry_s;
    int t = threadIdx.x;
    if (t == 0) carry_s = 0;
    __syncthreads();
    for (int base = 0; base < n; base += 1024) {
        int v = (base + t < n) ? cnt[base + t] : 0;
        sh[t] = v;
        __syncthreads();
        for (int o = 1; o < 1024; o <<= 1) {
            int x = (t >= o) ? sh[t - o] : 0;
            __syncthreads();
            sh[t] += x;
            __syncthreads();
        }
        int incl = sh[t];
        if (base + t < n) off[base + t] = carry_s + incl - v;
        __syncthreads();
        if (t == 0) carry_s += sh[1023];
        __syncthreads();
    }
    if (threadIdx.x == 0) off[n] = carry_s;
}

__global__ void k_scatter_csr(const int* __restrict__ src, const int* __restrict__ dst, int E,
                              const int* __restrict__ off, int* __restrict__ cur,
                              int* __restrict__ csr_src, float* __restrict__ csr_norm,
                              const float* __restrict__ dinv, int osrc, int odst) {
    int e = blockIdx.x * blockDim.x + threadIdx.x;
    if (e >= E) return;
    int r = src[e] + osrc;
    int c = dst[e] + odst;
    int pos = off[c] + atomicAdd(&cur[c], 1);
    csr_src[pos] = r;
    if (csr_norm) csr_norm[pos] = dinv[r] * dinv[c];
}

__global__ void k_scatter_loops(const int* __restrict__ off, int* __restrict__ cur,
                                int* __restrict__ csr_src, float* __restrict__ csr_norm,
                                const float* __restrict__ dinv, int n) {
    int i = blockIdx.x * blockDim.x + threadIdx.x;
    if (i >= n) return;
    int pos = off[i] + atomicAdd(&cur[i], 1);
    csr_src[pos] = i;
    float d = dinv[i];
    csr_norm[pos] = d * d;
}

// W[128,K] row-major -> Wt[K,128]
__global__ void k_transp(const float* __restrict__ W, float* __restrict__ Wt, int K) {
    int idx = blockIdx.x * blockDim.x + threadIdx.x;
    if (idx < 128 * K) {
        int k = idx >> 7;
        int n = idx & 127;
        Wt[idx] = W[n * K + k];
    }
}

// ------------------------- GEMM: out[M,128] (+)= A[M,K] @ Wt[K,128] (+bias) (relu) -------------------------
template<bool ACC, bool RELU>
__global__ __launch_bounds__(256)
void k_gemm(const float* __restrict__ A, const float* __restrict__ Wt,
            const float* __restrict__ bias, float* __restrict__ out, int M, int K)
{
    __shared__ __align__(16) float As[64][16];
    __shared__ __align__(16) float Ws[16][128];
    int tid = threadIdx.x;
    int tx = tid & 31;   // col group: cols tx*4 .. tx*4+3
    int ty = tid >> 5;   // row group: rows ty*8 .. ty*8+7
    int rowBase = blockIdx.x * 64;
    float acc[8][4];
#pragma unroll
    for (int i = 0; i < 8; i++)
#pragma unroll
        for (int j = 0; j < 4; j++) acc[i][j] = 0.f;

    for (int k0 = 0; k0 < K; k0 += 16) {
        // load A tile 64x16 (k-fast coalesced; store r-major, conflict-free)
#pragma unroll
        for (int i = 0; i < 4; i++) {
            int idx = i * 256 + tid;
            int r = idx >> 4, kk = idx & 15;
            int gr = rowBase + r;
            As[r][kk] = (gr < M) ? A[gr * K + k0 + kk] : 0.f;
        }
        // load W tile 16x128 from transposed weights (n-fast coalesced, conflict-free)
#pragma unroll
        for (int i = 0; i < 8; i++) {
            int idx = i * 256 + tid;
            int kk = idx >> 7, n = idx & 127;
            Ws[kk][n] = Wt[(k0 + kk) * 128 + n];
        }
        __syncthreads();
#pragma unroll
        for (int kk = 0; kk < 16; kk += 4) {
            float a_[8][4], b_[4][4];
#pragma unroll
            for (int i = 0; i < 8; i++) {
                float4 t = *(const float4*)&As[ty * 8 + i][kk];
                a_[i][0] = t.x; a_[i][1] = t.y; a_[i][2] = t.z; a_[i][3] = t.w;
            }
#pragma unroll
            for (int u = 0; u < 4; u++) {
                float4 t = *(const float4*)&Ws[kk + u][tx * 4];
                b_[u][0] = t.x; b_[u][1] = t.y; b_[u][2] = t.z; b_[u][3] = t.w;
            }
#pragma unroll
            for (int u = 0; u < 4; u++)
#pragma unroll
                for (int i = 0; i < 8; i++)
#pragma unroll
                    for (int j = 0; j < 4; j++)
                        acc[i][j] += a_[i][u] * b_[u][j];
        }
        __syncthreads();
    }
#pragma unroll
    for (int i = 0; i < 8; i++) {
        int gr = rowBase + ty * 8 + i;
        if (gr >= M) continue;
#pragma unroll
        for (int j = 0; j < 4; j++) {
            int n = tx * 4 + j;
            float v = acc[i][j];
            if (bias) v += bias[n];
            if (ACC) v += out[gr * HID + n];
            if (RELU) v = fmaxf(v, 0.f);
            out[gr * HID + n] = v;
        }
    }
}

// ------------------------- SAGE mean aggregation via CSR gather -------------------------
__global__ void k_gather_mean(const float* __restrict__ xsrc, const int* __restrict__ off,
                              const int* __restrict__ esrc, float* __restrict__ s) {
    int node = blockIdx.x;
    int c = threadIdx.x;
    int e0 = off[node], e1 = off[node + 1];
    float acc = 0.f;
    for (int e = e0; e < e1; e++)
        acc += xsrc[esrc[e] * HID + c];
    float cnt = (float)(e1 - e0);
    s[node * HID + c] = acc / fmaxf(cnt, 1.f);
}

// ------------------------- elementwise updates -------------------------
__global__ void k_upd_gene() {
    int i = blockIdx.x * blockDim.x + threadIdx.x;
    if (i < NG * HID) g_hg[i] = fmaxf(g_hg[i] + g_oG[i] * (1.0f / 3.0f), 0.f);
}
__global__ void k_upd_path() {
    int i = blockIdx.x * blockDim.x + threadIdx.x;
    if (i < NP * HID) g_hp[i] = fmaxf(g_hp[i] + g_oP[i], 0.f);
}

// ------------------------- APPNP step -------------------------
__global__ void k_appnp_step(const float* __restrict__ z, float* __restrict__ zn) {
    int node = blockIdx.x;
    int c = threadIdx.x;
    int e0 = g_off[node], e1 = g_off[node + 1];
    float acc = 0.f;
    for (int e = e0; e < e1; e++)
        acc += g_cnorm[e] * z[g_csrc[e] * HID + c];
    int idx = node * HID + c;
    zn[idx] = 0.9f * acc + 0.1f * g_h0[idx];
}

// ------------------------- host orchestration -------------------------
extern "C" void kernel_launch(void* const* d_in, const int* in_sizes, int n_in,
                              void* d_out, int out_size) {
    const float* x_gene  = (const float*)d_in[0];
    const float* x_path  = (const float*)d_in[1];
    const float* x_vacc  = (const float*)d_in[2];
    const float* win_g   = (const float*)d_in[3];
    const float* bin_g   = (const float*)d_in[4];
    const float* win_p   = (const float*)d_in[5];
    const float* bin_p   = (const float*)d_in[6];
    const float* win_v   = (const float*)d_in[7];
    const float* bin_v   = (const float*)d_in[8];
    const float* wsl     = (const float*)d_in[9];   // [2,4,128,128]
    const float* bsl     = (const float*)d_in[10];  // [2,4,128]
    const float* wsr     = (const float*)d_in[11];  // [2,4,128,128]
    const int*   ei_t    = (const int*)d_in[12];    // vaccine -> gene
    const int*   ei_in   = (const int*)d_in[13];    // gene -> pathway
    const int*   ei_ct   = (const int*)d_in[14];    // pathway -> gene
    const int*   ei_ii   = (const int*)d_in[15];    // gene -> gene
    float* out = (float*)d_out;

    float *hg, *hp, *hv, *oG, *oP, *s, *h0, *zb, *wt, *dinv, *cnorm;
    int *degi, *off, *cur, *csrc, *roff_tg, *roff_in, *roff_ct, *roff_ii, *rsrc, *tmp;
    cudaGetSymbolAddress((void**)&hg, g_hg);
    cudaGetSymbolAddress((void**)&hp, g_hp);
    cudaGetSymbolAddress((void**)&hv, g_hv);
    cudaGetSymbolAddress((void**)&oG, g_oG);
    cudaGetSymbolAddress((void**)&oP, g_oP);
    cudaGetSymbolAddress((void**)&s,  g_s);
    cudaGetSymbolAddress((void**)&h0, g_h0);
    cudaGetSymbolAddress((void**)&zb, g_zb);
    cudaGetSymbolAddress((void**)&wt, g_wt);
    cudaGetSymbolAddress((void**)&dinv, g_dinv);
    cudaGetSymbolAddress((void**)&cnorm, g_cnorm);
    cudaGetSymbolAddress((void**)&degi, g_degi);
    cudaGetSymbolAddress((void**)&off,  g_off);
    cudaGetSymbolAddress((void**)&cur,  g_cur);
    cudaGetSymbolAddress((void**)&csrc, g_csrc);
    cudaGetSymbolAddress((void**)&roff_tg, g_roff_tg);
    cudaGetSymbolAddress((void**)&roff_in, g_roff_in);
    cudaGetSymbolAddress((void**)&roff_ct, g_roff_ct);
    cudaGetSymbolAddress((void**)&roff_ii, g_roff_ii);
    cudaGetSymbolAddress((void**)&rsrc, g_rsrc);
    cudaGetSymbolAddress((void**)&tmp,  g_tmp);

    const int TB = 256;
    const int EB = CDIV(EPER, TB);

    // ---------- build per-relation CSRs (structure is layer-invariant) ----------
    auto build_rel = [&](const int* ei, int n_dst, int* roff, int* rsrc_out) {
        cudaMemsetAsync(tmp, 0, n_dst * sizeof(int));
        k_hist<<<EB, TB>>>(ei + EPER, EPER, tmp, 0);
        k_scan_excl<<<1, 1024>>>(tmp, roff, n_dst);
        cudaMemsetAsync(cur, 0, n_dst * sizeof(int));
        k_scatter_csr<<<EB, TB>>>(ei, ei + EPER, EPER, roff, cur, rsrc_out,
                                  (float*)0, (const float*)0, 0, 0);
    };
    build_rel(ei_t,  NG, roff_tg, rsrc + 0 * EPER);
    build_rel(ei_in, NP, roff_in, rsrc + 1 * EPER);
    build_rel(ei_ct, NG, roff_ct, rsrc + 2 * EPER);
    build_rel(ei_ii, NG, roff_ii, rsrc + 3 * EPER);

    // ---------- input projections (relu(x @ W^T + b)) ----------
    k_transp<<<CDIV(128 * 256, TB), TB>>>(win_g, wt, 256);
    k_gemm<false, true><<<CDIV(NG, 64), 256>>>(x_gene, wt, bin_g, hg, NG, 256);
    k_transp<<<CDIV(128 * 128, TB), TB>>>(win_p, wt, 128);
    k_gemm<false, true><<<CDIV(NP, 64), 256>>>(x_path, wt, bin_p, hp, NP, 128);
    k_transp<<<CDIV(128 * 64, TB), TB>>>(win_v, wt, 64);
    k_gemm<false, true><<<CDIV(NV, 64), 256>>>(x_vacc, wt, bin_v, hv, NV, 64);

    // ---------- 2 hetero SAGE layers ----------
    for (int l = 0; l < 2; l++) {
        cudaMemsetAsync(oG, 0, (size_t)NG * HID * sizeof(float));
        cudaMemsetAsync(oP, 0, (size_t)NP * HID * sizeof(float));
        const int W128 = CDIV(128 * 128, TB);
        // r=0: targets (hv -> gene)
        k_gather_mean<<<NG, HID>>>(hv, roff_tg, rsrc + 0 * EPER, s);
        k_transp<<<W128, TB>>>(wsl + (l * 4 + 0) * 16384, wt, 128);
        k_gemm<true, false><<<CDIV(NG, 64), 256>>>(s, wt, bsl + (l * 4 + 0) * 128, oG, NG, 128);
        k_transp<<<W128, TB>>>(wsr + (l * 4 + 0) * 16384, wt, 128);
        k_gemm<true, false><<<CDIV(NG, 64), 256>>>(hg, wt, (const float*)0, oG, NG, 128);
        // r=1: in (hg -> pathway)
        k_gather_mean<<<NP, HID>>>(hg, roff_in, rsrc + 1 * EPER, s);
        k_transp<<<W128, TB>>>(wsl + (l * 4 + 1) * 16384, wt, 128);
        k_gemm<true, false><<<CDIV(NP, 64), 256>>>(s, wt, bsl + (l * 4 + 1) * 128, oP, NP, 128);
        k_transp<<<W128, TB>>>(wsr + (l * 4 + 1) * 16384, wt, 128);
        k_gemm<true, false><<<CDIV(NP, 64), 256>>>(hp, wt, (const float*)0, oP, NP, 128);
        // r=2: contains (hp -> gene)
        k_gather_mean<<<NG, HID>>>(hp, roff_ct, rsrc + 2 * EPER, s);
        k_transp<<<W128, TB>>>(wsl + (l * 4 + 2) * 16384, wt, 128);
        k_gemm<true, false><<<CDIV(NG, 64), 256>>>(s, wt, bsl + (l * 4 + 2) * 128, oG, NG, 128);
        k_transp<<<W128, TB>>>(wsr + (l * 4 + 2) * 16384, wt, 128);
        k_gemm<true, false><<<CDIV(NG, 64), 256>>>(hg, wt, (const float*)0, oG, NG, 128);
        // r=3: interacts (hg -> gene)
        k_gather_mean<<<NG, HID>>>(hg, roff_ii, rsrc + 3 * EPER, s);
        k_transp<<<W128, TB>>>(wsl + (l * 4 + 3) * 16384, wt, 128);
        k_gemm<true, false><<<CDIV(NG, 64), 256>>>(s, wt, bsl + (l * 4 + 3) * 128, oG, NG, 128);
        k_transp<<<W128, TB>>>(wsr + (l * 4 + 3) * 16384, wt, 128);
        k_gemm<true, false><<<CDIV(NG, 64), 256>>>(hg, wt, (const float*)0, oG, NG, 128);
        // residual + relu updates (hv unchanged: relu is idempotent on relu output)
        k_upd_gene<<<CDIV(NG * HID, TB), TB>>>();
        k_upd_path<<<CDIV(NP * HID, TB), TB>>>();
    }

    // ---------- APPNP combined-graph CSR ----------
    k_set_ones<<<CDIV(NT, TB), TB>>>(degi, NT);  // self loops
    k_hist<<<EB, TB>>>(ei_t + EPER,  EPER, degi, 0);
    k_hist<<<EB, TB>>>(ei_in + EPER, EPER, degi, NG);
    k_hist<<<EB, TB>>>(ei_ct + EPER, EPER, degi, 0);
    k_hist<<<EB, TB>>>(ei_ii + EPER, EPER, degi, 0);
    k_dinv<<<CDIV(NT, TB), TB>>>(degi, dinv, NT);
    k_scan_excl<<<1, 1024>>>(degi, off, NT);
    cudaMemsetAsync(cur, 0, NT * sizeof(int));
    k_scatter_csr<<<EB, TB>>>(ei_t,  ei_t + EPER,  EPER, off, cur, csrc, cnorm, dinv, NG + NP, 0);
    k_scatter_csr<<<EB, TB>>>(ei_in, ei_in + EPER, EPER, off, cur, csrc, cnorm, dinv, 0, NG);
    k_scatter_csr<<<EB, TB>>>(ei_ct, ei_ct + EPER, EPER, off, cur, csrc, cnorm, dinv, NG, 0);
    k_scatter_csr<<<EB, TB>>>(ei_ii, ei_ii + EPER, EPER, off, cur, csrc, cnorm, dinv, 0, 0);
    k_scatter_loops<<<CDIV(NT, TB), TB>>>(off, cur, csrc, cnorm, dinv, NT);

    // h0 = concat(hg, hp, hv)
    cudaMemcpyAsync(h0,                    hg, (size_t)NG * HID * sizeof(float), cudaMemcpyDeviceToDevice);
    cudaMemcpyAsync(h0 + (size_t)NG * HID, hp, (size_t)NP * HID * sizeof(float), cudaMemcpyDeviceToDevice);
    cudaMemcpyAsync(h0 + (size_t)(NG + NP) * HID, hv, (size_t)NV * HID * sizeof(float), cudaMemcpyDeviceToDevice);

    // ---------- 8 APPNP iterations: even k -> zb, odd k -> d_out; step 7 (last) lands in d_out ----------
    for (int k = 0; k < 8; k++) {
        const float* zin = (k == 0) ? h0 : ((k & 1) ? zb : out);
        float* zout = (k & 1) ? out : zb;
        k_appnp_step<<<NT, HID>>>(zin, zout);
    }
}

// round 2
// speedup vs baseline: 1.7116x; 1.7116x over previous
#include <cuda_runtime.h>

#define NG 50000
#define NP 20000
#define NV 10000
#define NT 80000
#define HID 128
#define EPER 250000
#define ETOT (4*EPER + NT)
#define CDIV(a,b) (((a)+(b)-1)/(b))

// ------------------------- device scratch (static, no allocs) -------------------------
__device__ float g_hg[NG*HID];
__device__ float g_hp[NP*HID];
__device__ float g_hv[NV*HID];
__device__ float g_sg[NG*512];       // gene concat staging [NG,512]
__device__ float g_sp[NP*256];       // pathway concat staging [NP,256]
__device__ float g_h0[NT*HID];
__device__ float g_zb[NT*HID];
__device__ float g_wt [256*HID];     // transposed weight staging (input proj, max K=256)
__device__ float g_wtg[512*HID];     // gene concat weights
__device__ float g_wtp[256*HID];     // pathway concat weights
__device__ float g_bg[HID];          // combined gene bias
__device__ int   g_degi[NT];
__device__ float g_dinv[NT];
__device__ int   g_off[NT+1];
__device__ int   g_cur[NT];
__device__ int   g_csrc[ETOT];
__device__ float g_cnorm[ETOT];
__device__ int   g_roff_tg[NG+1];
__device__ int   g_roff_in[NP+1];
__device__ int   g_roff_ct[NG+1];
__device__ int   g_roff_ii[NG+1];
__device__ int   g_rsrc[4*EPER];
__device__ int   g_tmp[NG];

// ------------------------- small utility kernels -------------------------
__global__ void k_set_ones(int* p, int n) {
    int i = blockIdx.x * blockDim.x + threadIdx.x;
    if (i < n) p[i] = 1;
}

__global__ void k_hist(const int* __restrict__ dst, int E, int* __restrict__ degi, int off) {
    int e = blockIdx.x * blockDim.x + threadIdx.x;
    if (e < E) atomicAdd(&degi[off + dst[e]], 1);
}

__global__ void k_dinv(const int* __restrict__ degi, float* __restrict__ dinv, int n) {
    int i = blockIdx.x * blockDim.x + threadIdx.x;
    if (i < n) dinv[i] = rsqrtf((float)degi[i]);
}

// single-block exclusive scan: each thread owns a contiguous chunk (2-pass)
__global__ void k_scan_excl(const int* __restrict__ cnt, int* __restrict__ off, int n) {
    __shared__ int part[1024];
    int t = threadIdx.x;
    int chunk = (n + 1023) / 1024;
    int lo = t * chunk;
    int hi = min(lo + chunk, n);
    int s = 0;
    for (int i = lo; i < hi; i++) s += cnt[i];
    part[t] = s;
    __syncthreads();
    for (int o = 1; o < 1024; o <<= 1) {
        int x = (t >= o) ? part[t - o] : 0;
        __syncthreads();
        part[t] += x;
        __syncthreads();
    }
    int run = part[t] - s;   // exclusive prefix of this chunk
    for (int i = lo; i < hi; i++) { off[i] = run; run += cnt[i]; }
    if (t == 1023) off[n] = part[1023];
}

__global__ void k_scatter_csr(const int* __restrict__ src, const int* __restrict__ dst, int E,
                              const int* __restrict__ off, int* __restrict__ cur,
                              int* __restrict__ csr_src, float* __restrict__ csr_norm,
                              const float* __restrict__ dinv, int osrc, int odst) {
    int e = blockIdx.x * blockDim.x + threadIdx.x;
    if (e >= E) return;
    int r = src[e] + osrc;
    int c = dst[e] + odst;
    int pos = off[c] + atomicAdd(&cur[c], 1);
    csr_src[pos] = r;
    if (csr_norm) csr_norm[pos] = dinv[r] * dinv[c];
}

__global__ void k_scatter_loops(const int* __restrict__ off, int* __restrict__ cur,
                                int* __restrict__ csr_src, float* __restrict__ csr_norm,
                                const float* __restrict__ dinv, int n) {
    int i = blockIdx.x * blockDim.x + threadIdx.x;
    if (i >= n) return;
    int pos = off[i] + atomicAdd(&cur[i], 1);
    csr_src[pos] = i;
    float d = dinv[i];
    csr_norm[pos] = d * d;
}

// W[128,K] row-major -> Wt[K,128]
__global__ void k_transp(const float* __restrict__ W, float* __restrict__ Wt, int K) {
    int idx = blockIdx.x * blockDim.x + threadIdx.x;
    if (idx < 128 * K) {
        int k = idx >> 7;
        int n = idx & 127;
        Wt[idx] = W[n * K + k];
    }
}

// build gene concat weight [512,128]: blocks: wl(tg), wl(ct), wl(ii), wr0+wr2+wr3; and bias sum
__global__ void k_build_wtg(const float* __restrict__ wsl, const float* __restrict__ wsr,
                            const float* __restrict__ bsl, int l,
                            float* __restrict__ wtg, float* __restrict__ bg) {
    int idx = blockIdx.x * blockDim.x + threadIdx.x;
    if (idx < 512 * 128) {
        int k = idx >> 7, n = idx & 127;
        int b = k >> 7, kk = k & 127;
        float v;
        if (b == 0)      v = wsl[((l * 4 + 0) * 128 + n) * 128 + kk];
        else if (b == 1) v = wsl[((l * 4 + 2) * 128 + n) * 128 + kk];
        else if (b == 2) v = wsl[((l * 4 + 3) * 128 + n) * 128 + kk];
        else             v = wsr[((l * 4 + 0) * 128 + n) * 128 + kk]
                           + wsr[((l * 4 + 2) * 128 + n) * 128 + kk]
                           + wsr[((l * 4 + 3) * 128 + n) * 128 + kk];
        wtg[idx] = v;
    }
    if (idx < 128) {
        bg[idx] = bsl[(l * 4 + 0) * 128 + idx] + bsl[(l * 4 + 2) * 128 + idx]
                + bsl[(l * 4 + 3) * 128 + idx];
    }
}

// build pathway concat weight [256,128]: wl(in), wr(in)
__global__ void k_build_wtp(const float* __restrict__ wsl, const float* __restrict__ wsr,
                            int l, float* __restrict__ wtp) {
    int idx = blockIdx.x * blockDim.x + threadIdx.x;
    if (idx < 256 * 128) {
        int k = idx >> 7, n = idx & 127;
        int b = k >> 7, kk = k & 127;
        float v = (b == 0) ? wsl[((l * 4 + 1) * 128 + n) * 128 + kk]
                           : wsr[((l * 4 + 1) * 128 + n) * 128 + kk];
        wtp[idx] = v;
    }
}

// ------------------------- GEMM: out[M,128] = f(A[M,K] @ Wt[K,128]) -------------------------
// double-buffered; RES: out = relu(res + (acc+bias)*scale); else out = relu(acc+bias)
template<bool RES>
__global__ __launch_bounds__(256)
void k_gemm(const float* __restrict__ A, const float* __restrict__ Wt,
            const float* __restrict__ bias, const float* __restrict__ res,
            float* __restrict__ out, int M, int K, float scale)
{
    __shared__ __align__(16) float As[2][64][16];
    __shared__ __align__(16) float Ws[2][16][128];
    int tid = threadIdx.x;
    int tx = tid & 31;    // col group: cols tx*4..tx*4+3
    int ty = tid >> 5;    // row group: rows ty*8..ty*8+7
    int rowBase = blockIdx.x * 64;
    int ra = tid >> 2;            // A load: row 0..63
    int ka = (tid & 3) * 4;       // A load: k offset 0,4,8,12
    int kw = tid >> 4;            // W load: k 0..15
    int nw = (tid & 15) * 8;      // W load: n offset

    float acc[8][4];
#pragma unroll
    for (int i = 0; i < 8; i++)
#pragma unroll
        for (int j = 0; j < 4; j++) acc[i][j] = 0.f;

    int gr_ld = rowBase + ra;
    // preload tile 0
    {
        float4 a0 = (gr_ld < M) ? *(const float4*)&A[(size_t)gr_ld * K + ka]
                                : make_float4(0.f, 0.f, 0.f, 0.f);
        float4 w0 = *(const float4*)&Wt[kw * 128 + nw];
        float4 w1 = *(const float4*)&Wt[kw * 128 + nw + 4];
        *(float4*)&As[0][ra][ka] = a0;
        *(float4*)&Ws[0][kw][nw] = w0;
        *(float4*)&Ws[0][kw][nw + 4] = w1;
    }
    __syncthreads();

    int nt = K >> 4;
    for (int t = 0; t < nt; t++) {
        int cur = t & 1, nxt = cur ^ 1;
        float4 an = make_float4(0.f, 0.f, 0.f, 0.f), wn0, wn1;
        bool more = (t + 1 < nt);
        if (more) {
            int k0 = (t + 1) << 4;
            if (gr_ld < M) an = *(const float4*)&A[(size_t)gr_ld * K + k0 + ka];
            wn0 = *(const float4*)&Wt[(k0 + kw) * 128 + nw];
            wn1 = *(const float4*)&Wt[(k0 + kw) * 128 + nw + 4];
        }
#pragma unroll
        for (int kk = 0; kk < 16; kk += 4) {
            float a_[8][4], b_[4][4];
#pragma unroll
            for (int i = 0; i < 8; i++) {
                float4 v = *(const float4*)&As[cur][ty * 8 + i][kk];
                a_[i][0] = v.x; a_[i][1] = v.y; a_[i][2] = v.z; a_[i][3] = v.w;
            }
#pragma unroll
            for (int u = 0; u < 4; u++) {
                float4 v = *(const float4*)&Ws[cur][kk + u][tx * 4];
                b_[u][0] = v.x; b_[u][1] = v.y; b_[u][2] = v.z; b_[u][3] = v.w;
            }
#pragma unroll
            for (int u = 0; u < 4; u++)
#pragma unroll
                for (int i = 0; i < 8; i++)
#pragma unroll
                    for (int j = 0; j < 4; j++)
                        acc[i][j] += a_[i][u] * b_[u][j];
        }
        if (more) {
            *(float4*)&As[nxt][ra][ka] = an;
            *(float4*)&Ws[nxt][kw][nw] = wn0;
            *(float4*)&Ws[nxt][kw][nw + 4] = wn1;
        }
        __syncthreads();
    }

#pragma unroll
    for (int i = 0; i < 8; i++) {
        int gr = rowBase + ty * 8 + i;
        if (gr >= M) continue;
#pragma unroll
        for (int j = 0; j < 4; j++) {
            int n = tx * 4 + j;
            float v = acc[i][j] + bias[n];
            if (RES) v = res[(size_t)gr * HID + n] + v * scale;
            v = fmaxf(v, 0.f);
            out[(size_t)gr * HID + n] = v;
        }
    }
}

// ------------------------- SAGE mean aggregation (float4, 32 threads/node) -------------------------
__global__ void k_gather_mean4(const float4* __restrict__ xsrc, const int* __restrict__ off,
                               const int* __restrict__ esrc, float4* __restrict__ dst,
                               int n_node, int stride4, int col4) {
    int t = blockIdx.x * blockDim.x + threadIdx.x;
    int lane = t & 31, node = t >> 5;
    if (node >= n_node) return;
    int e0 = off[node], e1 = off[node + 1];
    float4 a = make_float4(0.f, 0.f, 0.f, 0.f);
    for (int e = e0; e < e1; e++) {
        float4 v = __ldg(&xsrc[esrc[e] * 32 + lane]);
        a.x += v.x; a.y += v.y; a.z += v.z; a.w += v.w;
    }
    float inv = 1.f / fmaxf((float)(e1 - e0), 1.f);
    a.x *= inv; a.y *= inv; a.z *= inv; a.w *= inv;
    dst[(size_t)node * stride4 + col4 + lane] = a;
}

__global__ void k_copy_block4(const float4* __restrict__ src, float4* __restrict__ dst,
                              int n_node, int stride4, int col4) {
    int t = blockIdx.x * blockDim.x + threadIdx.x;
    int lane = t & 31, node = t >> 5;
    if (node >= n_node) return;
    dst[(size_t)node * stride4 + col4 + lane] = src[node * 32 + lane];
}

// ------------------------- APPNP step (float4, 32 threads/node) -------------------------
__global__ void k_appnp_step4(const float4* __restrict__ z, float4* __restrict__ zn,
                              const float4* __restrict__ h0) {
    int t = blockIdx.x * blockDim.x + threadIdx.x;
    int lane = t & 31, node = t >> 5;
    if (node >= NT) return;
    int e0 = g_off[node], e1 = g_off[node + 1];
    float4 a = make_float4(0.f, 0.f, 0.f, 0.f);
    for (int e = e0; e < e1; e++) {
        float w = g_cnorm[e];
        float4 v = __ldg(&z[g_csrc[e] * 32 + lane]);
        a.x += w * v.x; a.y += w * v.y; a.z += w * v.z; a.w += w * v.w;
    }
    int idx = node * 32 + lane;
    float4 h = h0[idx];
    float4 o;
    o.x = 0.9f * a.x + 0.1f * h.x;
    o.y = 0.9f * a.y + 0.1f * h.y;
    o.z = 0.9f * a.z + 0.1f * h.z;
    o.w = 0.9f * a.w + 0.1f * h.w;
    zn[idx] = o;
}

// ------------------------- host orchestration -------------------------
extern "C" void kernel_launch(void* const* d_in, const int* in_sizes, int n_in,
                              void* d_out, int out_size) {
    const float* x_gene  = (const float*)d_in[0];
    const float* x_path  = (const float*)d_in[1];
    const float* x_vacc  = (const float*)d_in[2];
    const float* win_g   = (const float*)d_in[3];
    const float* bin_g   = (const float*)d_in[4];
    const float* win_p   = (const float*)d_in[5];
    const float* bin_p   = (const float*)d_in[6];
    const float* win_v   = (const float*)d_in[7];
    const float* bin_v   = (const float*)d_in[8];
    const float* wsl     = (const float*)d_in[9];   // [2,4,128,128]
    const float* bsl     = (const float*)d_in[10];  // [2,4,128]
    const float* wsr     = (const float*)d_in[11];  // [2,4,128,128]
    const int*   ei_t    = (const int*)d_in[12];    // vaccine -> gene
    const int*   ei_in   = (const int*)d_in[13];    // gene -> pathway
    const int*   ei_ct   = (const int*)d_in[14];    // pathway -> gene
    const int*   ei_ii   = (const int*)d_in[15];    // gene -> gene
    float* out = (float*)d_out;

    float *hg, *hp, *hv, *sg, *sp, *h0, *zb, *wt, *wtg, *wtp, *bg, *dinv, *cnorm;
    int *degi, *off, *cur, *csrc, *roff_tg, *roff_in, *roff_ct, *roff_ii, *rsrc, *tmp;
    cudaGetSymbolAddress((void**)&hg, g_hg);
    cudaGetSymbolAddress((void**)&hp, g_hp);
    cudaGetSymbolAddress((void**)&hv, g_hv);
    cudaGetSymbolAddress((void**)&sg, g_sg);
    cudaGetSymbolAddress((void**)&sp, g_sp);
    cudaGetSymbolAddress((void**)&h0, g_h0);
    cudaGetSymbolAddress((void**)&zb, g_zb);
    cudaGetSymbolAddress((void**)&wt,  g_wt);
    cudaGetSymbolAddress((void**)&wtg, g_wtg);
    cudaGetSymbolAddress((void**)&wtp, g_wtp);
    cudaGetSymbolAddress((void**)&bg,  g_bg);
    cudaGetSymbolAddress((void**)&dinv, g_dinv);
    cudaGetSymbolAddress((void**)&cnorm, g_cnorm);
    cudaGetSymbolAddress((void**)&degi, g_degi);
    cudaGetSymbolAddress((void**)&off,  g_off);
    cudaGetSymbolAddress((void**)&cur,  g_cur);
    cudaGetSymbolAddress((void**)&csrc, g_csrc);
    cudaGetSymbolAddress((void**)&roff_tg, g_roff_tg);
    cudaGetSymbolAddress((void**)&roff_in, g_roff_in);
    cudaGetSymbolAddress((void**)&roff_ct, g_roff_ct);
    cudaGetSymbolAddress((void**)&roff_ii, g_roff_ii);
    cudaGetSymbolAddress((void**)&rsrc, g_rsrc);
    cudaGetSymbolAddress((void**)&tmp,  g_tmp);

    const int TB = 256;
    const int EB = CDIV(EPER, TB);

    // ---------- per-relation CSRs ----------
    auto build_rel = [&](const int* ei, int n_dst, int* roff, int* rsrc_out) {
        cudaMemsetAsync(tmp, 0, n_dst * sizeof(int));
        k_hist<<<EB, TB>>>(ei + EPER, EPER, tmp, 0);
        k_scan_excl<<<1, 1024>>>(tmp, roff, n_dst);
        cudaMemsetAsync(cur, 0, n_dst * sizeof(int));
        k_scatter_csr<<<EB, TB>>>(ei, ei + EPER, EPER, roff, cur, rsrc_out,
                                  (float*)0, (const float*)0, 0, 0);
    };
    build_rel(ei_t,  NG, roff_tg, rsrc + 0 * EPER);
    build_rel(ei_in, NP, roff_in, rsrc + 1 * EPER);
    build_rel(ei_ct, NG, roff_ct, rsrc + 2 * EPER);
    build_rel(ei_ii, NG, roff_ii, rsrc + 3 * EPER);

    // ---------- input projections relu(x @ W^T + b) ----------
    k_transp<<<CDIV(128 * 256, TB), TB>>>(win_g, wt, 256);
    k_gemm<false><<<CDIV(NG, 64), 256>>>(x_gene, wt, bin_g, (const float*)0, hg, NG, 256, 1.f);
    k_transp<<<CDIV(128 * 128, TB), TB>>>(win_p, wt, 128);
    k_gemm<false><<<CDIV(NP, 64), 256>>>(x_path, wt, bin_p, (const float*)0, hp, NP, 128, 1.f);
    k_transp<<<CDIV(128 * 64, TB), TB>>>(win_v, wt, 64);
    k_gemm<false><<<CDIV(NV, 64), 256>>>(x_vacc, wt, bin_v, (const float*)0, hv, NV, 64, 1.f);

    // ---------- 2 hetero SAGE layers (fused per-type GEMMs) ----------
    const int GBG = CDIV(NG * 32, TB);   // gather grids
    const int GBP = CDIV(NP * 32, TB);
    for (int l = 0; l < 2; l++) {
        k_build_wtg<<<CDIV(512 * 128, TB), TB>>>(wsl, wsr, bsl, l, wtg, bg);
        k_build_wtp<<<CDIV(256 * 128, TB), TB>>>(wsl, wsr, l, wtp);
        // gene staging sg[NG,512]: [agg(hv,tg) | agg(hp,ct) | agg(hg,ii) | hg]
        k_gather_mean4<<<GBG, TB>>>((const float4*)hv, roff_tg, rsrc + 0 * EPER,
                                    (float4*)sg, NG, 128, 0);
        k_gather_mean4<<<GBG, TB>>>((const float4*)hp, roff_ct, rsrc + 2 * EPER,
                                    (float4*)sg, NG, 128, 32);
        k_gather_mean4<<<GBG, TB>>>((const float4*)hg, roff_ii, rsrc + 3 * EPER,
                                    (float4*)sg, NG, 128, 64);
        k_copy_block4<<<GBG, TB>>>((const float4*)hg, (float4*)sg, NG, 128, 96);
        // pathway staging sp[NP,256]: [agg(hg,in) | hp]
        k_gather_mean4<<<GBP, TB>>>((const float4*)hg, roff_in, rsrc + 1 * EPER,
                                    (float4*)sp, NP, 64, 0);
        k_copy_block4<<<GBP, TB>>>((const float4*)hp, (float4*)sp, NP, 64, 32);
        // fused GEMM + residual + relu (in-place update of hg/hp)
        k_gemm<true><<<CDIV(NG, 64), 256>>>(sg, wtg, bg, hg, hg, NG, 512, 1.f / 3.f);
        k_gemm<true><<<CDIV(NP, 64), 256>>>(sp, wtp, bsl + (l * 4 + 1) * 128, hp, hp, NP, 256, 1.f);
        // hv: relu of relu output -> unchanged
    }

    // ---------- APPNP combined CSR ----------
    k_set_ones<<<CDIV(NT, TB), TB>>>(degi, NT);
    k_hist<<<EB, TB>>>(ei_t + EPER,  EPER, degi, 0);
    k_hist<<<EB, TB>>>(ei_in + EPER, EPER, degi, NG);
    k_hist<<<EB, TB>>>(ei_ct + EPER, EPER, degi, 0);
    k_hist<<<EB, TB>>>(ei_ii + EPER, EPER, degi, 0);
    k_dinv<<<CDIV(NT, TB), TB>>>(degi, dinv, NT);
    k_scan_excl<<<1, 1024>>>(degi, off, NT);
    cudaMemsetAsync(cur, 0, NT * sizeof(int));
    k_scatter_csr<<<EB, TB>>>(ei_t,  ei_t + EPER,  EPER, off, cur, csrc, cnorm, dinv, NG + NP, 0);
    k_scatter_csr<<<EB, TB>>>(ei_in, ei_in + EPER, EPER, off, cur, csrc, cnorm, dinv, 0, NG);
    k_scatter_csr<<<EB, TB>>>(ei_ct, ei_ct + EPER, EPER, off, cur, csrc, cnorm, dinv, NG, 0);
    k_scatter_csr<<<EB, TB>>>(ei_ii, ei_ii + EPER, EPER, off, cur, csrc, cnorm, dinv, 0, 0);
    k_scatter_loops<<<CDIV(NT, TB), TB>>>(off, cur, csrc, cnorm, dinv, NT);

    // h0 = concat(hg, hp, hv)
    cudaMemcpyAsync(h0,                           hg, (size_t)NG * HID * sizeof(float), cudaMemcpyDeviceToDevice);
    cudaMemcpyAsync(h0 + (size_t)NG * HID,        hp, (size_t)NP * HID * sizeof(float), cudaMemcpyDeviceToDevice);
    cudaMemcpyAsync(h0 + (size_t)(NG + NP) * HID, hv, (size_t)NV * HID * sizeof(float), cudaMemcpyDeviceToDevice);

    // ---------- 8 APPNP iterations; last (k=7, odd) lands in d_out ----------
    const int AB = CDIV(NT * 32, TB);
    for (int k = 0; k < 8; k++) {
        const float* zin = (k == 0) ? h0 : ((k & 1) ? zb : out);
        float* zout = (k & 1) ? out : zb;
        k_appnp_step4<<<AB, TB>>>((const float4*)zin, (float4*)zout, (const float4*)h0);
    }
}

// round 3
// speedup vs baseline: 2.2754x; 1.3294x over previous
#include <cuda_runtime.h>
#include <cstdint>

#define NG 50000
#define NP 20000
#define NV 10000
#define NT 80000
#define HID 128
#define EPER 250000
#define ETOT (4*EPER + NT)
#define CDIV(a,b) (((a)+(b)-1)/(b))

// ------------------------- device scratch (static, no allocs) -------------------------
__device__ float g_hg[NG*HID];
__device__ float g_hp[NP*HID];
__device__ float g_hv[NV*HID];
__device__ float g_sg[NG*512];       // gene concat staging [NG,512]
__device__ float g_sp[NP*256];       // pathway concat staging [NP,256]
__device__ float g_h0[NT*HID];
__device__ float g_zb[NT*HID];
__device__ float g_wt [256*HID];     // transposed weight staging (input proj, max K=256)
__device__ float g_wtg[512*HID];     // gene concat weights
__device__ float g_wtp[256*HID];     // pathway concat weights
__device__ float g_bg[HID];          // combined gene bias
__device__ int   g_degi[NT];
__device__ float g_dinv[NT];
__device__ int   g_off[NT+1];
__device__ int   g_cur[NT];
__device__ int   g_csrc[ETOT];
__device__ float g_cnorm[ETOT];
__device__ int   g_roff_tg[NG+1];
__device__ int   g_roff_in[NP+1];
__device__ int   g_roff_ct[NG+1];
__device__ int   g_roff_ii[NG+1];
__device__ int   g_rsrc[4*EPER];
__device__ int   g_tmp[NG];

// ------------------------- small utility kernels -------------------------
__global__ void k_set_ones(int* p, int n) {
    int i = blockIdx.x * blockDim.x + threadIdx.x;
    if (i < n) p[i] = 1;
}

__global__ void k_hist(const int* __restrict__ dst, int E, int* __restrict__ degi, int off) {
    int e = blockIdx.x * blockDim.x + threadIdx.x;
    if (e < E) atomicAdd(&degi[off + dst[e]], 1);
}

__global__ void k_dinv(const int* __restrict__ degi, float* __restrict__ dinv, int n) {
    int i = blockIdx.x * blockDim.x + threadIdx.x;
    if (i < n) dinv[i] = rsqrtf((float)degi[i]);
}

// single-block exclusive scan: each thread owns a contiguous chunk (2-pass)
__global__ void k_scan_excl(const int* __restrict__ cnt, int* __restrict__ off, int n) {
    __shared__ int part[1024];
    int t = threadIdx.x;
    int chunk = (n + 1023) / 1024;
    int lo = t * chunk;
    int hi = min(lo + chunk, n);
    int s = 0;
    for (int i = lo; i < hi; i++) s += cnt[i];
    part[t] = s;
    __syncthreads();
    for (int o = 1; o < 1024; o <<= 1) {
        int x = (t >= o) ? part[t - o] : 0;
        __syncthreads();
        part[t] += x;
        __syncthreads();
    }
    int run = part[t] - s;
    for (int i = lo; i < hi; i++) { off[i] = run; run += cnt[i]; }
    if (t == 1023) off[n] = part[1023];
}

__global__ void k_scatter_csr(const int* __restrict__ src, const int* __restrict__ dst, int E,
                              const int* __restrict__ off, int* __restrict__ cur,
                              int* __restrict__ csr_src, float* __restrict__ csr_norm,
                              const float* __restrict__ dinv, int osrc, int odst) {
    int e = blockIdx.x * blockDim.x + threadIdx.x;
    if (e >= E) return;
    int r = src[e] + osrc;
    int c = dst[e] + odst;
    int pos = off[c] + atomicAdd(&cur[c], 1);
    csr_src[pos] = r;
    if (csr_norm) csr_norm[pos] = dinv[r] * dinv[c];
}

__global__ void k_scatter_loops(const int* __restrict__ off, int* __restrict__ cur,
                                int* __restrict__ csr_src, float* __restrict__ csr_norm,
                                const float* __restrict__ dinv, int n) {
    int i = blockIdx.x * blockDim.x + threadIdx.x;
    if (i >= n) return;
    int pos = off[i] + atomicAdd(&cur[i], 1);
    csr_src[pos] = i;
    float d = dinv[i];
    csr_norm[pos] = d * d;
}

// W[128,K] row-major -> Wt[K,128]
__global__ void k_transp(const float* __restrict__ W, float* __restrict__ Wt, int K) {
    int idx = blockIdx.x * blockDim.x + threadIdx.x;
    if (idx < 128 * K) {
        int k = idx >> 7;
        int n = idx & 127;
        Wt[idx] = W[n * K + k];
    }
}

// build gene concat weight [512,128]: blocks: wl(tg), wl(ct), wl(ii), wr0+wr2+wr3; and bias sum
__global__ void k_build_wtg(const float* __restrict__ wsl, const float* __restrict__ wsr,
                            const float* __restrict__ bsl, int l,
                            float* __restrict__ wtg, float* __restrict__ bg) {
    int idx = blockIdx.x * blockDim.x + threadIdx.x;
    if (idx < 512 * 128) {
        int k = idx >> 7, n = idx & 127;
        int b = k >> 7, kk = k & 127;
        float v;
        if (b == 0)      v = wsl[((l * 4 + 0) * 128 + n) * 128 + kk];
        else if (b == 1) v = wsl[((l * 4 + 2) * 128 + n) * 128 + kk];
        else if (b == 2) v = wsl[((l * 4 + 3) * 128 + n) * 128 + kk];
        else             v = wsr[((l * 4 + 0) * 128 + n) * 128 + kk]
                           + wsr[((l * 4 + 2) * 128 + n) * 128 + kk]
                           + wsr[((l * 4 + 3) * 128 + n) * 128 + kk];
        wtg[idx] = v;
    }
    if (idx < 128) {
        bg[idx] = bsl[(l * 4 + 0) * 128 + idx] + bsl[(l * 4 + 2) * 128 + idx]
                + bsl[(l * 4 + 3) * 128 + idx];
    }
}

// build pathway concat weight [256,128]: wl(in), wr(in)
__global__ void k_build_wtp(const float* __restrict__ wsl, const float* __restrict__ wsr,
                            int l, float* __restrict__ wtp) {
    int idx = blockIdx.x * blockDim.x + threadIdx.x;
    if (idx < 256 * 128) {
        int k = idx >> 7, n = idx & 127;
        int b = k >> 7, kk = k & 127;
        float v = (b == 0) ? wsl[((l * 4 + 1) * 128 + n) * 128 + kk]
                           : wsr[((l * 4 + 1) * 128 + n) * 128 + kk];
        wtp[idx] = v;
    }
}

// ------------------------- TF32 tensor-core GEMM -------------------------
// out[M,128] = f(A[M,K] @ Wt[K,128]); RES: out = relu(res + (acc+bias)*scale)
__device__ __forceinline__ uint32_t f2tf(float x) {
    uint32_t r;
    asm("cvt.rna.tf32.f32 %0, %1;" : "=r"(r) : "f"(x));
    return r;
}
__device__ __forceinline__ void mma_tf32(float c[4], uint32_t a0, uint32_t a1,
                                         uint32_t a2, uint32_t a3,
                                         uint32_t b0, uint32_t b1) {
    asm volatile(
        "mma.sync.aligned.m16n8k8.row.col.f32.tf32.tf32.f32 "
        "{%0,%1,%2,%3}, {%4,%5,%6,%7}, {%8,%9}, {%0,%1,%2,%3};"
        : "+f"(c[0]), "+f"(c[1]), "+f"(c[2]), "+f"(c[3])
        : "r"(a0), "r"(a1), "r"(a2), "r"(a3), "r"(b0), "r"(b1));
}

#define AST 20   // A smem row stride (conflict-free for frag loads)
#define BST 136  // B smem row stride

template<bool RES>
__global__ __launch_bounds__(256)
void k_gemm_tc(const float* __restrict__ A, const float* __restrict__ Wt,
               const float* __restrict__ bias, const float* __restrict__ res,
               float* __restrict__ out, int M, int K, float scale)
{
    __shared__ uint32_t As[2][128][AST];
    __shared__ uint32_t Bs[2][16][BST];

    int tid  = threadIdx.x;
    int lane = tid & 31;
    int wid  = tid >> 5;
    int wm = wid >> 2;          // 0..1 -> 64 rows each
    int wn = wid & 3;           // 0..3 -> 32 cols each
    int g   = lane >> 2;        // groupID 0..7
    int tig = lane & 3;         // thread in group 0..3

    int rowBase = blockIdx.x * 128;

    // load mappings
    int a_r  = tid >> 2;            // 0..63 (and +64)
    int a_kq = (tid & 3) * 4;       // k quad
    int b_r  = tid >> 5;            // 0..7 (and +8)
    int b_c  = (tid & 31) * 4;      // col quad

    float acc[4][4][4];
#pragma unroll
    for (int mt = 0; mt < 4; mt++)
#pragma unroll
        for (int nt = 0; nt < 4; nt++)
#pragma unroll
            for (int r = 0; r < 4; r++) acc[mt][nt][r] = 0.f;

    int ntk = K >> 4;

    // preload tile 0
    {
        int gr0 = rowBase + a_r, gr1 = gr0 + 64;
        float4 a0 = (gr0 < M) ? *(const float4*)&A[(size_t)gr0 * K + a_kq] : make_float4(0,0,0,0);
        float4 a1 = (gr1 < M) ? *(const float4*)&A[(size_t)gr1 * K + a_kq] : make_float4(0,0,0,0);
        float4 b0 = *(const float4*)&Wt[(size_t)b_r * 128 + b_c];
        float4 b1 = *(const float4*)&Wt[(size_t)(b_r + 8) * 128 + b_c];
        uint32_t* pa0 = &As[0][a_r][a_kq];
        pa0[0]=f2tf(a0.x); pa0[1]=f2tf(a0.y); pa0[2]=f2tf(a0.z); pa0[3]=f2tf(a0.w);
        uint32_t* pa1 = &As[0][a_r + 64][a_kq];
        pa1[0]=f2tf(a1.x); pa1[1]=f2tf(a1.y); pa1[2]=f2tf(a1.z); pa1[3]=f2tf(a1.w);
        uint32_t* pb0 = &Bs[0][b_r][b_c];
        pb0[0]=f2tf(b0.x); pb0[1]=f2tf(b0.y); pb0[2]=f2tf(b0.z); pb0[3]=f2tf(b0.w);
        uint32_t* pb1 = &Bs[0][b_r + 8][b_c];
        pb1[0]=f2tf(b1.x); pb1[1]=f2tf(b1.y); pb1[2]=f2tf(b1.z); pb1[3]=f2tf(b1.w);
    }
    __syncthreads();

    for (int t = 0; t < ntk; t++) {
        int buf = t & 1;
        bool more = (t + 1 < ntk);
        float4 an0, an1, bn0, bn1;
        if (more) {
            int k0 = (t + 1) << 4;
            int gr0 = rowBase + a_r, gr1 = gr0 + 64;
            an0 = (gr0 < M) ? *(const float4*)&A[(size_t)gr0 * K + k0 + a_kq] : make_float4(0,0,0,0);
            an1 = (gr1 < M) ? *(const float4*)&A[(size_t)gr1 * K + k0 + a_kq] : make_float4(0,0,0,0);
            bn0 = *(const float4*)&Wt[(size_t)(k0 + b_r) * 128 + b_c];
            bn1 = *(const float4*)&Wt[(size_t)(k0 + b_r + 8) * 128 + b_c];
        }
#pragma unroll
        for (int ks = 0; ks < 16; ks += 8) {
            uint32_t af[4][4], bf[4][2];
#pragma unroll
            for (int mt = 0; mt < 4; mt++) {
                int r0 = wm * 64 + mt * 16 + g;
                af[mt][0] = As[buf][r0][ks + tig];
                af[mt][1] = As[buf][r0 + 8][ks + tig];
                af[mt][2] = As[buf][r0][ks + tig + 4];
                af[mt][3] = As[buf][r0 + 8][ks + tig + 4];
            }
#pragma unroll
            for (int nt = 0; nt < 4; nt++) {
                int c0 = wn * 32 + nt * 8 + g;
                bf[nt][0] = Bs[buf][ks + tig][c0];
                bf[nt][1] = Bs[buf][ks + tig + 4][c0];
            }
#pragma unroll
            for (int mt = 0; mt < 4; mt++)
#pragma unroll
                for (int nt = 0; nt < 4; nt++)
                    mma_tf32(acc[mt][nt], af[mt][0], af[mt][1], af[mt][2], af[mt][3],
                             bf[nt][0], bf[nt][1]);
        }
        if (more) {
            int nb = buf ^ 1;
            uint32_t* pa0 = &As[nb][a_r][a_kq];
            pa0[0]=f2tf(an0.x); pa0[1]=f2tf(an0.y); pa0[2]=f2tf(an0.z); pa0[3]=f2tf(an0.w);
            uint32_t* pa1 = &As[nb][a_r + 64][a_kq];
            pa1[0]=f2tf(an1.x); pa1[1]=f2tf(an1.y); pa1[2]=f2tf(an1.z); pa1[3]=f2tf(an1.w);
            uint32_t* pb0 = &Bs[nb][b_r][b_c];
            pb0[0]=f2tf(bn0.x); pb0[1]=f2tf(bn0.y); pb0[2]=f2tf(bn0.z); pb0[3]=f2tf(bn0.w);
            uint32_t* pb1 = &Bs[nb][b_r + 8][b_c];
            pb1[0]=f2tf(bn1.x); pb1[1]=f2tf(bn1.y); pb1[2]=f2tf(bn1.z); pb1[3]=f2tf(bn1.w);
        }
        __syncthreads();
    }

    // epilogue: c0,c1 adjacent cols; rows g and g+8
#pragma unroll
    for (int mt = 0; mt < 4; mt++) {
#pragma unroll
        for (int nt = 0; nt < 4; nt++) {
            int col = wn * 32 + nt * 8 + tig * 2;
            float b0 = bias[col], b1 = bias[col + 1];
#pragma unroll
            for (int h = 0; h < 2; h++) {
                int row = rowBase + wm * 64 + mt * 16 + g + h * 8;
                if (row >= M) continue;
                float v0 = acc[mt][nt][h * 2 + 0] + b0;
                float v1 = acc[mt][nt][h * 2 + 1] + b1;
                if (RES) {
                    float2 rv = *(const float2*)&res[(size_t)row * HID + col];
                    v0 = rv.x + v0 * scale;
                    v1 = rv.y + v1 * scale;
                }
                v0 = fmaxf(v0, 0.f);
                v1 = fmaxf(v1, 0.f);
                float2 o; o.x = v0; o.y = v1;
                *(float2*)&out[(size_t)row * HID + col] = o;
            }
        }
    }
}

// ------------------------- SAGE mean aggregation (float4, 32 threads/node) -------------------------
__global__ void k_gather_mean4(const float4* __restrict__ xsrc, const int* __restrict__ off,
                               const int* __restrict__ esrc, float4* __restrict__ dst,
                               int n_node, int stride4, int col4) {
    int t = blockIdx.x * blockDim.x + threadIdx.x;
    int lane = t & 31, node = t >> 5;
    if (node >= n_node) return;
    int e0 = off[node], e1 = off[node + 1];
    float4 a = make_float4(0.f, 0.f, 0.f, 0.f);
    for (int e = e0; e < e1; e++) {
        float4 v = __ldg(&xsrc[esrc[e] * 32 + lane]);
        a.x += v.x; a.y += v.y; a.z += v.z; a.w += v.w;
    }
    float inv = 1.f / fmaxf((float)(e1 - e0), 1.f);
    a.x *= inv; a.y *= inv; a.z *= inv; a.w *= inv;
    dst[(size_t)node * stride4 + col4 + lane] = a;
}

__global__ void k_copy_block4(const float4* __restrict__ src, float4* __restrict__ dst,
                              int n_node, int stride4, int col4) {
    int t = blockIdx.x * blockDim.x + threadIdx.x;
    int lane = t & 31, node = t >> 5;
    if (node >= n_node) return;
    dst[(size_t)node * stride4 + col4 + lane] = src[node * 32 + lane];
}

// ------------------------- APPNP step (float4, 32 threads/node) -------------------------
__global__ void k_appnp_step4(const float4* __restrict__ z, float4* __restrict__ zn,
                              const float4* __restrict__ h0) {
    int t = blockIdx.x * blockDim.x + threadIdx.x;
    int lane = t & 31, node = t >> 5;
    if (node >= NT) return;
    int e0 = g_off[node], e1 = g_off[node + 1];
    float4 a = make_float4(0.f, 0.f, 0.f, 0.f);
    for (int e = e0; e < e1; e++) {
        float w = g_cnorm[e];
        float4 v = __ldg(&z[g_csrc[e] * 32 + lane]);
        a.x += w * v.x; a.y += w * v.y; a.z += w * v.z; a.w += w * v.w;
    }
    int idx = node * 32 + lane;
    float4 h = h0[idx];
    float4 o;
    o.x = 0.9f * a.x + 0.1f * h.x;
    o.y = 0.9f * a.y + 0.1f * h.y;
    o.z = 0.9f * a.z + 0.1f * h.z;
    o.w = 0.9f * a.w + 0.1f * h.w;
    zn[idx] = o;
}

// ------------------------- host orchestration -------------------------
extern "C" void kernel_launch(void* const* d_in, const int* in_sizes, int n_in,
                              void* d_out, int out_size) {
    const float* x_gene  = (const float*)d_in[0];
    const float* x_path  = (const float*)d_in[1];
    const float* x_vacc  = (const float*)d_in[2];
    const float* win_g   = (const float*)d_in[3];
    const float* bin_g   = (const float*)d_in[4];
    const float* win_p   = (const float*)d_in[5];
    const float* bin_p   = (const float*)d_in[6];
    const float* win_v   = (const float*)d_in[7];
    const float* bin_v   = (const float*)d_in[8];
    const float* wsl     = (const float*)d_in[9];
    const float* bsl     = (const float*)d_in[10];
    const float* wsr     = (const float*)d_in[11];
    const int*   ei_t    = (const int*)d_in[12];
    const int*   ei_in   = (const int*)d_in[13];
    const int*   ei_ct   = (const int*)d_in[14];
    const int*   ei_ii   = (const int*)d_in[15];
    float* out = (float*)d_out;

    float *hg, *hp, *hv, *sg, *sp, *h0, *zb, *wt, *wtg, *wtp, *bg, *dinv, *cnorm;
    int *degi, *off, *cur, *csrc, *roff_tg, *roff_in, *roff_ct, *roff_ii, *rsrc, *tmp;
    cudaGetSymbolAddress((void**)&hg, g_hg);
    cudaGetSymbolAddress((void**)&hp, g_hp);
    cudaGetSymbolAddress((void**)&hv, g_hv);
    cudaGetSymbolAddress((void**)&sg, g_sg);
    cudaGetSymbolAddress((void**)&sp, g_sp);
    cudaGetSymbolAddress((void**)&h0, g_h0);
    cudaGetSymbolAddress((void**)&zb, g_zb);
    cudaGetSymbolAddress((void**)&wt,  g_wt);
    cudaGetSymbolAddress((void**)&wtg, g_wtg);
    cudaGetSymbolAddress((void**)&wtp, g_wtp);
    cudaGetSymbolAddress((void**)&bg,  g_bg);
    cudaGetSymbolAddress((void**)&dinv, g_dinv);
    cudaGetSymbolAddress((void**)&cnorm, g_cnorm);
    cudaGetSymbolAddress((void**)&degi, g_degi);
    cudaGetSymbolAddress((void**)&off,  g_off);
    cudaGetSymbolAddress((void**)&cur,  g_cur);
    cudaGetSymbolAddress((void**)&csrc, g_csrc);
    cudaGetSymbolAddress((void**)&roff_tg, g_roff_tg);
    cudaGetSymbolAddress((void**)&roff_in, g_roff_in);
    cudaGetSymbolAddress((void**)&roff_ct, g_roff_ct);
    cudaGetSymbolAddress((void**)&roff_ii, g_roff_ii);
    cudaGetSymbolAddress((void**)&rsrc, g_rsrc);
    cudaGetSymbolAddress((void**)&tmp,  g_tmp);

    const int TB = 256;
    const int EB = CDIV(EPER, TB);

    // ---------- per-relation CSRs ----------
    auto build_rel = [&](const int* ei, int n_dst, int* roff, int* rsrc_out) {
        cudaMemsetAsync(tmp, 0, n_dst * sizeof(int));
        k_hist<<<EB, TB>>>(ei + EPER, EPER, tmp, 0);
        k_scan_excl<<<1, 1024>>>(tmp, roff, n_dst);
        cudaMemsetAsync(cur, 0, n_dst * sizeof(int));
        k_scatter_csr<<<EB, TB>>>(ei, ei + EPER, EPER, roff, cur, rsrc_out,
                                  (float*)0, (const float*)0, 0, 0);
    };
    build_rel(ei_t,  NG, roff_tg, rsrc + 0 * EPER);
    build_rel(ei_in, NP, roff_in, rsrc + 1 * EPER);
    build_rel(ei_ct, NG, roff_ct, rsrc + 2 * EPER);
    build_rel(ei_ii, NG, roff_ii, rsrc + 3 * EPER);

    // ---------- input projections relu(x @ W^T + b) ----------
    k_transp<<<CDIV(128 * 256, TB), TB>>>(win_g, wt, 256);
    k_gemm_tc<false><<<CDIV(NG, 128), 256>>>(x_gene, wt, bin_g, (const float*)0, hg, NG, 256, 1.f);
    k_transp<<<CDIV(128 * 128, TB), TB>>>(win_p, wt, 128);
    k_gemm_tc<false><<<CDIV(NP, 128), 256>>>(x_path, wt, bin_p, (const float*)0, hp, NP, 128, 1.f);
    k_transp<<<CDIV(128 * 64, TB), TB>>>(win_v, wt, 64);
    k_gemm_tc<false><<<CDIV(NV, 128), 256>>>(x_vacc, wt, bin_v, (const float*)0, hv, NV, 64, 1.f);

    // ---------- 2 hetero SAGE layers (fused per-type GEMMs) ----------
    const int GBG = CDIV(NG * 32, TB);
    const int GBP = CDIV(NP * 32, TB);
    for (int l = 0; l < 2; l++) {
        k_build_wtg<<<CDIV(512 * 128, TB), TB>>>(wsl, wsr, bsl, l, wtg, bg);
        k_build_wtp<<<CDIV(256 * 128, TB), TB>>>(wsl, wsr, l, wtp);
        // gene staging sg[NG,512]: [agg(hv,tg) | agg(hp,ct) | agg(hg,ii) | hg]
        k_gather_mean4<<<GBG, TB>>>((const float4*)hv, roff_tg, rsrc + 0 * EPER,
                                    (float4*)sg, NG, 128, 0);
        k_gather_mean4<<<GBG, TB>>>((const float4*)hp, roff_ct, rsrc + 2 * EPER,
                                    (float4*)sg, NG, 128, 32);
        k_gather_mean4<<<GBG, TB>>>((const float4*)hg, roff_ii, rsrc + 3 * EPER,
                                    (float4*)sg, NG, 128, 64);
        k_copy_block4<<<GBG, TB>>>((const float4*)hg, (float4*)sg, NG, 128, 96);
        // pathway staging sp[NP,256]: [agg(hg,in) | hp]
        k_gather_mean4<<<GBP, TB>>>((const float4*)hg, roff_in, rsrc + 1 * EPER,
                                    (float4*)sp, NP, 64, 0);
        k_copy_block4<<<GBP, TB>>>((const float4*)hp, (float4*)sp, NP, 64, 32);
        // fused GEMM + residual + relu (in-place update of hg/hp)
        k_gemm_tc<true><<<CDIV(NG, 128), 256>>>(sg, wtg, bg, hg, hg, NG, 512, 1.f / 3.f);
        k_gemm_tc<true><<<CDIV(NP, 128), 256>>>(sp, wtp, bsl + (l * 4 + 1) * 128, hp, hp, NP, 256, 1.f);
    }

    // ---------- APPNP combined CSR ----------
    k_set_ones<<<CDIV(NT, TB), TB>>>(degi, NT);
    k_hist<<<EB, TB>>>(ei_t + EPER,  EPER, degi, 0);
    k_hist<<<EB, TB>>>(ei_in + EPER, EPER, degi, NG);
    k_hist<<<EB, TB>>>(ei_ct + EPER, EPER, degi, 0);
    k_hist<<<EB, TB>>>(ei_ii + EPER, EPER, degi, 0);
    k_dinv<<<CDIV(NT, TB), TB>>>(degi, dinv, NT);
    k_scan_excl<<<1, 1024>>>(degi, off, NT);
    cudaMemsetAsync(cur, 0, NT * sizeof(int));
    k_scatter_csr<<<EB, TB>>>(ei_t,  ei_t + EPER,  EPER, off, cur, csrc, cnorm, dinv, NG + NP, 0);
    k_scatter_csr<<<EB, TB>>>(ei_in, ei_in + EPER, EPER, off, cur, csrc, cnorm, dinv, 0, NG);
    k_scatter_csr<<<EB, TB>>>(ei_ct, ei_ct + EPER, EPER, off, cur, csrc, cnorm, dinv, NG, 0);
    k_scatter_csr<<<EB, TB>>>(ei_ii, ei_ii + EPER, EPER, off, cur, csrc, cnorm, dinv, 0, 0);
    k_scatter_loops<<<CDIV(NT, TB), TB>>>(off, cur, csrc, cnorm, dinv, NT);

    // h0 = concat(hg, hp, hv)
    cudaMemcpyAsync(h0,                           hg, (size_t)NG * HID * sizeof(float), cudaMemcpyDeviceToDevice);
    cudaMemcpyAsync(h0 + (size_t)NG * HID,        hp, (size_t)NP * HID * sizeof(float), cudaMemcpyDeviceToDevice);
    cudaMemcpyAsync(h0 + (size_t)(NG + NP) * HID, hv, (size_t)NV * HID * sizeof(float), cudaMemcpyDeviceToDevice);

    // ---------- 8 APPNP iterations; last (k=7, odd) lands in d_out ----------
    const int AB = CDIV(NT * 32, TB);
    for (int k = 0; k < 8; k++) {
        const float* zin = (k == 0) ? h0 : ((k & 1) ? zb : out);
        float* zout = (k & 1) ? out : zb;
        k_appnp_step4<<<AB, TB>>>((const float4*)zin, (float4*)zout, (const float4*)h0);
    }
}

// round 4
// speedup vs baseline: 2.6852x; 1.1801x over previous
#include <cuda_runtime.h>
#include <cstdint>

#define NG 50000
#define NP 20000
#define NV 10000
#define NT 80000
#define HID 128
#define EPER 250000
#define ETOT (4*EPER + NT)
#define CDIV(a,b) (((a)+(b)-1)/(b))

// cnts/curz segment offsets: tg:0, in:NG, ct:NG+NP, ii:2NG+NP, all(curz only):3NG+NP
#define OFF_TG 0
#define OFF_IN (NG)
#define OFF_CT (NG+NP)
#define OFF_II (2*NG+NP)
#define OFF_ALL (3*NG+NP)
#define CNTS_SZ (3*NG+NP)
#define CURZ_SZ (3*NG+NP+NT)

// ------------------------- device scratch (static, no allocs) -------------------------
__device__ float g_h0[NT*HID];          // also hg | hp | hv (aliased sections)
__device__ float g_zb[NT*HID];
__device__ float g_sg[NG*512];
__device__ float g_sp[NP*256];
__device__ float g_wtin[(256+128+64)*HID]; // transposed input-proj weights
__device__ float g_wtg[512*HID];
__device__ float g_wtp[256*HID];
__device__ float g_bg[HID];
__device__ int   g_degi[NT];
__device__ float g_dinv[NT];
__device__ int   g_off[NT+1];
__device__ int   g_cnts[CNTS_SZ];
__device__ int   g_curz[CURZ_SZ];
__device__ int   g_csrc[ETOT];
__device__ float g_cnorm[ETOT];
__device__ int   g_roff_tg[NG+1];
__device__ int   g_roff_in[NP+1];
__device__ int   g_roff_ct[NG+1];
__device__ int   g_roff_ii[NG+1];
__device__ int   g_rsrc[4*EPER];

// ------------------------- fused setup kernels -------------------------
// transpose the 3 input-projection weights in one kernel
__global__ void k_transp_all(const float* __restrict__ wg, const float* __restrict__ wp,
                             const float* __restrict__ wv) {
    int idx = blockIdx.x * blockDim.x + threadIdx.x;
    if (idx >= (256 + 128 + 64) * 128) return;
    if (idx < 256 * 128) {
        int k = idx >> 7, n = idx & 127;
        g_wtin[idx] = wg[n * 256 + k];
    } else if (idx < (256 + 128) * 128) {
        int i = idx - 256 * 128;
        int k = i >> 7, n = i & 127;
        g_wtin[idx] = wp[n * 128 + k];
    } else {
        int i = idx - (256 + 128) * 128;
        int k = i >> 7, n = i & 127;
        g_wtin[idx] = wv[n * 64 + k];
    }
}

// 4 per-relation dst histograms in one kernel
__global__ void k_hist4(const int* __restrict__ e0, const int* __restrict__ e1,
                        const int* __restrict__ e2, const int* __restrict__ e3) {
    int t = blockIdx.x * blockDim.x + threadIdx.x;
    if (t >= 4 * EPER) return;
    int r = t / EPER, e = t - r * EPER;
    const int* ei = (r == 0) ? e0 : (r == 1) ? e1 : (r == 2) ? e2 : e3;
    int base = (r == 0) ? OFF_TG : (r == 1) ? OFF_IN : (r == 2) ? OFF_CT : OFF_II;
    atomicAdd(&g_cnts[base + ei[EPER + e]], 1);
}

// degi = 1 + relevant rel counts; dinv = rsqrt(degi)
__global__ void k_deg() {
    int i = blockIdx.x * blockDim.x + threadIdx.x;
    if (i >= NT) return;
    int d = 1;
    if (i < NG) d += g_cnts[OFF_TG + i] + g_cnts[OFF_CT + i] + g_cnts[OFF_II + i];
    else if (i < NG + NP) d += g_cnts[OFF_IN + (i - NG)];
    g_degi[i] = d;
    g_dinv[i] = rsqrtf((float)d);
}

// 5 exclusive scans in one launch (block b = one array)
__global__ void k_scan5() {
    __shared__ int part[1024];
    const int* cnt; int* off; int n;
    switch (blockIdx.x) {
        case 0: cnt = g_cnts + OFF_TG; off = g_roff_tg; n = NG; break;
        case 1: cnt = g_cnts + OFF_IN; off = g_roff_in; n = NP; break;
        case 2: cnt = g_cnts + OFF_CT; off = g_roff_ct; n = NG; break;
        case 3: cnt = g_cnts + OFF_II; off = g_roff_ii; n = NG; break;
        default: cnt = g_degi; off = g_off; n = NT; break;
    }
    int t = threadIdx.x;
    int chunk = (n + 1023) / 1024;
    int lo = t * chunk, hi = min(lo + chunk, n);
    int s = 0;
    for (int i = lo; i < hi; i++) s += cnt[i];
    part[t] = s;
    __syncthreads();
    for (int o = 1; o < 1024; o <<= 1) {
        int x = (t >= o) ? part[t - o] : 0;
        __syncthreads();
        part[t] += x;
        __syncthreads();
    }
    int run = part[t] - s;
    for (int i = lo; i < hi; i++) { off[i] = run; run += cnt[i]; }
    if (t == 1023) off[n] = part[1023];
}

// fused scatter: per-relation CSRs + combined APPNP CSR + self loops
__global__ void k_scatter_all(const int* __restrict__ e0, const int* __restrict__ e1,
                              const int* __restrict__ e2, const int* __restrict__ e3) {
    int t = blockIdx.x * blockDim.x + threadIdx.x;
    if (t < 4 * EPER) {
        int r = t / EPER, e = t - r * EPER;
        const int* ei; const int* roff; int cbase, osrc, odst;
        if (r == 0)      { ei = e0; roff = g_roff_tg; cbase = OFF_TG; osrc = NG + NP; odst = 0; }
        else if (r == 1) { ei = e1; roff = g_roff_in; cbase = OFF_IN; osrc = 0;       odst = NG; }
        else if (r == 2) { ei = e2; roff = g_roff_ct; cbase = OFF_CT; osrc = NG;      odst = 0; }
        else             { ei = e3; roff = g_roff_ii; cbase = OFF_II; osrc = 0;       odst = 0; }
        int s = ei[e], d = ei[EPER + e];
        // relation CSR
        int p = roff[d] + atomicAdd(&g_curz[cbase + d], 1);
        g_rsrc[r * EPER + p] = s;
        // combined CSR
        int gs = s + osrc, gd = d + odst;
        int p2 = g_off[gd] + atomicAdd(&g_curz[OFF_ALL + gd], 1);
        g_csrc[p2] = gs;
        g_cnorm[p2] = g_dinv[gs] * g_dinv[gd];
    } else if (t < 4 * EPER + NT) {
        int i = t - 4 * EPER;
        int p = g_off[i] + atomicAdd(&g_curz[OFF_ALL + i], 1);
        g_csrc[p] = i;
        float dv = g_dinv[i];
        g_cnorm[p] = dv * dv;
    }
}

// build gene concat weight [512,128] + combined bias
__global__ void k_build_wtg(const float* __restrict__ wsl, const float* __restrict__ wsr,
                            const float* __restrict__ bsl, int l) {
    int idx = blockIdx.x * blockDim.x + threadIdx.x;
    if (idx < 512 * 128) {
        int k = idx >> 7, n = idx & 127;
        int b = k >> 7, kk = k & 127;
        float v;
        if (b == 0)      v = wsl[((l * 4 + 0) * 128 + n) * 128 + kk];
        else if (b == 1) v = wsl[((l * 4 + 2) * 128 + n) * 128 + kk];
        else if (b == 2) v = wsl[((l * 4 + 3) * 128 + n) * 128 + kk];
        else             v = wsr[((l * 4 + 0) * 128 + n) * 128 + kk]
                           + wsr[((l * 4 + 2) * 128 + n) * 128 + kk]
                           + wsr[((l * 4 + 3) * 128 + n) * 128 + kk];
        g_wtg[idx] = v;
    }
    if (idx < 128) {
        g_bg[idx] = bsl[(l * 4 + 0) * 128 + idx] + bsl[(l * 4 + 2) * 128 + idx]
                  + bsl[(l * 4 + 3) * 128 + idx];
    }
}

__global__ void k_build_wtp(const float* __restrict__ wsl, const float* __restrict__ wsr, int l) {
    int idx = blockIdx.x * blockDim.x + threadIdx.x;
    if (idx < 256 * 128) {
        int k = idx >> 7, n = idx & 127;
        int b = k >> 7, kk = k & 127;
        g_wtp[idx] = (b == 0) ? wsl[((l * 4 + 1) * 128 + n) * 128 + kk]
                              : wsr[((l * 4 + 1) * 128 + n) * 128 + kk];
    }
}

// ------------------------- TF32 tensor-core GEMM (KTILE=32, dynamic smem) -------------------------
__device__ __forceinline__ uint32_t f2tf(float x) {
    uint32_t r;
    asm("cvt.rna.tf32.f32 %0, %1;" : "=r"(r) : "f"(x));
    return r;
}
__device__ __forceinline__ void mma_tf32(float c[4], uint32_t a0, uint32_t a1,
                                         uint32_t a2, uint32_t a3,
                                         uint32_t b0, uint32_t b1) {
    asm volatile(
        "mma.sync.aligned.m16n8k8.row.col.f32.tf32.tf32.f32 "
        "{%0,%1,%2,%3}, {%4,%5,%6,%7}, {%8,%9}, {%0,%1,%2,%3};"
        : "+f"(c[0]), "+f"(c[1]), "+f"(c[2]), "+f"(c[3])
        : "r"(a0), "r"(a1), "r"(a2), "r"(a3), "r"(b0), "r"(b1));
}

#define AST 36               // A smem row stride (words)
#define BST 136              // B smem row stride (words)
#define ABUF (128*AST)       // one A buffer size
#define BBUF (32*BST)
#define SMEM_WORDS (2*ABUF + 2*BBUF)

template<bool RES>
__global__ __launch_bounds__(256)
void k_gemm_tc(const float* __restrict__ A, const float* __restrict__ Wt,
               const float* __restrict__ bias, const float* __restrict__ res,
               float* __restrict__ out, int M, int K, float scale)
{
    extern __shared__ uint32_t sm[];
    uint32_t* Asm = sm;                 // [2][128][AST]
    uint32_t* Bsm = sm + 2 * ABUF;      // [2][32][BST]

    int tid  = threadIdx.x;
    int lane = tid & 31;
    int wid  = tid >> 5;
    int wm = wid >> 2;          // 0..1 -> 64 rows each
    int wn = wid & 3;           // 0..3 -> 32 cols each
    int g   = lane >> 2;
    int tig = lane & 3;

    int rowBase = blockIdx.x * 128;

    // load mappings
    int a_r  = tid >> 1;             // 0..127
    int a_kb = (tid & 1) * 16;       // k half
    int b_r  = tid >> 3;             // 0..31
    int b_cq = (tid & 7) * 4;        // col quad base (cols b_cq + 32j)

    float acc[4][4][4];
#pragma unroll
    for (int mt = 0; mt < 4; mt++)
#pragma unroll
        for (int nt = 0; nt < 4; nt++)
#pragma unroll
            for (int r = 0; r < 4; r++) acc[mt][nt][r] = 0.f;

    int ntk = K >> 5;
    int gr = rowBase + a_r;

    // preload tile 0
    {
        float4 av[4], bv[4];
#pragma unroll
        for (int j = 0; j < 4; j++) {
            av[j] = (gr < M) ? *(const float4*)&A[(size_t)gr * K + a_kb + 4 * j]
                             : make_float4(0, 0, 0, 0);
            bv[j] = *(const float4*)&Wt[(size_t)b_r * 128 + b_cq + 32 * j];
        }
#pragma unroll
        for (int j = 0; j < 4; j++) {
            uint32_t* pa = &Asm[a_r * AST + a_kb + 4 * j];
            pa[0] = f2tf(av[j].x); pa[1] = f2tf(av[j].y);
            pa[2] = f2tf(av[j].z); pa[3] = f2tf(av[j].w);
            uint32_t* pb = &Bsm[b_r * BST + b_cq + 32 * j];
            pb[0] = f2tf(bv[j].x); pb[1] = f2tf(bv[j].y);
            pb[2] = f2tf(bv[j].z); pb[3] = f2tf(bv[j].w);
        }
    }
    __syncthreads();

    for (int t = 0; t < ntk; t++) {
        int buf = t & 1;
        bool more = (t + 1 < ntk);
        float4 av[4], bv[4];
        if (more) {
            int k0 = (t + 1) << 5;
#pragma unroll
            for (int j = 0; j < 4; j++) {
                av[j] = (gr < M) ? *(const float4*)&A[(size_t)gr * K + k0 + a_kb + 4 * j]
                                 : make_float4(0, 0, 0, 0);
                bv[j] = *(const float4*)&Wt[(size_t)(k0 + b_r) * 128 + b_cq + 32 * j];
            }
        }
        const uint32_t* Ab = Asm + buf * ABUF;
        const uint32_t* Bb = Bsm + buf * BBUF;
#pragma unroll
        for (int ks = 0; ks < 32; ks += 8) {
            uint32_t af[4][4], bf[4][2];
#pragma unroll
            for (int mt = 0; mt < 4; mt++) {
                int r0 = wm * 64 + mt * 16 + g;
                af[mt][0] = Ab[r0 * AST + ks + tig];
                af[mt][1] = Ab[(r0 + 8) * AST + ks + tig];
                af[mt][2] = Ab[r0 * AST + ks + tig + 4];
                af[mt][3] = Ab[(r0 + 8) * AST + ks + tig + 4];
            }
#pragma unroll
            for (int nt = 0; nt < 4; nt++) {
                int c0 = wn * 32 + nt * 8 + g;
                bf[nt][0] = Bb[(ks + tig) * BST + c0];
                bf[nt][1] = Bb[(ks + tig + 4) * BST + c0];
            }
#pragma unroll
            for (int mt = 0; mt < 4; mt++)
#pragma unroll
                for (int nt = 0; nt < 4; nt++)
                    mma_tf32(acc[mt][nt], af[mt][0], af[mt][1], af[mt][2], af[mt][3],
                             bf[nt][0], bf[nt][1]);
        }
        if (more) {
            int nb = buf ^ 1;
            uint32_t* An = Asm + nb * ABUF;
            uint32_t* Bn = Bsm + nb * BBUF;
#pragma unroll
            for (int j = 0; j < 4; j++) {
                uint32_t* pa = &An[a_r * AST + a_kb + 4 * j];
                pa[0] = f2tf(av[j].x); pa[1] = f2tf(av[j].y);
                pa[2] = f2tf(av[j].z); pa[3] = f2tf(av[j].w);
                uint32_t* pb = &Bn[b_r * BST + b_cq + 32 * j];
                pb[0] = f2tf(bv[j].x); pb[1] = f2tf(bv[j].y);
                pb[2] = f2tf(bv[j].z); pb[3] = f2tf(bv[j].w);
            }
        }
        __syncthreads();
    }

#pragma unroll
    for (int mt = 0; mt < 4; mt++) {
#pragma unroll
        for (int nt = 0; nt < 4; nt++) {
            int col = wn * 32 + nt * 8 + tig * 2;
            float b0 = bias[col], b1 = bias[col + 1];
#pragma unroll
            for (int h = 0; h < 2; h++) {
                int row = rowBase + wm * 64 + mt * 16 + g + h * 8;
                if (row >= M) continue;
                float v0 = acc[mt][nt][h * 2 + 0] + b0;
                float v1 = acc[mt][nt][h * 2 + 1] + b1;
                if (RES) {
                    float2 rv = *(const float2*)&res[(size_t)row * HID + col];
                    v0 = rv.x + v0 * scale;
                    v1 = rv.y + v1 * scale;
                }
                v0 = fmaxf(v0, 0.f);
                v1 = fmaxf(v1, 0.f);
                float2 o; o.x = v0; o.y = v1;
                *(float2*)&out[(size_t)row * HID + col] = o;
            }
        }
    }
}

// ------------------------- SAGE mean gather (+optional row copy) -------------------------
__global__ void k_gather_mean4(const float4* __restrict__ xsrc, const int* __restrict__ off,
                               const int* __restrict__ esrc, float4* __restrict__ dst,
                               int n_node, int stride4, int col4,
                               const float4* __restrict__ copy_src, int ccol4) {
    int t = blockIdx.x * blockDim.x + threadIdx.x;
    int lane = t & 31, node = t >> 5;
    if (node >= n_node) return;
    int e0 = off[node], e1 = off[node + 1];
    float4 a = make_float4(0.f, 0.f, 0.f, 0.f);
    for (int e = e0; e < e1; e++) {
        float4 v = __ldg(&xsrc[esrc[e] * 32 + lane]);
        a.x += v.x; a.y += v.y; a.z += v.z; a.w += v.w;
    }
    float inv = 1.f / fmaxf((float)(e1 - e0), 1.f);
    a.x *= inv; a.y *= inv; a.z *= inv; a.w *= inv;
    dst[(size_t)node * stride4 + col4 + lane] = a;
    if (copy_src)
        dst[(size_t)node * stride4 + ccol4 + lane] = copy_src[node * 32 + lane];
}

// ------------------------- APPNP step -------------------------
__global__ void k_appnp_step4(const float4* __restrict__ z, float4* __restrict__ zn,
                              const float4* __restrict__ h0) {
    int t = blockIdx.x * blockDim.x + threadIdx.x;
    int lane = t & 31, node = t >> 5;
    if (node >= NT) return;
    int e0 = g_off[node], e1 = g_off[node + 1];
    float4 a = make_float4(0.f, 0.f, 0.f, 0.f);
    for (int e = e0; e < e1; e++) {
        float w = g_cnorm[e];
        float4 v = __ldg(&z[g_csrc[e] * 32 + lane]);
        a.x += w * v.x; a.y += w * v.y; a.z += w * v.z; a.w += w * v.w;
    }
    int idx = node * 32 + lane;
    float4 h = h0[idx];
    float4 o;
    o.x = 0.9f * a.x + 0.1f * h.x;
    o.y = 0.9f * a.y + 0.1f * h.y;
    o.z = 0.9f * a.z + 0.1f * h.z;
    o.w = 0.9f * a.w + 0.1f * h.w;
    zn[idx] = o;
}

// ------------------------- host orchestration -------------------------
extern "C" void kernel_launch(void* const* d_in, const int* in_sizes, int n_in,
                              void* d_out, int out_size) {
    const float* x_gene  = (const float*)d_in[0];
    const float* x_path  = (const float*)d_in[1];
    const float* x_vacc  = (const float*)d_in[2];
    const float* win_g   = (const float*)d_in[3];
    const float* bin_g   = (const float*)d_in[4];
    const float* win_p   = (const float*)d_in[5];
    const float* bin_p   = (const float*)d_in[6];
    const float* win_v   = (const float*)d_in[7];
    const float* bin_v   = (const float*)d_in[8];
    const float* wsl     = (const float*)d_in[9];
    const float* bsl     = (const float*)d_in[10];
    const float* wsr     = (const float*)d_in[11];
    const int*   ei_t    = (const int*)d_in[12];
    const int*   ei_in   = (const int*)d_in[13];
    const int*   ei_ct   = (const int*)d_in[14];
    const int*   ei_ii   = (const int*)d_in[15];
    float* out = (float*)d_out;

    float *h0, *zb, *sg, *sp, *wtin, *wtg, *wtp, *bg;
    int *cnts, *curz, *roff_tg, *roff_in, *roff_ct, *roff_ii, *rsrc;
    cudaGetSymbolAddress((void**)&h0, g_h0);
    cudaGetSymbolAddress((void**)&zb, g_zb);
    cudaGetSymbolAddress((void**)&sg, g_sg);
    cudaGetSymbolAddress((void**)&sp, g_sp);
    cudaGetSymbolAddress((void**)&wtin, g_wtin);
    cudaGetSymbolAddress((void**)&wtg, g_wtg);
    cudaGetSymbolAddress((void**)&wtp, g_wtp);
    cudaGetSymbolAddress((void**)&bg,  g_bg);
    cudaGetSymbolAddress((void**)&cnts, g_cnts);
    cudaGetSymbolAddress((void**)&curz, g_curz);
    cudaGetSymbolAddress((void**)&roff_tg, g_roff_tg);
    cudaGetSymbolAddress((void**)&roff_in, g_roff_in);
    cudaGetSymbolAddress((void**)&roff_ct, g_roff_ct);
    cudaGetSymbolAddress((void**)&roff_ii, g_roff_ii);
    cudaGetSymbolAddress((void**)&rsrc, g_rsrc);

    // aliased node-feature sections
    float* hg = h0;
    float* hp = h0 + (size_t)NG * HID;
    float* hv = h0 + (size_t)(NG + NP) * HID;

    const int TB = 256;
    const int SMB = SMEM_WORDS * 4;   // gemm dynamic smem bytes
    static bool attr_set = false;
    if (!attr_set) {
        cudaFuncSetAttribute(k_gemm_tc<false>, cudaFuncAttributeMaxDynamicSharedMemorySize, SMB);
        cudaFuncSetAttribute(k_gemm_tc<true>,  cudaFuncAttributeMaxDynamicSharedMemorySize, SMB);
        attr_set = true;
    }

    // ---------- input projections + layer-0 weight builds (GEMM at launch #6 for ncu) ----------
    k_transp_all<<<CDIV((256 + 128 + 64) * 128, TB), TB>>>(win_g, win_p, win_v);
    k_build_wtg<<<CDIV(512 * 128, TB), TB>>>(wsl, wsr, bsl, 0);
    k_build_wtp<<<CDIV(256 * 128, TB), TB>>>(wsl, wsr, 0);
    k_gemm_tc<false><<<CDIV(NV, 128), 256, SMB>>>(x_vacc, wtin + (256 + 128) * 128, bin_v,
                                                  (const float*)0, hv, NV, 64, 1.f);
    k_gemm_tc<false><<<CDIV(NP, 128), 256, SMB>>>(x_path, wtin + 256 * 128, bin_p,
                                                  (const float*)0, hp, NP, 128, 1.f);
    k_gemm_tc<false><<<CDIV(NG, 128), 256, SMB>>>(x_gene, wtin, bin_g,
                                                  (const float*)0, hg, NG, 256, 1.f);

    // ---------- CSR setup (fused) ----------
    cudaMemsetAsync(cnts, 0, CNTS_SZ * sizeof(int));
    k_hist4<<<CDIV(4 * EPER, TB), TB>>>(ei_t, ei_in, ei_ct, ei_ii);
    k_deg<<<CDIV(NT, TB), TB>>>();
    k_scan5<<<5, 1024>>>();
    cudaMemsetAsync(curz, 0, CURZ_SZ * sizeof(int));
    k_scatter_all<<<CDIV(4 * EPER + NT, TB), TB>>>(ei_t, ei_in, ei_ct, ei_ii);

    // ---------- 2 hetero SAGE layers ----------
    const int GBG = CDIV(NG * 32, TB);
    const int GBP = CDIV(NP * 32, TB);
    for (int l = 0; l < 2; l++) {
        // sg[NG,512] = [agg(hv,tg) | agg(hp,ct) | agg(hg,ii) | hg]
        k_gather_mean4<<<GBG, TB>>>((const float4*)hv, roff_tg, rsrc + 0 * EPER,
                                    (float4*)sg, NG, 128, 0, (const float4*)0, 0);
        k_gather_mean4<<<GBG, TB>>>((const float4*)hp, roff_ct, rsrc + 2 * EPER,
                                    (float4*)sg, NG, 128, 32, (const float4*)0, 0);
        k_gather_mean4<<<GBG, TB>>>((const float4*)hg, roff_ii, rsrc + 3 * EPER,
                                    (float4*)sg, NG, 128, 64, (const float4*)hg, 96);
        // sp[NP,256] = [agg(hg,in) | hp]
        k_gather_mean4<<<GBP, TB>>>((const float4*)hg, roff_in, rsrc + 1 * EPER,
                                    (float4*)sp, NP, 64, 0, (const float4*)hp, 32);
        // fused GEMM + residual + relu (in-place into h0 sections)
        k_gemm_tc<true><<<CDIV(NG, 128), 256, SMB>>>(sg, wtg, bg, hg, hg, NG, 512, 1.f / 3.f);
        k_gemm_tc<true><<<CDIV(NP, 128), 256, SMB>>>(sp, wtp, bsl + (l * 4 + 1) * 128,
                                                     hp, hp, NP, 256, 1.f);
        if (l == 0) {   // build layer-1 weights (stream-ordered after layer-0 GEMMs)
            k_build_wtg<<<CDIV(512 * 128, TB), TB>>>(wsl, wsr, bsl, 1);
            k_build_wtp<<<CDIV(256 * 128, TB), TB>>>(wsl, wsr, 1);
        }
    }

    // ---------- 8 APPNP iterations; last (k=7, odd) lands in d_out ----------
    const int AB = CDIV(NT * 32, TB);
    for (int k = 0; k < 8; k++) {
        const float* zin = (k == 0) ? h0 : ((k & 1) ? zb : out);
        float* zout = (k & 1) ? out : zb;
        k_appnp_step4<<<AB, TB>>>((const float4*)zin, (float4*)zout, (const float4*)h0);
    }
}

// round 5
// speedup vs baseline: 2.9838x; 1.1112x over previous
#include <cuda_runtime.h>
#include <cuda_fp16.h>
#include <cstdint>

#define NG 50000
#define NP 20000
#define NV 10000
#define NT 80000
#define HID 128
#define EPER 250000
#define ETOT (4*EPER + NT)
#define CDIV(a,b) (((a)+(b)-1)/(b))

#define OFF_TG 0
#define OFF_IN (NG)
#define OFF_CT (NG+NP)
#define OFF_II (2*NG+NP)
#define OFF_ALL (3*NG+NP)
#define CNTS_SZ (3*NG+NP)
#define CURZ_SZ (3*NG+NP+NT)

// ------------------------- device scratch -------------------------
__device__ float g_h0[NT*HID];                       // fp32 node features (hg|hp|hv)
__device__ __align__(16) __half g_h16[NT*HID];       // fp16 mirror
__device__ __align__(16) __half g_z16a[NT*HID];      // APPNP ping
__device__ __align__(16) __half g_z16b[NT*HID];      // APPNP pong
__device__ float g_sg[NG*512];
__device__ float g_sp[NP*256];
__device__ float g_wtin[(256+128+64)*HID];
__device__ float g_wtg[512*HID];
__device__ float g_wtp[256*HID];
__device__ float g_bg[HID];
__device__ int   g_degi[NT];
__device__ float g_dinv[NT];
__device__ int   g_off[NT+1];
__device__ int   g_cnts[CNTS_SZ];
__device__ int   g_curz[CURZ_SZ];
__device__ int   g_csrc[ETOT];
__device__ float g_cnorm[ETOT];
__device__ int   g_roff_tg[NG+1];
__device__ int   g_roff_in[NP+1];
__device__ int   g_roff_ct[NG+1];
__device__ int   g_roff_ii[NG+1];
__device__ int   g_rsrc[4*EPER];

// ------------------------- fused setup kernels -------------------------
__global__ void k_transp_all(const float* __restrict__ wg, const float* __restrict__ wp,
                             const float* __restrict__ wv) {
    int idx = blockIdx.x * blockDim.x + threadIdx.x;
    if (idx >= (256 + 128 + 64) * 128) return;
    if (idx < 256 * 128) {
        int k = idx >> 7, n = idx & 127;
        g_wtin[idx] = wg[n * 256 + k];
    } else if (idx < (256 + 128) * 128) {
        int i = idx - 256 * 128;
        int k = i >> 7, n = i & 127;
        g_wtin[idx] = wp[n * 128 + k];
    } else {
        int i = idx - (256 + 128) * 128;
        int k = i >> 7, n = i & 127;
        g_wtin[idx] = wv[n * 64 + k];
    }
}

__global__ void k_hist4(const int* __restrict__ e0, const int* __restrict__ e1,
                        const int* __restrict__ e2, const int* __restrict__ e3) {
    int t = blockIdx.x * blockDim.x + threadIdx.x;
    if (t >= 4 * EPER) return;
    int r = t / EPER, e = t - r * EPER;
    const int* ei = (r == 0) ? e0 : (r == 1) ? e1 : (r == 2) ? e2 : e3;
    int base = (r == 0) ? OFF_TG : (r == 1) ? OFF_IN : (r == 2) ? OFF_CT : OFF_II;
    atomicAdd(&g_cnts[base + ei[EPER + e]], 1);
}

__global__ void k_deg() {
    int i = blockIdx.x * blockDim.x + threadIdx.x;
    if (i >= NT) return;
    int d = 1;
    if (i < NG) d += g_cnts[OFF_TG + i] + g_cnts[OFF_CT + i] + g_cnts[OFF_II + i];
    else if (i < NG + NP) d += g_cnts[OFF_IN + (i - NG)];
    g_degi[i] = d;
    g_dinv[i] = rsqrtf((float)d);
}

__global__ void k_scan5() {
    __shared__ int part[1024];
    const int* cnt; int* off; int n;
    switch (blockIdx.x) {
        case 0: cnt = g_cnts + OFF_TG; off = g_roff_tg; n = NG; break;
        case 1: cnt = g_cnts + OFF_IN; off = g_roff_in; n = NP; break;
        case 2: cnt = g_cnts + OFF_CT; off = g_roff_ct; n = NG; break;
        case 3: cnt = g_cnts + OFF_II; off = g_roff_ii; n = NG; break;
        default: cnt = g_degi; off = g_off; n = NT; break;
    }
    int t = threadIdx.x;
    int chunk = (n + 1023) / 1024;
    int lo = t * chunk, hi = min(lo + chunk, n);
    int s = 0;
    for (int i = lo; i < hi; i++) s += cnt[i];
    part[t] = s;
    __syncthreads();
    for (int o = 1; o < 1024; o <<= 1) {
        int x = (t >= o) ? part[t - o] : 0;
        __syncthreads();
        part[t] += x;
        __syncthreads();
    }
    int run = part[t] - s;
    for (int i = lo; i < hi; i++) { off[i] = run; run += cnt[i]; }
    if (t == 1023) off[n] = part[1023];
}

__global__ void k_scatter_all(const int* __restrict__ e0, const int* __restrict__ e1,
                              const int* __restrict__ e2, const int* __restrict__ e3) {
    int t = blockIdx.x * blockDim.x + threadIdx.x;
    if (t < 4 * EPER) {
        int r = t / EPER, e = t - r * EPER;
        const int* ei; const int* roff; int cbase, osrc, odst;
        if (r == 0)      { ei = e0; roff = g_roff_tg; cbase = OFF_TG; osrc = NG + NP; odst = 0; }
        else if (r == 1) { ei = e1; roff = g_roff_in; cbase = OFF_IN; osrc = 0;       odst = NG; }
        else if (r == 2) { ei = e2; roff = g_roff_ct; cbase = OFF_CT; osrc = NG;      odst = 0; }
        else             { ei = e3; roff = g_roff_ii; cbase = OFF_II; osrc = 0;       odst = 0; }
        int s = ei[e], d = ei[EPER + e];
        int p = roff[d] + atomicAdd(&g_curz[cbase + d], 1);
        g_rsrc[r * EPER + p] = s;
        int gs = s + osrc, gd = d + odst;
        int p2 = g_off[gd] + atomicAdd(&g_curz[OFF_ALL + gd], 1);
        g_csrc[p2] = gs;
        g_cnorm[p2] = g_dinv[gs] * g_dinv[gd];
    } else if (t < 4 * EPER + NT) {
        int i = t - 4 * EPER;
        int p = g_off[i] + atomicAdd(&g_curz[OFF_ALL + i], 1);
        g_csrc[p] = i;
        float dv = g_dinv[i];
        g_cnorm[p] = dv * dv;
    }
}

__global__ void k_build_wtg(const float* __restrict__ wsl, const float* __restrict__ wsr,
                            const float* __restrict__ bsl, int l) {
    int idx = blockIdx.x * blockDim.x + threadIdx.x;
    if (idx < 512 * 128) {
        int k = idx >> 7, n = idx & 127;
        int b = k >> 7, kk = k & 127;
        float v;
        if (b == 0)      v = wsl[((l * 4 + 0) * 128 + n) * 128 + kk];
        else if (b == 1) v = wsl[((l * 4 + 2) * 128 + n) * 128 + kk];
        else if (b == 2) v = wsl[((l * 4 + 3) * 128 + n) * 128 + kk];
        else             v = wsr[((l * 4 + 0) * 128 + n) * 128 + kk]
                           + wsr[((l * 4 + 2) * 128 + n) * 128 + kk]
                           + wsr[((l * 4 + 3) * 128 + n) * 128 + kk];
        g_wtg[idx] = v;
    }
    if (idx < 128) {
        g_bg[idx] = bsl[(l * 4 + 0) * 128 + idx] + bsl[(l * 4 + 2) * 128 + idx]
                  + bsl[(l * 4 + 3) * 128 + idx];
    }
}

__global__ void k_build_wtp(const float* __restrict__ wsl, const float* __restrict__ wsr, int l) {
    int idx = blockIdx.x * blockDim.x + threadIdx.x;
    if (idx < 256 * 128) {
        int k = idx >> 7, n = idx & 127;
        int b = k >> 7, kk = k & 127;
        g_wtp[idx] = (b == 0) ? wsl[((l * 4 + 1) * 128 + n) * 128 + kk]
                              : wsr[((l * 4 + 1) * 128 + n) * 128 + kk];
    }
}

// ------------------------- TF32 tensor-core GEMM (KTILE=32) -------------------------
__device__ __forceinline__ uint32_t f2tf(float x) {
    uint32_t r;
    asm("cvt.rna.tf32.f32 %0, %1;" : "=r"(r) : "f"(x));
    return r;
}
__device__ __forceinline__ void mma_tf32(float c[4], uint32_t a0, uint32_t a1,
                                         uint32_t a2, uint32_t a3,
                                         uint32_t b0, uint32_t b1) {
    asm volatile(
        "mma.sync.aligned.m16n8k8.row.col.f32.tf32.tf32.f32 "
        "{%0,%1,%2,%3}, {%4,%5,%6,%7}, {%8,%9}, {%0,%1,%2,%3};"
        : "+f"(c[0]), "+f"(c[1]), "+f"(c[2]), "+f"(c[3])
        : "r"(a0), "r"(a1), "r"(a2), "r"(a3), "r"(b0), "r"(b1));
}

#define AST 36
#define BST 136
#define ABUF (128*AST)
#define BBUF (32*BST)
#define SMEM_WORDS (2*ABUF + 2*BBUF)

template<bool RES>
__global__ __launch_bounds__(256)
void k_gemm_tc(const float* __restrict__ A, const float* __restrict__ Wt,
               const float* __restrict__ bias, const float* __restrict__ res,
               float* __restrict__ out, __half* __restrict__ h16out,
               int M, int K, float scale)
{
    extern __shared__ uint32_t sm[];
    uint32_t* Asm = sm;
    uint32_t* Bsm = sm + 2 * ABUF;

    int tid  = threadIdx.x;
    int lane = tid & 31;
    int wid  = tid >> 5;
    int wm = wid >> 2;
    int wn = wid & 3;
    int g   = lane >> 2;
    int tig = lane & 3;

    int rowBase = blockIdx.x * 128;

    int a_r  = tid >> 1;
    int a_kb = (tid & 1) * 16;
    int b_r  = tid >> 3;
    int b_cq = (tid & 7) * 4;

    float acc[4][4][4];
#pragma unroll
    for (int mt = 0; mt < 4; mt++)
#pragma unroll
        for (int nt = 0; nt < 4; nt++)
#pragma unroll
            for (int r = 0; r < 4; r++) acc[mt][nt][r] = 0.f;

    int ntk = K >> 5;
    int gr = rowBase + a_r;

    {
        float4 av[4], bv[4];
#pragma unroll
        for (int j = 0; j < 4; j++) {
            av[j] = (gr < M) ? *(const float4*)&A[(size_t)gr * K + a_kb + 4 * j]
                             : make_float4(0, 0, 0, 0);
            bv[j] = *(const float4*)&Wt[(size_t)b_r * 128 + b_cq + 32 * j];
        }
#pragma unroll
        for (int j = 0; j < 4; j++) {
            uint32_t* pa = &Asm[a_r * AST + a_kb + 4 * j];
            pa[0] = f2tf(av[j].x); pa[1] = f2tf(av[j].y);
            pa[2] = f2tf(av[j].z); pa[3] = f2tf(av[j].w);
            uint32_t* pb = &Bsm[b_r * BST + b_cq + 32 * j];
            pb[0] = f2tf(bv[j].x); pb[1] = f2tf(bv[j].y);
            pb[2] = f2tf(bv[j].z); pb[3] = f2tf(bv[j].w);
        }
    }
    __syncthreads();

    for (int t = 0; t < ntk; t++) {
        int buf = t & 1;
        bool more = (t + 1 < ntk);
        float4 av[4], bv[4];
        if (more) {
            int k0 = (t + 1) << 5;
#pragma unroll
            for (int j = 0; j < 4; j++) {
                av[j] = (gr < M) ? *(const float4*)&A[(size_t)gr * K + k0 + a_kb + 4 * j]
                                 : make_float4(0, 0, 0, 0);
                bv[j] = *(const float4*)&Wt[(size_t)(k0 + b_r) * 128 + b_cq + 32 * j];
            }
        }
        const uint32_t* Ab = Asm + buf * ABUF;
        const uint32_t* Bb = Bsm + buf * BBUF;
#pragma unroll
        for (int ks = 0; ks < 32; ks += 8) {
            uint32_t af[4][4], bf[4][2];
#pragma unroll
            for (int mt = 0; mt < 4; mt++) {
                int r0 = wm * 64 + mt * 16 + g;
                af[mt][0] = Ab[r0 * AST + ks + tig];
                af[mt][1] = Ab[(r0 + 8) * AST + ks + tig];
                af[mt][2] = Ab[r0 * AST + ks + tig + 4];
                af[mt][3] = Ab[(r0 + 8) * AST + ks + tig + 4];
            }
#pragma unroll
            for (int nt = 0; nt < 4; nt++) {
                int c0 = wn * 32 + nt * 8 + g;
                bf[nt][0] = Bb[(ks + tig) * BST + c0];
                bf[nt][1] = Bb[(ks + tig + 4) * BST + c0];
            }
#pragma unroll
            for (int mt = 0; mt < 4; mt++)
#pragma unroll
                for (int nt = 0; nt < 4; nt++)
                    mma_tf32(acc[mt][nt], af[mt][0], af[mt][1], af[mt][2], af[mt][3],
                             bf[nt][0], bf[nt][1]);
        }
        if (more) {
            int nb = buf ^ 1;
            uint32_t* An = Asm + nb * ABUF;
            uint32_t* Bn = Bsm + nb * BBUF;
#pragma unroll
            for (int j = 0; j < 4; j++) {
                uint32_t* pa = &An[a_r * AST + a_kb + 4 * j];
                pa[0] = f2tf(av[j].x); pa[1] = f2tf(av[j].y);
                pa[2] = f2tf(av[j].z); pa[3] = f2tf(av[j].w);
                uint32_t* pb = &Bn[b_r * BST + b_cq + 32 * j];
                pb[0] = f2tf(bv[j].x); pb[1] = f2tf(bv[j].y);
                pb[2] = f2tf(bv[j].z); pb[3] = f2tf(bv[j].w);
            }
        }
        __syncthreads();
    }

#pragma unroll
    for (int mt = 0; mt < 4; mt++) {
#pragma unroll
        for (int nt = 0; nt < 4; nt++) {
            int col = wn * 32 + nt * 8 + tig * 2;
            float b0 = bias[col], b1 = bias[col + 1];
#pragma unroll
            for (int h = 0; h < 2; h++) {
                int row = rowBase + wm * 64 + mt * 16 + g + h * 8;
                if (row >= M) continue;
                float v0 = acc[mt][nt][h * 2 + 0] + b0;
                float v1 = acc[mt][nt][h * 2 + 1] + b1;
                if (RES) {
                    float2 rv = *(const float2*)&res[(size_t)row * HID + col];
                    v0 = rv.x + v0 * scale;
                    v1 = rv.y + v1 * scale;
                }
                v0 = fmaxf(v0, 0.f);
                v1 = fmaxf(v1, 0.f);
                float2 o; o.x = v0; o.y = v1;
                *(float2*)&out[(size_t)row * HID + col] = o;
                *(__half2*)&h16out[(size_t)row * HID + col] = __floats2half2_rn(v0, v1);
            }
        }
    }
}

// ------------------------- fp16 helpers -------------------------
__device__ __forceinline__ void h8_acc(uint4 v, float w, float a[8]) {
    const __half2* h = (const __half2*)&v;
#pragma unroll
    for (int j = 0; j < 4; j++) {
        float2 f = __half22float2(h[j]);
        a[2 * j]     += w * f.x;
        a[2 * j + 1] += w * f.y;
    }
}

// ------------------------- SAGE mean gather (fp16 source, 16 lanes/node) -------------------------
__global__ void k_gather_mean_h(const uint4* __restrict__ xsrc, const int* __restrict__ off,
                                const int* __restrict__ esrc, float4* __restrict__ dst,
                                int n_node, int stride4, int col4,
                                const float4* __restrict__ copy_src, int ccol4) {
    int t = blockIdx.x * blockDim.x + threadIdx.x;
    int lane = t & 15, node = t >> 4;
    if (node >= n_node) return;
    int e0 = off[node], e1 = off[node + 1];
    float a[8] = {0.f, 0.f, 0.f, 0.f, 0.f, 0.f, 0.f, 0.f};
    for (int e = e0; e < e1; e++) {
        uint4 v = __ldg(&xsrc[(size_t)esrc[e] * 16 + lane]);
        h8_acc(v, 1.f, a);
    }
    float inv = 1.f / fmaxf((float)(e1 - e0), 1.f);
    float4 o0 = make_float4(a[0] * inv, a[1] * inv, a[2] * inv, a[3] * inv);
    float4 o1 = make_float4(a[4] * inv, a[5] * inv, a[6] * inv, a[7] * inv);
    size_t base = (size_t)node * stride4 + col4 + lane * 2;
    dst[base] = o0;
    dst[base + 1] = o1;
    if (copy_src) {
        size_t cb = (size_t)node * stride4 + ccol4 + lane * 2;
        dst[cb]     = copy_src[node * 32 + lane * 2];
        dst[cb + 1] = copy_src[node * 32 + lane * 2 + 1];
    }
}

// ------------------------- APPNP step (fp16 gather, 16 lanes/node) -------------------------
template<bool LAST>
__global__ void k_appnp_h(const uint4* __restrict__ z, uint4* __restrict__ zn,
                          const float4* __restrict__ h0, float4* __restrict__ outf) {
    int t = blockIdx.x * blockDim.x + threadIdx.x;
    int lane = t & 15, node = t >> 4;
    if (node >= NT) return;
    int e0 = g_off[node], e1 = g_off[node + 1];
    float a[8] = {0.f, 0.f, 0.f, 0.f, 0.f, 0.f, 0.f, 0.f};
    for (int e = e0; e < e1; e++) {
        float w = g_cnorm[e];
        uint4 v = __ldg(&z[(size_t)g_csrc[e] * 16 + lane]);
        h8_acc(v, w, a);
    }
    float4 ha = h0[(size_t)node * 32 + lane * 2];
    float4 hb = h0[(size_t)node * 32 + lane * 2 + 1];
    float r[8];
    r[0] = 0.9f * a[0] + 0.1f * ha.x;
    r[1] = 0.9f * a[1] + 0.1f * ha.y;
    r[2] = 0.9f * a[2] + 0.1f * ha.z;
    r[3] = 0.9f * a[3] + 0.1f * ha.w;
    r[4] = 0.9f * a[4] + 0.1f * hb.x;
    r[5] = 0.9f * a[5] + 0.1f * hb.y;
    r[6] = 0.9f * a[6] + 0.1f * hb.z;
    r[7] = 0.9f * a[7] + 0.1f * hb.w;
    if (LAST) {
        outf[(size_t)node * 32 + lane * 2]     = make_float4(r[0], r[1], r[2], r[3]);
        outf[(size_t)node * 32 + lane * 2 + 1] = make_float4(r[4], r[5], r[6], r[7]);
    } else {
        uint4 pk;
        __half2* ph = (__half2*)&pk;
        ph[0] = __floats2half2_rn(r[0], r[1]);
        ph[1] = __floats2half2_rn(r[2], r[3]);
        ph[2] = __floats2half2_rn(r[4], r[5]);
        ph[3] = __floats2half2_rn(r[6], r[7]);
        zn[(size_t)node * 16 + lane] = pk;
    }
}

// ------------------------- host orchestration -------------------------
extern "C" void kernel_launch(void* const* d_in, const int* in_sizes, int n_in,
                              void* d_out, int out_size) {
    const float* x_gene  = (const float*)d_in[0];
    const float* x_path  = (const float*)d_in[1];
    const float* x_vacc  = (const float*)d_in[2];
    const float* win_g   = (const float*)d_in[3];
    const float* bin_g   = (const float*)d_in[4];
    const float* win_p   = (const float*)d_in[5];
    const float* bin_p   = (const float*)d_in[6];
    const float* win_v   = (const float*)d_in[7];
    const float* bin_v   = (const float*)d_in[8];
    const float* wsl     = (const float*)d_in[9];
    const float* bsl     = (const float*)d_in[10];
    const float* wsr     = (const float*)d_in[11];
    const int*   ei_t    = (const int*)d_in[12];
    const int*   ei_in   = (const int*)d_in[13];
    const int*   ei_ct   = (const int*)d_in[14];
    const int*   ei_ii   = (const int*)d_in[15];
    float* out = (float*)d_out;

    float *h0, *sg, *sp, *wtin, *wtg, *wtp, *bg;
    __half *h16, *z16a, *z16b;
    int *cnts, *curz, *roff_tg, *roff_in, *roff_ct, *roff_ii, *rsrc;
    cudaGetSymbolAddress((void**)&h0, g_h0);
    cudaGetSymbolAddress((void**)&h16, g_h16);
    cudaGetSymbolAddress((void**)&z16a, g_z16a);
    cudaGetSymbolAddress((void**)&z16b, g_z16b);
    cudaGetSymbolAddress((void**)&sg, g_sg);
    cudaGetSymbolAddress((void**)&sp, g_sp);
    cudaGetSymbolAddress((void**)&wtin, g_wtin);
    cudaGetSymbolAddress((void**)&wtg, g_wtg);
    cudaGetSymbolAddress((void**)&wtp, g_wtp);
    cudaGetSymbolAddress((void**)&bg,  g_bg);
    cudaGetSymbolAddress((void**)&cnts, g_cnts);
    cudaGetSymbolAddress((void**)&curz, g_curz);
    cudaGetSymbolAddress((void**)&roff_tg, g_roff_tg);
    cudaGetSymbolAddress((void**)&roff_in, g_roff_in);
    cudaGetSymbolAddress((void**)&roff_ct, g_roff_ct);
    cudaGetSymbolAddress((void**)&roff_ii, g_roff_ii);
    cudaGetSymbolAddress((void**)&rsrc, g_rsrc);

    float* hg = h0;
    float* hp = h0 + (size_t)NG * HID;
    float* hv = h0 + (size_t)(NG + NP) * HID;
    __half* hg16 = h16;
    __half* hp16 = h16 + (size_t)NG * HID;
    __half* hv16 = h16 + (size_t)(NG + NP) * HID;

    const int TB = 256;
    const int SMB = SMEM_WORDS * 4;
    static bool attr_set = false;
    if (!attr_set) {
        cudaFuncSetAttribute(k_gemm_tc<false>, cudaFuncAttributeMaxDynamicSharedMemorySize, SMB);
        cudaFuncSetAttribute(k_gemm_tc<true>,  cudaFuncAttributeMaxDynamicSharedMemorySize, SMB);
        attr_set = true;
    }

    // ---------- input projections + layer-0 weight builds ----------
    k_transp_all<<<CDIV((256 + 128 + 64) * 128, TB), TB>>>(win_g, win_p, win_v);
    k_build_wtg<<<CDIV(512 * 128, TB), TB>>>(wsl, wsr, bsl, 0);
    k_build_wtp<<<CDIV(256 * 128, TB), TB>>>(wsl, wsr, 0);
    k_gemm_tc<false><<<CDIV(NV, 128), 256, SMB>>>(x_vacc, wtin + (256 + 128) * 128, bin_v,
                                                  (const float*)0, hv, hv16, NV, 64, 1.f);
    k_gemm_tc<false><<<CDIV(NP, 128), 256, SMB>>>(x_path, wtin + 256 * 128, bin_p,
                                                  (const float*)0, hp, hp16, NP, 128, 1.f);
    k_gemm_tc<false><<<CDIV(NG, 128), 256, SMB>>>(x_gene, wtin, bin_g,
                                                  (const float*)0, hg, hg16, NG, 256, 1.f);

    // ---------- CSR setup ----------
    cudaMemsetAsync(cnts, 0, CNTS_SZ * sizeof(int));
    k_hist4<<<CDIV(4 * EPER, TB), TB>>>(ei_t, ei_in, ei_ct, ei_ii);
    k_deg<<<CDIV(NT, TB), TB>>>();
    k_scan5<<<5, 1024>>>();
    cudaMemsetAsync(curz, 0, CURZ_SZ * sizeof(int));
    k_scatter_all<<<CDIV(4 * EPER + NT, TB), TB>>>(ei_t, ei_in, ei_ct, ei_ii);

    // ---------- 2 hetero SAGE layers ----------
    const int GBG = CDIV(NG * 16, TB);
    const int GBP = CDIV(NP * 16, TB);
    for (int l = 0; l < 2; l++) {
        k_gather_mean_h<<<GBG, TB>>>((const uint4*)hv16, roff_tg, rsrc + 0 * EPER,
                                     (float4*)sg, NG, 128, 0, (const float4*)0, 0);
        k_gather_mean_h<<<GBG, TB>>>((const uint4*)hp16, roff_ct, rsrc + 2 * EPER,
                                     (float4*)sg, NG, 128, 32, (const float4*)0, 0);
        k_gather_mean_h<<<GBG, TB>>>((const uint4*)hg16, roff_ii, rsrc + 3 * EPER,
                                     (float4*)sg, NG, 128, 64, (const float4*)hg, 96);
        k_gather_mean_h<<<GBP, TB>>>((const uint4*)hg16, roff_in, rsrc + 1 * EPER,
                                     (float4*)sp, NP, 64, 0, (const float4*)hp, 32);
        k_gemm_tc<true><<<CDIV(NG, 128), 256, SMB>>>(sg, wtg, bg, hg, hg, hg16, NG, 512, 1.f / 3.f);
        k_gemm_tc<true><<<CDIV(NP, 128), 256, SMB>>>(sp, wtp, bsl + (l * 4 + 1) * 128,
                                                     hp, hp, hp16, NP, 256, 1.f);
        if (l == 0) {
            k_build_wtg<<<CDIV(512 * 128, TB), TB>>>(wsl, wsr, bsl, 1);
            k_build_wtp<<<CDIV(256 * 128, TB), TB>>>(wsl, wsr, 1);
        }
    }

    // ---------- 8 APPNP iterations (fp16 z); last writes fp32 d_out ----------
    const int AB = CDIV(NT * 16, TB);
    __half* bufs[2] = {z16a, z16b};
    for (int k = 0; k < 7; k++) {
        const __half* zin = (k == 0) ? h16 : bufs[(k - 1) & 1];
        __half* zout = bufs[k & 1];
        k_appnp_h<false><<<AB, TB>>>((const uint4*)zin, (uint4*)zout,
                                     (const float4*)h0, (float4*)0);
    }
    k_appnp_h<true><<<AB, TB>>>((const uint4*)bufs[0], (uint4*)0,
                                (const float4*)h0, (float4*)out);
}

// round 6
// speedup vs baseline: 3.4193x; 1.1460x over previous
#include <cuda_runtime.h>
#include <cuda_fp16.h>
#include <cstdint>

#define NG 50000
#define NP 20000
#define NV 10000
#define NT 80000
#define HID 128
#define EPER 250000
#define ETOT (4*EPER + NT)
#define CDIV(a,b) (((a)+(b)-1)/(b))

#define OFF_TG 0
#define OFF_IN (NG)
#define OFF_CT (NG+NP)
#define OFF_II (2*NG+NP)
#define OFF_ALL (3*NG+NP)
#define CNTS_SZ (3*NG+NP)
#define CURZ_SZ (3*NG+NP+NT)

// ------------------------- device scratch -------------------------
__device__ float g_h0[NT*HID];                       // fp32 node features (hg|hp|hv)
__device__ __align__(16) __half g_h16[NT*HID];       // fp16 mirror (for SAGE gathers)
__device__ __align__(16) __half g_z16a[NT*HID];      // APPNP scaled state ping (z' = dinv*z)
__device__ __align__(16) __half g_z16b[NT*HID];      // pong
__device__ __align__(16) __half g_hq[NT*HID];        // 0.1*dinv*h0 (fp16)
__device__ float g_sg[NG*512];
__device__ float g_sp[NP*256];
__device__ float g_wtin[(256+128+64)*HID];
__device__ float g_wtg[512*HID];
__device__ float g_wtp[256*HID];
__device__ float g_bg[HID];
__device__ int   g_degi[NT];
__device__ float g_dinv[NT];
__device__ int   g_off[NT+1];
__device__ int   g_cnts[CNTS_SZ];
__device__ int   g_curz[CURZ_SZ];
__device__ int   g_csrc[ETOT];
__device__ int   g_roff_tg[NG+1];
__device__ int   g_roff_in[NP+1];
__device__ int   g_roff_ct[NG+1];
__device__ int   g_roff_ii[NG+1];
__device__ int   g_rsrc[4*EPER];

// ------------------------- setup kernels -------------------------
__global__ void k_hist4(const int* __restrict__ e0, const int* __restrict__ e1,
                        const int* __restrict__ e2, const int* __restrict__ e3) {
    int t = blockIdx.x * blockDim.x + threadIdx.x;
    if (t >= 4 * EPER) return;
    int r = t / EPER, e = t - r * EPER;
    const int* ei = (r == 0) ? e0 : (r == 1) ? e1 : (r == 2) ? e2 : e3;
    int base = (r == 0) ? OFF_TG : (r == 1) ? OFF_IN : (r == 2) ? OFF_CT : OFF_II;
    atomicAdd(&g_cnts[base + ei[EPER + e]], 1);
}

__global__ void k_deg() {
    int i = blockIdx.x * blockDim.x + threadIdx.x;
    if (i >= NT) return;
    int d = 1;
    if (i < NG) d += g_cnts[OFF_TG + i] + g_cnts[OFF_CT + i] + g_cnts[OFF_II + i];
    else if (i < NG + NP) d += g_cnts[OFF_IN + (i - NG)];
    g_degi[i] = d;
    g_dinv[i] = rsqrtf((float)d);
}

__global__ void k_scan5() {
    __shared__ int part[1024];
    const int* cnt; int* off; int n;
    switch (blockIdx.x) {
        case 0: cnt = g_cnts + OFF_TG; off = g_roff_tg; n = NG; break;
        case 1: cnt = g_cnts + OFF_IN; off = g_roff_in; n = NP; break;
        case 2: cnt = g_cnts + OFF_CT; off = g_roff_ct; n = NG; break;
        case 3: cnt = g_cnts + OFF_II; off = g_roff_ii; n = NG; break;
        default: cnt = g_degi; off = g_off; n = NT; break;
    }
    int t = threadIdx.x;
    int chunk = (n + 1023) / 1024;
    int lo = t * chunk, hi = min(lo + chunk, n);
    int s = 0;
    for (int i = lo; i < hi; i++) s += cnt[i];
    part[t] = s;
    __syncthreads();
    for (int o = 1; o < 1024; o <<= 1) {
        int x = (t >= o) ? part[t - o] : 0;
        __syncthreads();
        part[t] += x;
        __syncthreads();
    }
    int run = part[t] - s;
    for (int i = lo; i < hi; i++) { off[i] = run; run += cnt[i]; }
    if (t == 1023) off[n] = part[1023];
}

__global__ void k_scatter_all(const int* __restrict__ e0, const int* __restrict__ e1,
                              const int* __restrict__ e2, const int* __restrict__ e3) {
    int t = blockIdx.x * blockDim.x + threadIdx.x;
    if (t < 4 * EPER) {
        int r = t / EPER, e = t - r * EPER;
        const int* ei; const int* roff; int cbase, osrc, odst;
        if (r == 0)      { ei = e0; roff = g_roff_tg; cbase = OFF_TG; osrc = NG + NP; odst = 0; }
        else if (r == 1) { ei = e1; roff = g_roff_in; cbase = OFF_IN; osrc = 0;       odst = NG; }
        else if (r == 2) { ei = e2; roff = g_roff_ct; cbase = OFF_CT; osrc = NG;      odst = 0; }
        else             { ei = e3; roff = g_roff_ii; cbase = OFF_II; osrc = 0;       odst = 0; }
        int s = ei[e], d = ei[EPER + e];
        int p = roff[d] + atomicAdd(&g_curz[cbase + d], 1);
        g_rsrc[r * EPER + p] = s;
        int gd = d + odst;
        int p2 = g_off[gd] + atomicAdd(&g_curz[OFF_ALL + gd], 1);
        g_csrc[p2] = s + osrc;
    } else if (t < 4 * EPER + NT) {
        int i = t - 4 * EPER;
        int p = g_off[i] + atomicAdd(&g_curz[OFF_ALL + i], 1);
        g_csrc[p] = i;
    }
}

// fused: input-proj transposes + layer-0 weight builds
__global__ void k_prep(const float* __restrict__ wg, const float* __restrict__ wp,
                       const float* __restrict__ wv, const float* __restrict__ wsl,
                       const float* __restrict__ wsr, const float* __restrict__ bsl) {
    int idx = blockIdx.x * blockDim.x + threadIdx.x;
    const int T0 = 256 * 128, T1 = T0 + 128 * 128, T2 = T1 + 64 * 128;
    const int W0 = T2 + 512 * 128, W1 = W0 + 256 * 128;
    if (idx < T0) {
        int k = idx >> 7, n = idx & 127;
        g_wtin[idx] = wg[n * 256 + k];
    } else if (idx < T1) {
        int i = idx - T0; int k = i >> 7, n = i & 127;
        g_wtin[idx] = wp[n * 128 + k];
    } else if (idx < T2) {
        int i = idx - T1; int k = i >> 7, n = i & 127;
        g_wtin[idx] = wv[n * 64 + k];
    } else if (idx < W0) {
        int i = idx - T2;
        int k = i >> 7, n = i & 127;
        int b = k >> 7, kk = k & 127;
        float v;
        if (b == 0)      v = wsl[(0 * 128 + n) * 128 + kk];
        else if (b == 1) v = wsl[(2 * 128 + n) * 128 + kk];
        else if (b == 2) v = wsl[(3 * 128 + n) * 128 + kk];
        else             v = wsr[(0 * 128 + n) * 128 + kk]
                           + wsr[(2 * 128 + n) * 128 + kk]
                           + wsr[(3 * 128 + n) * 128 + kk];
        g_wtg[i] = v;
        if (i < 128) g_bg[i] = bsl[0 * 128 + i] + bsl[2 * 128 + i] + bsl[3 * 128 + i];
    } else if (idx < W1) {
        int i = idx - W0;
        int k = i >> 7, n = i & 127;
        int b = k >> 7, kk = k & 127;
        g_wtp[i] = (b == 0) ? wsl[(1 * 128 + n) * 128 + kk]
                            : wsr[(1 * 128 + n) * 128 + kk];
    }
}

// fused layer-1 weight builds
__global__ void k_build2(const float* __restrict__ wsl, const float* __restrict__ wsr,
                         const float* __restrict__ bsl) {
    int idx = blockIdx.x * blockDim.x + threadIdx.x;
    const int l = 1;
    if (idx < 512 * 128) {
        int k = idx >> 7, n = idx & 127;
        int b = k >> 7, kk = k & 127;
        float v;
        if (b == 0)      v = wsl[((l * 4 + 0) * 128 + n) * 128 + kk];
        else if (b == 1) v = wsl[((l * 4 + 2) * 128 + n) * 128 + kk];
        else if (b == 2) v = wsl[((l * 4 + 3) * 128 + n) * 128 + kk];
        else             v = wsr[((l * 4 + 0) * 128 + n) * 128 + kk]
                           + wsr[((l * 4 + 2) * 128 + n) * 128 + kk]
                           + wsr[((l * 4 + 3) * 128 + n) * 128 + kk];
        g_wtg[idx] = v;
        if (idx < 128)
            g_bg[idx] = bsl[(l * 4 + 0) * 128 + idx] + bsl[(l * 4 + 2) * 128 + idx]
                      + bsl[(l * 4 + 3) * 128 + idx];
    } else if (idx < 512 * 128 + 256 * 128) {
        int i = idx - 512 * 128;
        int k = i >> 7, n = i & 127;
        int b = k >> 7, kk = k & 127;
        g_wtp[i] = (b == 0) ? wsl[((l * 4 + 1) * 128 + n) * 128 + kk]
                            : wsr[((l * 4 + 1) * 128 + n) * 128 + kk];
    }
}

// ------------------------- TF32 tensor-core GEMM (KTILE=32) -------------------------
__device__ __forceinline__ uint32_t f2tf(float x) {
    uint32_t r;
    asm("cvt.rna.tf32.f32 %0, %1;" : "=r"(r) : "f"(x));
    return r;
}
__device__ __forceinline__ void mma_tf32(float c[4], uint32_t a0, uint32_t a1,
                                         uint32_t a2, uint32_t a3,
                                         uint32_t b0, uint32_t b1) {
    asm volatile(
        "mma.sync.aligned.m16n8k8.row.col.f32.tf32.tf32.f32 "
        "{%0,%1,%2,%3}, {%4,%5,%6,%7}, {%8,%9}, {%0,%1,%2,%3};"
        : "+f"(c[0]), "+f"(c[1]), "+f"(c[2]), "+f"(c[3])
        : "r"(a0), "r"(a1), "r"(a2), "r"(a3), "r"(b0), "r"(b1));
}

#define AST 36
#define BST 136
#define ABUF (128*AST)
#define BBUF (32*BST)
#define SMEM_WORDS (2*ABUF + 2*BBUF)

// epilogue extras: h16out always; if zs!=0 also write zs=dinv*v (fp16) and hq=0.1*dinv*v (fp16)
template<bool RES>
__global__ __launch_bounds__(256)
void k_gemm_tc(const float* __restrict__ A, const float* __restrict__ Wt,
               const float* __restrict__ bias, const float* __restrict__ res,
               float* __restrict__ out, __half* __restrict__ h16out,
               __half* __restrict__ zs, __half* __restrict__ hqo,
               const float* __restrict__ dv,
               int M, int K, float scale)
{
    extern __shared__ uint32_t sm[];
    uint32_t* Asm = sm;
    uint32_t* Bsm = sm + 2 * ABUF;

    int tid  = threadIdx.x;
    int lane = tid & 31;
    int wid  = tid >> 5;
    int wm = wid >> 2;
    int wn = wid & 3;
    int g   = lane >> 2;
    int tig = lane & 3;

    int rowBase = blockIdx.x * 128;

    int a_r  = tid >> 1;
    int a_kb = (tid & 1) * 16;
    int b_r  = tid >> 3;
    int b_cq = (tid & 7) * 4;

    float acc[4][4][4];
#pragma unroll
    for (int mt = 0; mt < 4; mt++)
#pragma unroll
        for (int nt = 0; nt < 4; nt++)
#pragma unroll
            for (int r = 0; r < 4; r++) acc[mt][nt][r] = 0.f;

    int ntk = K >> 5;
    int gr = rowBase + a_r;

    {
        float4 av[4], bv[4];
#pragma unroll
        for (int j = 0; j < 4; j++) {
            av[j] = (gr < M) ? *(const float4*)&A[(size_t)gr * K + a_kb + 4 * j]
                             : make_float4(0, 0, 0, 0);
            bv[j] = *(const float4*)&Wt[(size_t)b_r * 128 + b_cq + 32 * j];
        }
#pragma unroll
        for (int j = 0; j < 4; j++) {
            uint32_t* pa = &Asm[a_r * AST + a_kb + 4 * j];
            pa[0] = f2tf(av[j].x); pa[1] = f2tf(av[j].y);
            pa[2] = f2tf(av[j].z); pa[3] = f2tf(av[j].w);
            uint32_t* pb = &Bsm[b_r * BST + b_cq + 32 * j];
            pb[0] = f2tf(bv[j].x); pb[1] = f2tf(bv[j].y);
            pb[2] = f2tf(bv[j].z); pb[3] = f2tf(bv[j].w);
        }
    }
    __syncthreads();

    for (int t = 0; t < ntk; t++) {
        int buf = t & 1;
        bool more = (t + 1 < ntk);
        float4 av[4], bv[4];
        if (more) {
            int k0 = (t + 1) << 5;
#pragma unroll
            for (int j = 0; j < 4; j++) {
                av[j] = (gr < M) ? *(const float4*)&A[(size_t)gr * K + k0 + a_kb + 4 * j]
                                 : make_float4(0, 0, 0, 0);
                bv[j] = *(const float4*)&Wt[(size_t)(k0 + b_r) * 128 + b_cq + 32 * j];
            }
        }
        const uint32_t* Ab = Asm + buf * ABUF;
        const uint32_t* Bb = Bsm + buf * BBUF;
#pragma unroll
        for (int ks = 0; ks < 32; ks += 8) {
            uint32_t af[4][4], bf[4][2];
#pragma unroll
            for (int mt = 0; mt < 4; mt++) {
                int r0 = wm * 64 + mt * 16 + g;
                af[mt][0] = Ab[r0 * AST + ks + tig];
                af[mt][1] = Ab[(r0 + 8) * AST + ks + tig];
                af[mt][2] = Ab[r0 * AST + ks + tig + 4];
                af[mt][3] = Ab[(r0 + 8) * AST + ks + tig + 4];
            }
#pragma unroll
            for (int nt = 0; nt < 4; nt++) {
                int c0 = wn * 32 + nt * 8 + g;
                bf[nt][0] = Bb[(ks + tig) * BST + c0];
                bf[nt][1] = Bb[(ks + tig + 4) * BST + c0];
            }
#pragma unroll
            for (int mt = 0; mt < 4; mt++)
#pragma unroll
                for (int nt = 0; nt < 4; nt++)
                    mma_tf32(acc[mt][nt], af[mt][0], af[mt][1], af[mt][2], af[mt][3],
                             bf[nt][0], bf[nt][1]);
        }
        if (more) {
            int nb = buf ^ 1;
            uint32_t* An = Asm + nb * ABUF;
            uint32_t* Bn = Bsm + nb * BBUF;
#pragma unroll
            for (int j = 0; j < 4; j++) {
                uint32_t* pa = &An[a_r * AST + a_kb + 4 * j];
                pa[0] = f2tf(av[j].x); pa[1] = f2tf(av[j].y);
                pa[2] = f2tf(av[j].z); pa[3] = f2tf(av[j].w);
                uint32_t* pb = &Bn[b_r * BST + b_cq + 32 * j];
                pb[0] = f2tf(bv[j].x); pb[1] = f2tf(bv[j].y);
                pb[2] = f2tf(bv[j].z); pb[3] = f2tf(bv[j].w);
            }
        }
        __syncthreads();
    }

#pragma unroll
    for (int mt = 0; mt < 4; mt++) {
#pragma unroll
        for (int nt = 0; nt < 4; nt++) {
            int col = wn * 32 + nt * 8 + tig * 2;
            float b0 = bias[col], b1 = bias[col + 1];
#pragma unroll
            for (int h = 0; h < 2; h++) {
                int row = rowBase + wm * 64 + mt * 16 + g + h * 8;
                if (row >= M) continue;
                float v0 = acc[mt][nt][h * 2 + 0] + b0;
                float v1 = acc[mt][nt][h * 2 + 1] + b1;
                if (RES) {
                    float2 rv = *(const float2*)&res[(size_t)row * HID + col];
                    v0 = rv.x + v0 * scale;
                    v1 = rv.y + v1 * scale;
                }
                v0 = fmaxf(v0, 0.f);
                v1 = fmaxf(v1, 0.f);
                float2 o; o.x = v0; o.y = v1;
                *(float2*)&out[(size_t)row * HID + col] = o;
                *(__half2*)&h16out[(size_t)row * HID + col] = __floats2half2_rn(v0, v1);
                if (zs) {
                    float d = dv[row];
                    *(__half2*)&zs[(size_t)row * HID + col] =
                        __floats2half2_rn(v0 * d, v1 * d);
                    *(__half2*)&hqo[(size_t)row * HID + col] =
                        __floats2half2_rn(0.1f * d * v0, 0.1f * d * v1);
                }
            }
        }
    }
}

// ------------------------- fp16 helpers -------------------------
__device__ __forceinline__ void h8_add(uint4 v, float a[8]) {
    const __half2* h = (const __half2*)&v;
#pragma unroll
    for (int j = 0; j < 4; j++) {
        float2 f = __half22float2(h[j]);
        a[2 * j]     += f.x;
        a[2 * j + 1] += f.y;
    }
}

// ------------------------- fused SAGE gathers (all 4 relations, one launch) -------------------------
__global__ void k_gather_all() {
    int t = blockIdx.x * blockDim.x + threadIdx.x;
    int lane = t & 15, slot = t >> 4;
    if (slot >= 3 * NG + NP) return;
    const __half* xs; const int* off; const int* es;
    float* dst; int stride4, col4, node;
    const float* cp = 0; int ccol4 = 0;
    if (slot < NG) {
        node = slot; xs = g_h16 + (size_t)(NG + NP) * HID;
        off = g_roff_tg; es = g_rsrc; dst = g_sg; stride4 = 128; col4 = 0;
    } else if (slot < 2 * NG) {
        node = slot - NG; xs = g_h16 + (size_t)NG * HID;
        off = g_roff_ct; es = g_rsrc + 2 * EPER; dst = g_sg; stride4 = 128; col4 = 32;
    } else if (slot < 3 * NG) {
        node = slot - 2 * NG; xs = g_h16;
        off = g_roff_ii; es = g_rsrc + 3 * EPER; dst = g_sg; stride4 = 128; col4 = 64;
        cp = g_h0; ccol4 = 96;
    } else {
        node = slot - 3 * NG; xs = g_h16;
        off = g_roff_in; es = g_rsrc + 1 * EPER; dst = g_sp; stride4 = 64; col4 = 0;
        cp = g_h0 + (size_t)NG * HID; ccol4 = 32;
    }
    const uint4* x4 = (const uint4*)xs;
    int e0 = off[node], e1 = off[node + 1];
    float a[8] = {0.f, 0.f, 0.f, 0.f, 0.f, 0.f, 0.f, 0.f};
    int e = e0;
    for (; e + 2 <= e1; e += 2) {
        int s0 = es[e], s1 = es[e + 1];
        uint4 v0 = __ldg(&x4[(size_t)s0 * 16 + lane]);
        uint4 v1 = __ldg(&x4[(size_t)s1 * 16 + lane]);
        h8_add(v0, a);
        h8_add(v1, a);
    }
    if (e < e1) {
        uint4 v = __ldg(&x4[(size_t)es[e] * 16 + lane]);
        h8_add(v, a);
    }
    float inv = 1.f / fmaxf((float)(e1 - e0), 1.f);
    size_t base = (size_t)node * stride4 + col4 + lane * 2;
    ((float4*)dst)[base]     = make_float4(a[0] * inv, a[1] * inv, a[2] * inv, a[3] * inv);
    ((float4*)dst)[base + 1] = make_float4(a[4] * inv, a[5] * inv, a[6] * inv, a[7] * inv);
    if (cp) {
        size_t cb = (size_t)node * stride4 + ccol4 + lane * 2;
        ((float4*)dst)[cb]     = ((const float4*)cp)[node * 32 + lane * 2];
        ((float4*)dst)[cb + 1] = ((const float4*)cp)[node * 32 + lane * 2 + 1];
    }
}

// ------------------------- APPNP step on scaled state -------------------------
// middle: z'_out = 0.9*dinv^2 * S + hq         (hq = 0.1*dinv*h0, fp16 in/out)
// last:   out    = 0.9*dinv   * S + 0.1*h0     (fp32 out)
template<bool LAST>
__global__ void k_appnp_s(const uint4* __restrict__ z, uint4* __restrict__ zn,
                          float4* __restrict__ outf) {
    int t = blockIdx.x * blockDim.x + threadIdx.x;
    int lane = t & 15, node = t >> 4;
    if (node >= NT) return;
    int e0 = g_off[node], e1 = g_off[node + 1];
    float a[8] = {0.f, 0.f, 0.f, 0.f, 0.f, 0.f, 0.f, 0.f};
    int e = e0;
    for (; e + 2 <= e1; e += 2) {
        int s0 = g_csrc[e], s1 = g_csrc[e + 1];
        uint4 v0 = __ldg(&z[(size_t)s0 * 16 + lane]);
        uint4 v1 = __ldg(&z[(size_t)s1 * 16 + lane]);
        h8_add(v0, a);
        h8_add(v1, a);
    }
    if (e < e1) {
        uint4 v = __ldg(&z[(size_t)g_csrc[e] * 16 + lane]);
        h8_add(v, a);
    }
    float d = g_dinv[node];
    if (LAST) {
        float c = 0.9f * d;
        const float4* h0p = (const float4*)g_h0;
        float4 ha = h0p[(size_t)node * 32 + lane * 2];
        float4 hb = h0p[(size_t)node * 32 + lane * 2 + 1];
        outf[(size_t)node * 32 + lane * 2] =
            make_float4(c * a[0] + 0.1f * ha.x, c * a[1] + 0.1f * ha.y,
                        c * a[2] + 0.1f * ha.z, c * a[3] + 0.1f * ha.w);
        outf[(size_t)node * 32 + lane * 2 + 1] =
            make_float4(c * a[4] + 0.1f * hb.x, c * a[5] + 0.1f * hb.y,
                        c * a[6] + 0.1f * hb.z, c * a[7] + 0.1f * hb.w);
    } else {
        float c1 = 0.9f * d * d;
        uint4 hqv = ((const uint4*)g_hq)[(size_t)node * 16 + lane];
        const __half2* hh = (const __half2*)&hqv;
        float r[8];
#pragma unroll
        for (int j = 0; j < 4; j++) {
            float2 f = __half22float2(hh[j]);
            r[2 * j]     = c1 * a[2 * j]     + f.x;
            r[2 * j + 1] = c1 * a[2 * j + 1] + f.y;
        }
        uint4 pk;
        __half2* ph = (__half2*)&pk;
        ph[0] = __floats2half2_rn(r[0], r[1]);
        ph[1] = __floats2half2_rn(r[2], r[3]);
        ph[2] = __floats2half2_rn(r[4], r[5]);
        ph[3] = __floats2half2_rn(r[6], r[7]);
        zn[(size_t)node * 16 + lane] = pk;
    }
}

// ------------------------- host orchestration -------------------------
extern "C" void kernel_launch(void* const* d_in, const int* in_sizes, int n_in,
                              void* d_out, int out_size) {
    const float* x_gene  = (const float*)d_in[0];
    const float* x_path  = (const float*)d_in[1];
    const float* x_vacc  = (const float*)d_in[2];
    const float* win_g   = (const float*)d_in[3];
    const float* bin_g   = (const float*)d_in[4];
    const float* win_p   = (const float*)d_in[5];
    const float* bin_p   = (const float*)d_in[6];
    const float* win_v   = (const float*)d_in[7];
    const float* bin_v   = (const float*)d_in[8];
    const float* wsl     = (const float*)d_in[9];
    const float* bsl     = (const float*)d_in[10];
    const float* wsr     = (const float*)d_in[11];
    const int*   ei_t    = (const int*)d_in[12];
    const int*   ei_in   = (const int*)d_in[13];
    const int*   ei_ct   = (const int*)d_in[14];
    const int*   ei_ii   = (const int*)d_in[15];
    float* out = (float*)d_out;

    float *h0, *wtin, *wtg, *wtp, *bg, *dinv, *sg, *sp;
    __half *h16, *z16a, *z16b, *hq;
    int *cnts, *curz;
    cudaGetSymbolAddress((void**)&h0, g_h0);
    cudaGetSymbolAddress((void**)&h16, g_h16);
    cudaGetSymbolAddress((void**)&z16a, g_z16a);
    cudaGetSymbolAddress((void**)&z16b, g_z16b);
    cudaGetSymbolAddress((void**)&hq, g_hq);
    cudaGetSymbolAddress((void**)&wtin, g_wtin);
    cudaGetSymbolAddress((void**)&wtg, g_wtg);
    cudaGetSymbolAddress((void**)&wtp, g_wtp);
    cudaGetSymbolAddress((void**)&bg,  g_bg);
    cudaGetSymbolAddress((void**)&dinv, g_dinv);
    cudaGetSymbolAddress((void**)&sg, g_sg);
    cudaGetSymbolAddress((void**)&sp, g_sp);
    cudaGetSymbolAddress((void**)&cnts, g_cnts);
    cudaGetSymbolAddress((void**)&curz, g_curz);

    float* hg = h0;
    float* hp = h0 + (size_t)NG * HID;
    float* hv = h0 + (size_t)(NG + NP) * HID;
    __half* hg16 = h16;
    __half* hp16 = h16 + (size_t)NG * HID;
    __half* hv16 = h16 + (size_t)(NG + NP) * HID;

    const int TB = 256;
    const int SMB = SMEM_WORDS * 4;
    static bool attr_set = false;
    if (!attr_set) {
        cudaFuncSetAttribute(k_gemm_tc<false>, cudaFuncAttributeMaxDynamicSharedMemorySize, SMB);
        cudaFuncSetAttribute(k_gemm_tc<true>,  cudaFuncAttributeMaxDynamicSharedMemorySize, SMB);
        attr_set = true;
    }

    // ---------- CSR setup first (so dinv is ready for epilogue prescaling) ----------
    cudaMemsetAsync(cnts, 0, CNTS_SZ * sizeof(int));
    k_hist4<<<CDIV(4 * EPER, TB), TB>>>(ei_t, ei_in, ei_ct, ei_ii);
    k_deg<<<CDIV(NT, TB), TB>>>();
    k_scan5<<<5, 1024>>>();
    cudaMemsetAsync(curz, 0, CURZ_SZ * sizeof(int));
    k_scatter_all<<<CDIV(4 * EPER + NT, TB), TB>>>(ei_t, ei_in, ei_ct, ei_ii);

    // ---------- weight prep (transposes + layer-0 builds) ----------
    k_prep<<<CDIV((256 + 128 + 64) * 128 + 512 * 128 + 256 * 128, TB), TB>>>(
        win_g, win_p, win_v, wsl, wsr, bsl);

    // ---------- input projections ----------
    // hv is never changed by SAGE -> emit its scaled APPNP state + hq now
    k_gemm_tc<false><<<CDIV(NV, 128), 256, SMB>>>(x_vacc, wtin + (256 + 128) * 128, bin_v,
        (const float*)0, hv, hv16,
        z16a + (size_t)(NG + NP) * HID, hq + (size_t)(NG + NP) * HID,
        dinv + (NG + NP), NV, 64, 1.f);
    k_gemm_tc<false><<<CDIV(NP, 128), 256, SMB>>>(x_path, wtin + 256 * 128, bin_p,
        (const float*)0, hp, hp16, (__half*)0, (__half*)0, (const float*)0, NP, 128, 1.f);
    k_gemm_tc<false><<<CDIV(NG, 128), 256, SMB>>>(x_gene, wtin, bin_g,
        (const float*)0, hg, hg16, (__half*)0, (__half*)0, (const float*)0, NG, 256, 1.f);

    // ---------- SAGE layer 0 ----------
    const int GALL = CDIV((3 * NG + NP) * 16, TB);
    k_gather_all<<<GALL, TB>>>();
    k_gemm_tc<true><<<CDIV(NG, 128), 256, SMB>>>(sg, wtg, bg, hg, hg, hg16,
        (__half*)0, (__half*)0, (const float*)0, NG, 512, 1.f / 3.f);
    k_gemm_tc<true><<<CDIV(NP, 128), 256, SMB>>>(sp, wtp, bsl + 1 * 128, hp, hp, hp16,
        (__half*)0, (__half*)0, (const float*)0, NP, 256, 1.f);
    k_build2<<<CDIV(512 * 128 + 256 * 128, TB), TB>>>(wsl, wsr, bsl);

    // ---------- SAGE layer 1 (final state -> emit scaled z + hq in epilogue) ----------
    k_gather_all<<<GALL, TB>>>();
    k_gemm_tc<true><<<CDIV(NG, 128), 256, SMB>>>(sg, wtg, bg, hg, hg, hg16,
        z16a, hq, dinv, NG, 512, 1.f / 3.f);
    k_gemm_tc<true><<<CDIV(NP, 128), 256, SMB>>>(sp, wtp, bsl + (4 + 1) * 128, hp, hp, hp16,
        z16a + (size_t)NG * HID, hq + (size_t)NG * HID, dinv + NG, NP, 256, 1.f);

    // ---------- 8 APPNP iterations on scaled state; last writes fp32 d_out ----------
    const int AB = CDIV(NT * 16, TB);
    // steps 0..6 middle: in = (k even ? a : b), out = other; step 7 last: in = b
    __half* bufs[2] = {z16a, z16b};
    for (int k = 0; k < 7; k++) {
        const __half* zin = bufs[k & 1];
        __half* zout = bufs[(k & 1) ^ 1];
        k_appnp_s<false><<<AB, TB>>>((const uint4*)zin, (uint4*)zout, (float4*)0);
    }
    k_appnp_s<true><<<AB, TB>>>((const uint4*)bufs[1], (uint4*)0, (float4*)out);
}

// round 8
// speedup vs baseline: 3.8358x; 1.1218x over previous
#include <cuda_runtime.h>
#include <cuda_fp16.h>
#include <cstdint>

#define NG 50000
#define NP 20000
#define NV 10000
#define NT 80000
#define HID 128
#define EPER 250000
#define ETOT (4*EPER + NT)
#define CDIV(a,b) (((a)+(b)-1)/(b))

#define OFF_TG 0
#define OFF_IN (NG)
#define OFF_CT (NG+NP)
#define OFF_II (2*NG+NP)
#define OFF_ALL (3*NG+NP)
#define CNTS_SZ (3*NG+NP)
#define CURZ_SZ (3*NG+NP+NT)

// ------------------------- device scratch -------------------------
__device__ float g_h0[NT*HID];                       // fp32 node features (hg|hp|hv)
__device__ __align__(16) __half g_h16[NT*HID];       // fp16 mirror (SAGE gathers)
__device__ __align__(16) __half g_z16a[NT*HID];      // APPNP scaled state ping
__device__ __align__(16) __half g_z16b[NT*HID];      // pong
__device__ __align__(16) __half g_hq[NT*HID];        // 0.1*dinv*h0 (fp16)
__device__ __align__(16) __half g_sg16[NG*512];      // gene staging (fp16)
__device__ __align__(16) __half g_sp16[NP*256];      // pathway staging (fp16)
__device__ __align__(16) __half g_wtin16[(256+128+64)*HID]; // input-proj W, [n][k] fp16
__device__ __align__(16) __half g_wtg16[512*HID];    // gene concat W, [n=128][k=512] fp16
__device__ __align__(16) __half g_wtp16[256*HID];    // pathway concat W, [n=128][k=256] fp16
__device__ float g_bg[HID];
__device__ int   g_degi[NT];
__device__ float g_dinv[NT];
__device__ int   g_off[NT+1];
__device__ int   g_cnts[CNTS_SZ];
__device__ int   g_curz[CURZ_SZ];
__device__ int   g_csrc[ETOT];
__device__ int   g_roff_tg[NG+1];
__device__ int   g_roff_in[NP+1];
__device__ int   g_roff_ct[NG+1];
__device__ int   g_roff_ii[NG+1];
__device__ int   g_rsrc[4*EPER];

__device__ __forceinline__ uint32_t h2u(__half2 h) {
    uint32_t u;
    memcpy(&u, &h, 4);
    return u;
}

// ------------------------- setup kernels -------------------------
__global__ void k_hist4(const int* __restrict__ e0, const int* __restrict__ e1,
                        const int* __restrict__ e2, const int* __restrict__ e3) {
    int t = blockIdx.x * blockDim.x + threadIdx.x;
    if (t >= 4 * EPER) return;
    int r = t / EPER, e = t - r * EPER;
    const int* ei = (r == 0) ? e0 : (r == 1) ? e1 : (r == 2) ? e2 : e3;
    int base = (r == 0) ? OFF_TG : (r == 1) ? OFF_IN : (r == 2) ? OFF_CT : OFF_II;
    atomicAdd(&g_cnts[base + ei[EPER + e]], 1);
}

__global__ void k_deg() {
    int i = blockIdx.x * blockDim.x + threadIdx.x;
    if (i >= NT) return;
    int d = 1;
    if (i < NG) d += g_cnts[OFF_TG + i] + g_cnts[OFF_CT + i] + g_cnts[OFF_II + i];
    else if (i < NG + NP) d += g_cnts[OFF_IN + (i - NG)];
    g_degi[i] = d;
    g_dinv[i] = rsqrtf((float)d);
}

__global__ void k_scan5() {
    __shared__ int part[1024];
    const int* cnt; int* off; int n;
    switch (blockIdx.x) {
        case 0: cnt = g_cnts + OFF_TG; off = g_roff_tg; n = NG; break;
        case 1: cnt = g_cnts + OFF_IN; off = g_roff_in; n = NP; break;
        case 2: cnt = g_cnts + OFF_CT; off = g_roff_ct; n = NG; break;
        case 3: cnt = g_cnts + OFF_II; off = g_roff_ii; n = NG; break;
        default: cnt = g_degi; off = g_off; n = NT; break;
    }
    int t = threadIdx.x;
    int chunk = (n + 1023) / 1024;
    int lo = t * chunk, hi = min(lo + chunk, n);
    int s = 0;
    for (int i = lo; i < hi; i++) s += cnt[i];
    part[t] = s;
    __syncthreads();
    for (int o = 1; o < 1024; o <<= 1) {
        int x = (t >= o) ? part[t - o] : 0;
        __syncthreads();
        part[t] += x;
        __syncthreads();
    }
    int run = part[t] - s;
    for (int i = lo; i < hi; i++) { off[i] = run; run += cnt[i]; }
    if (t == 1023) off[n] = part[1023];
}

__global__ void k_scatter_all(const int* __restrict__ e0, const int* __restrict__ e1,
                              const int* __restrict__ e2, const int* __restrict__ e3) {
    int t = blockIdx.x * blockDim.x + threadIdx.x;
    if (t < 4 * EPER) {
        int r = t / EPER, e = t - r * EPER;
        const int* ei; const int* roff; int cbase, osrc, odst;
        if (r == 0)      { ei = e0; roff = g_roff_tg; cbase = OFF_TG; osrc = NG + NP; odst = 0; }
        else if (r == 1) { ei = e1; roff = g_roff_in; cbase = OFF_IN; osrc = 0;       odst = NG; }
        else if (r == 2) { ei = e2; roff = g_roff_ct; cbase = OFF_CT; osrc = NG;      odst = 0; }
        else             { ei = e3; roff = g_roff_ii; cbase = OFF_II; osrc = 0;       odst = 0; }
        int s = ei[e], d = ei[EPER + e];
        int p = roff[d] + atomicAdd(&g_curz[cbase + d], 1);
        g_rsrc[r * EPER + p] = s;
        int gd = d + odst;
        int p2 = g_off[gd] + atomicAdd(&g_curz[OFF_ALL + gd], 1);
        g_csrc[p2] = s + osrc;
    } else if (t < 4 * EPER + NT) {
        int i = t - 4 * EPER;
        int p = g_off[i] + atomicAdd(&g_curz[OFF_ALL + i], 1);
        g_csrc[p] = i;
    }
}

// fused weight prep: input-proj fp16 copies + layer-l SAGE weight builds (all [n][k] layout)
__global__ void k_prep16(const float* __restrict__ wg, const float* __restrict__ wp,
                         const float* __restrict__ wv, const float* __restrict__ wsl,
                         const float* __restrict__ wsr, const float* __restrict__ bsl,
                         int l, int do_in) {
    int idx = blockIdx.x * blockDim.x + threadIdx.x;
    const int TIN = (256 + 128 + 64) * 128;           // flat input-proj copies
    const int WG  = 512 * 128;
    int base = do_in ? TIN : 0;
    if (do_in && idx < TIN) {
        float v;
        if (idx < 256 * 128) v = wg[idx];
        else if (idx < (256 + 128) * 128) v = wp[idx - 256 * 128];
        else v = wv[idx - (256 + 128) * 128];
        g_wtin16[idx] = __float2half(v);
        return;
    }
    int i = idx - base;
    if (i < 0) return;
    if (i < WG) {
        // wtg16[n][k], k blocks: wl0 | wl2 | wl3 | wr0+wr2+wr3
        int n = i >> 9, k = i & 511;
        int b = k >> 7, kk = k & 127;
        float v;
        if (b == 0)      v = wsl[((l * 4 + 0) * 128 + n) * 128 + kk];
        else if (b == 1) v = wsl[((l * 4 + 2) * 128 + n) * 128 + kk];
        else if (b == 2) v = wsl[((l * 4 + 3) * 128 + n) * 128 + kk];
        else             v = wsr[((l * 4 + 0) * 128 + n) * 128 + kk]
                           + wsr[((l * 4 + 2) * 128 + n) * 128 + kk]
                           + wsr[((l * 4 + 3) * 128 + n) * 128 + kk];
        g_wtg16[i] = __float2half(v);
        if (i < 128)
            g_bg[i] = bsl[(l * 4 + 0) * 128 + i] + bsl[(l * 4 + 2) * 128 + i]
                    + bsl[(l * 4 + 3) * 128 + i];
    } else if (i < WG + 256 * 128) {
        int j = i - WG;
        int n = j >> 8, k = j & 255;
        int b = k >> 7, kk = k & 127;
        float v = (b == 0) ? wsl[((l * 4 + 1) * 128 + n) * 128 + kk]
                           : wsr[((l * 4 + 1) * 128 + n) * 128 + kk];
        g_wtp16[j] = __float2half(v);
    }
}

// ------------------------- FP16 tensor-core GEMM (KTILE=32) -------------------------
__device__ __forceinline__ void mma_f16(float c[4], uint32_t a0, uint32_t a1,
                                        uint32_t a2, uint32_t a3,
                                        uint32_t b0, uint32_t b1) {
    asm volatile(
        "mma.sync.aligned.m16n8k16.row.col.f32.f16.f16.f32 "
        "{%0,%1,%2,%3}, {%4,%5,%6,%7}, {%8,%9}, {%0,%1,%2,%3};"
        : "+f"(c[0]), "+f"(c[1]), "+f"(c[2]), "+f"(c[3])
        : "r"(a0), "r"(a1), "r"(a2), "r"(a3), "r"(b0), "r"(b1));
}

#define SST 20               // smem row stride in words (16 data + 4 pad)
#define TBUF (128*SST)       // one A or B buffer (words)
#define GSMEM_BYTES (4*TBUF*4)

// A: [M,K]; AH: A is fp16 (else fp32, converted on load). B(W16): [128 n][K k] fp16.
// out = relu((A@W^T + bias)*scale + res); also h16out; optional zs=dinv*v, hq=0.1*dinv*v.
template<bool RES, bool AH>
__global__ __launch_bounds__(256)
void k_gemm16(const void* __restrict__ Araw, const __half* __restrict__ W16,
              const float* __restrict__ bias, const float* __restrict__ res,
              float* __restrict__ out, __half* __restrict__ h16out,
              __half* __restrict__ zs, __half* __restrict__ hqo,
              const float* __restrict__ dv,
              int M, int K, float scale)
{
    extern __shared__ uint32_t sm[];
    uint32_t* Asm = sm;              // [2][128][SST]
    uint32_t* Bsm = sm + 2 * TBUF;   // [2][128][SST]

    int tid  = threadIdx.x;
    int lane = tid & 31;
    int wid  = tid >> 5;
    int wm = wid >> 2;
    int wn = wid & 3;
    int g   = lane >> 2;
    int tig = lane & 3;

    int rowBase = blockIdx.x * 128;
    int r_ld  = tid >> 1;            // 0..127 (row for both A and B loads)
    int hsel  = (tid & 1);           // which 16-half chunk

    float acc[4][4][4];
#pragma unroll
    for (int mt = 0; mt < 4; mt++)
#pragma unroll
        for (int nt = 0; nt < 4; nt++)
#pragma unroll
            for (int r = 0; r < 4; r++) acc[mt][nt][r] = 0.f;

    int ntk = K >> 5;
    int gr = rowBase + r_ld;
    const __half* Ah = (const __half*)Araw;
    const float*  Af = (const float*)Araw;

    // load helpers: produce two uint4 (8 words = 16 halves) for row r at k-chunk
    auto loadA = [&](int k0, uint4& u0, uint4& u1) {
        if (AH) {
            if (gr < M) {
                const uint4* p = (const uint4*)&Ah[(size_t)gr * K + k0 + hsel * 16];
                u0 = p[0]; u1 = p[1];
            } else { u0 = make_uint4(0,0,0,0); u1 = make_uint4(0,0,0,0); }
        } else {
            if (gr < M) {
                const float4* p = (const float4*)&Af[(size_t)gr * K + k0 + hsel * 16];
                float4 f0 = p[0], f1 = p[1], f2 = p[2], f3 = p[3];
                uint32_t* w0 = (uint32_t*)&u0;
                uint32_t* w1 = (uint32_t*)&u1;
                w0[0] = h2u(__floats2half2_rn(f0.x, f0.y));
                w0[1] = h2u(__floats2half2_rn(f0.z, f0.w));
                w0[2] = h2u(__floats2half2_rn(f1.x, f1.y));
                w0[3] = h2u(__floats2half2_rn(f1.z, f1.w));
                w1[0] = h2u(__floats2half2_rn(f2.x, f2.y));
                w1[1] = h2u(__floats2half2_rn(f2.z, f2.w));
                w1[2] = h2u(__floats2half2_rn(f3.x, f3.y));
                w1[3] = h2u(__floats2half2_rn(f3.z, f3.w));
            } else { u0 = make_uint4(0,0,0,0); u1 = make_uint4(0,0,0,0); }
        }
    };
    auto loadB = [&](int k0, uint4& u0, uint4& u1) {
        const uint4* p = (const uint4*)&W16[(size_t)r_ld * K + k0 + hsel * 16];
        u0 = p[0]; u1 = p[1];
    };
    auto store = [&](uint32_t* buf, uint4 u0, uint4 u1) {
        int base = r_ld * SST + hsel * 8;
        *(uint4*)&buf[base] = u0;
        *(uint4*)&buf[base + 4] = u1;
    };

    {   // preload tile 0
        uint4 a0, a1, b0, b1;
        loadA(0, a0, a1);
        loadB(0, b0, b1);
        store(Asm, a0, a1);
        store(Bsm, b0, b1);
    }
    __syncthreads();

    for (int t = 0; t < ntk; t++) {
        int buf = t & 1;
        bool more = (t + 1 < ntk);
        uint4 an0, an1, bn0, bn1;
        if (more) {
            int k0 = (t + 1) << 5;
            loadA(k0, an0, an1);
            loadB(k0, bn0, bn1);
        }
        const uint32_t* Ab = Asm + buf * TBUF;
        const uint32_t* Bb = Bsm + buf * TBUF;
#pragma unroll
        for (int ks2 = 0; ks2 < 16; ks2 += 8) {   // 2 k-steps of 16 halves (8 words)
            uint32_t af[4][4], bf[4][2];
#pragma unroll
            for (int mt = 0; mt < 4; mt++) {
                int r0 = wm * 64 + mt * 16 + g;
                af[mt][0] = Ab[r0 * SST + ks2 + tig];
                af[mt][1] = Ab[(r0 + 8) * SST + ks2 + tig];
                af[mt][2] = Ab[r0 * SST + ks2 + tig + 4];
                af[mt][3] = Ab[(r0 + 8) * SST + ks2 + tig + 4];
            }
#pragma unroll
            for (int nt = 0; nt < 4; nt++) {
                int c0 = wn * 32 + nt * 8 + g;
                bf[nt][0] = Bb[c0 * SST + ks2 + tig];
                bf[nt][1] = Bb[c0 * SST + ks2 + tig + 4];
            }
#pragma unroll
            for (int mt = 0; mt < 4; mt++)
#pragma unroll
                for (int nt = 0; nt < 4; nt++)
                    mma_f16(acc[mt][nt], af[mt][0], af[mt][1], af[mt][2], af[mt][3],
                            bf[nt][0], bf[nt][1]);
        }
        if (more) {
            int nb = buf ^ 1;
            store(Asm + nb * TBUF, an0, an1);
            store(Bsm + nb * TBUF, bn0, bn1);
        }
        __syncthreads();
    }

#pragma unroll
    for (int mt = 0; mt < 4; mt++) {
#pragma unroll
        for (int nt = 0; nt < 4; nt++) {
            int col = wn * 32 + nt * 8 + tig * 2;
            float b0 = bias[col], b1 = bias[col + 1];
#pragma unroll
            for (int h = 0; h < 2; h++) {
                int row = rowBase + wm * 64 + mt * 16 + g + h * 8;
                if (row >= M) continue;
                float v0 = acc[mt][nt][h * 2 + 0] + b0;
                float v1 = acc[mt][nt][h * 2 + 1] + b1;
                if (RES) {
                    float2 rv = *(const float2*)&res[(size_t)row * HID + col];
                    v0 = rv.x + v0 * scale;
                    v1 = rv.y + v1 * scale;
                }
                v0 = fmaxf(v0, 0.f);
                v1 = fmaxf(v1, 0.f);
                float2 o; o.x = v0; o.y = v1;
                *(float2*)&out[(size_t)row * HID + col] = o;
                *(__half2*)&h16out[(size_t)row * HID + col] = __floats2half2_rn(v0, v1);
                if (zs) {
                    float d = dv[row];
                    *(__half2*)&zs[(size_t)row * HID + col] =
                        __floats2half2_rn(v0 * d, v1 * d);
                    *(__half2*)&hqo[(size_t)row * HID + col] =
                        __floats2half2_rn(0.1f * d * v0, 0.1f * d * v1);
                }
            }
        }
    }
}

// ------------------------- fp16 helpers -------------------------
__device__ __forceinline__ void h8_add(uint4 v, float a[8]) {
    const __half2* h = (const __half2*)&v;
#pragma unroll
    for (int j = 0; j < 4; j++) {
        float2 f = __half22float2(h[j]);
        a[2 * j]     += f.x;
        a[2 * j + 1] += f.y;
    }
}
__device__ __forceinline__ uint4 pack8(const float r[8]) {
    uint4 pk;
    __half2* ph = (__half2*)&pk;
    ph[0] = __floats2half2_rn(r[0], r[1]);
    ph[1] = __floats2half2_rn(r[2], r[3]);
    ph[2] = __floats2half2_rn(r[4], r[5]);
    ph[3] = __floats2half2_rn(r[6], r[7]);
    return pk;
}

// ------------------------- fused SAGE gathers (fp16 staging out) -------------------------
__global__ void k_gather_all() {
    int t = blockIdx.x * blockDim.x + threadIdx.x;
    int lane = t & 15, slot = t >> 4;
    if (slot >= 3 * NG + NP) return;
    const __half* xs; const int* off; const int* es;
    __half* dst; int strideH, colH, node;
    const __half* cp = 0; int ccolH = 0;
    if (slot < NG) {
        node = slot; xs = g_h16 + (size_t)(NG + NP) * HID;
        off = g_roff_tg; es = g_rsrc; dst = g_sg16; strideH = 512; colH = 0;
    } else if (slot < 2 * NG) {
        node = slot - NG; xs = g_h16 + (size_t)NG * HID;
        off = g_roff_ct; es = g_rsrc + 2 * EPER; dst = g_sg16; strideH = 512; colH = 128;
    } else if (slot < 3 * NG) {
        node = slot - 2 * NG; xs = g_h16;
        off = g_roff_ii; es = g_rsrc + 3 * EPER; dst = g_sg16; strideH = 512; colH = 256;
        cp = g_h16; ccolH = 384;
    } else {
        node = slot - 3 * NG; xs = g_h16;
        off = g_roff_in; es = g_rsrc + 1 * EPER; dst = g_sp16; strideH = 256; colH = 0;
        cp = g_h16 + (size_t)NG * HID; ccolH = 128;
    }
    const uint4* x4 = (const uint4*)xs;
    int e0 = off[node], e1 = off[node + 1];
    float a[8] = {0.f, 0.f, 0.f, 0.f, 0.f, 0.f, 0.f, 0.f};
    int e = e0;
    for (; e + 2 <= e1; e += 2) {
        uint4 v0 = __ldg(&x4[(size_t)es[e] * 16 + lane]);
        uint4 v1 = __ldg(&x4[(size_t)es[e + 1] * 16 + lane]);
        h8_add(v0, a);
        h8_add(v1, a);
    }
    if (e < e1) {
        uint4 v = __ldg(&x4[(size_t)es[e] * 16 + lane]);
        h8_add(v, a);
    }
    float inv = 1.f / fmaxf((float)(e1 - e0), 1.f);
    float r[8];
#pragma unroll
    for (int j = 0; j < 8; j++) r[j] = a[j] * inv;
    *(uint4*)&dst[(size_t)node * strideH + colH + lane * 8] = pack8(r);
    if (cp)
        *(uint4*)&dst[(size_t)node * strideH + ccolH + lane * 8] =
            ((const uint4*)cp)[(size_t)node * 16 + lane];
}

// ------------------------- APPNP step on scaled state -------------------------
template<bool LAST>
__global__ void k_appnp_s(const uint4* __restrict__ z, uint4* __restrict__ zn,
                          float4* __restrict__ outf) {
    int t = blockIdx.x * blockDim.x + threadIdx.x;
    int lane = t & 15, node = t >> 4;
    if (node >= NT) return;
    int e0 = g_off[node], e1 = g_off[node + 1];
    float a[8] = {0.f, 0.f, 0.f, 0.f, 0.f, 0.f, 0.f, 0.f};
    int e = e0;
    for (; e + 4 <= e1; e += 4) {
        uint4 v0 = __ldg(&z[(size_t)g_csrc[e] * 16 + lane]);
        uint4 v1 = __ldg(&z[(size_t)g_csrc[e + 1] * 16 + lane]);
        uint4 v2 = __ldg(&z[(size_t)g_csrc[e + 2] * 16 + lane]);
        uint4 v3 = __ldg(&z[(size_t)g_csrc[e + 3] * 16 + lane]);
        h8_add(v0, a); h8_add(v1, a); h8_add(v2, a); h8_add(v3, a);
    }
    for (; e < e1; e++) {
        uint4 v = __ldg(&z[(size_t)g_csrc[e] * 16 + lane]);
        h8_add(v, a);
    }
    float d = g_dinv[node];
    if (LAST) {
        float c = 0.9f * d;
        const float4* h0p = (const float4*)g_h0;
        float4 ha = h0p[(size_t)node * 32 + lane * 2];
        float4 hb = h0p[(size_t)node * 32 + lane * 2 + 1];
        outf[(size_t)node * 32 + lane * 2] =
            make_float4(c * a[0] + 0.1f * ha.x, c * a[1] + 0.1f * ha.y,
                        c * a[2] + 0.1f * ha.z, c * a[3] + 0.1f * ha.w);
        outf[(size_t)node * 32 + lane * 2 + 1] =
            make_float4(c * a[4] + 0.1f * hb.x, c * a[5] + 0.1f * hb.y,
                        c * a[6] + 0.1f * hb.z, c * a[7] + 0.1f * hb.w);
    } else {
        float c1 = 0.9f * d * d;
        uint4 hqv = ((const uint4*)g_hq)[(size_t)node * 16 + lane];
        const __half2* hh = (const __half2*)&hqv;
        float r[8];
#pragma unroll
        for (int j = 0; j < 4; j++) {
            float2 f = __half22float2(hh[j]);
            r[2 * j]     = c1 * a[2 * j]     + f.x;
            r[2 * j + 1] = c1 * a[2 * j + 1] + f.y;
        }
        zn[(size_t)node * 16 + lane] = pack8(r);
    }
}

// ------------------------- host orchestration -------------------------
extern "C" void kernel_launch(void* const* d_in, const int* in_sizes, int n_in,
                              void* d_out, int out_size) {
    const float* x_gene  = (const float*)d_in[0];
    const float* x_path  = (const float*)d_in[1];
    const float* x_vacc  = (const float*)d_in[2];
    const float* win_g   = (const float*)d_in[3];
    const float* bin_g   = (const float*)d_in[4];
    const float* win_p   = (const float*)d_in[5];
    const float* bin_p   = (const float*)d_in[6];
    const float* win_v   = (const float*)d_in[7];
    const float* bin_v   = (const float*)d_in[8];
    const float* wsl     = (const float*)d_in[9];
    const float* bsl     = (const float*)d_in[10];
    const float* wsr     = (const float*)d_in[11];
    const int*   ei_t    = (const int*)d_in[12];
    const int*   ei_in   = (const int*)d_in[13];
    const int*   ei_ct   = (const int*)d_in[14];
    const int*   ei_ii   = (const int*)d_in[15];
    float* out = (float*)d_out;

    float *h0, *bg, *dinv;
    __half *h16, *z16a, *z16b, *hq, *sg16, *sp16, *wtin16, *wtg16, *wtp16;
    int *cnts, *curz;
    cudaGetSymbolAddress((void**)&h0, g_h0);
    cudaGetSymbolAddress((void**)&h16, g_h16);
    cudaGetSymbolAddress((void**)&z16a, g_z16a);
    cudaGetSymbolAddress((void**)&z16b, g_z16b);
    cudaGetSymbolAddress((void**)&hq, g_hq);
    cudaGetSymbolAddress((void**)&sg16, g_sg16);
    cudaGetSymbolAddress((void**)&sp16, g_sp16);
    cudaGetSymbolAddress((void**)&wtin16, g_wtin16);
    cudaGetSymbolAddress((void**)&wtg16, g_wtg16);
    cudaGetSymbolAddress((void**)&wtp16, g_wtp16);
    cudaGetSymbolAddress((void**)&bg,  g_bg);
    cudaGetSymbolAddress((void**)&dinv, g_dinv);
    cudaGetSymbolAddress((void**)&cnts, g_cnts);
    cudaGetSymbolAddress((void**)&curz, g_curz);

    float* hg = h0;
    float* hp = h0 + (size_t)NG * HID;
    float* hv = h0 + (size_t)(NG + NP) * HID;
    __half* hg16 = h16;
    __half* hp16 = h16 + (size_t)NG * HID;
    __half* hv16 = h16 + (size_t)(NG + NP) * HID;

    const int TB = 256;
    static bool attr_set = false;
    if (!attr_set) {
        cudaFuncSetAttribute(k_gemm16<false, false>, cudaFuncAttributeMaxDynamicSharedMemorySize, GSMEM_BYTES);
        cudaFuncSetAttribute(k_gemm16<true,  true>,  cudaFuncAttributeMaxDynamicSharedMemorySize, GSMEM_BYTES);
        attr_set = true;
    }

    // ---------- CSR setup (dinv ready before epilogue prescaling) ----------
    cudaMemsetAsync(cnts, 0, CNTS_SZ * sizeof(int));
    k_hist4<<<CDIV(4 * EPER, TB), TB>>>(ei_t, ei_in, ei_ct, ei_ii);
    k_deg<<<CDIV(NT, TB), TB>>>();
    k_scan5<<<5, 1024>>>();
    cudaMemsetAsync(curz, 0, CURZ_SZ * sizeof(int));
    k_scatter_all<<<CDIV(4 * EPER + NT, TB), TB>>>(ei_t, ei_in, ei_ct, ei_ii);

    // ---------- weight prep (fp16, [n][k] layout) + layer-0 builds ----------
    const int PREP_N = (256 + 128 + 64) * 128 + 512 * 128 + 256 * 128;
    k_prep16<<<CDIV(PREP_N, TB), TB>>>(win_g, win_p, win_v, wsl, wsr, bsl, 0, 1);

    // ---------- input projections ----------
    k_gemm16<false, false><<<CDIV(NV, 128), 256, GSMEM_BYTES>>>(
        x_vacc, wtin16 + (256 + 128) * 128, bin_v, (const float*)0, hv, hv16,
        z16a + (size_t)(NG + NP) * HID, hq + (size_t)(NG + NP) * HID,
        dinv + (NG + NP), NV, 64, 1.f);
    k_gemm16<false, false><<<CDIV(NP, 128), 256, GSMEM_BYTES>>>(
        x_path, wtin16 + 256 * 128, bin_p, (const float*)0, hp, hp16,
        (__half*)0, (__half*)0, (const float*)0, NP, 128, 1.f);
    k_gemm16<false, false><<<CDIV(NG, 128), 256, GSMEM_BYTES>>>(
        x_gene, wtin16, bin_g, (const float*)0, hg, hg16,
        (__half*)0, (__half*)0, (const float*)0, NG, 256, 1.f);

    // ---------- SAGE layer 0 ----------
    const int GALL = CDIV((3 * NG + NP) * 16, TB);
    k_gather_all<<<GALL, TB>>>();
    k_gemm16<true, true><<<CDIV(NG, 128), 256, GSMEM_BYTES>>>(
        sg16, wtg16, bg, hg, hg, hg16, (__half*)0, (__half*)0, (const float*)0, NG, 512, 1.f / 3.f);
    k_gemm16<true, true><<<CDIV(NP, 128), 256, GSMEM_BYTES>>>(
        sp16, wtp16, bsl + 1 * 128, hp, hp, hp16, (__half*)0, (__half*)0, (const float*)0, NP, 256, 1.f);
    k_prep16<<<CDIV(512 * 128 + 256 * 128, TB), TB>>>(win_g, win_p, win_v, wsl, wsr, bsl, 1, 0);

    // ---------- SAGE layer 1 (emit scaled APPNP state in epilogue) ----------
    k_gather_all<<<GALL, TB>>>();
    k_gemm16<true, true><<<CDIV(NG, 128), 256, GSMEM_BYTES>>>(
        sg16, wtg16, bg, hg, hg, hg16, z16a, hq, dinv, NG, 512, 1.f / 3.f);
    k_gemm16<true, true><<<CDIV(NP, 128), 256, GSMEM_BYTES>>>(
        sp16, wtp16, bsl + (4 + 1) * 128, hp, hp, hp16,
        z16a + (size_t)NG * HID, hq + (size_t)NG * HID, dinv + NG, NP, 256, 1.f);

    // ---------- 8 APPNP iterations on scaled state; last writes fp32 d_out ----------
    const int AB = CDIV(NT * 16, TB);
    __half* bufs[2] = {z16a, z16b};
    for (int k = 0; k < 7; k++) {
        const __half* zin = bufs[k & 1];
        __half* zout = bufs[(k & 1) ^ 1];
        k_appnp_s<false><<<AB, TB>>>((const uint4*)zin, (uint4*)zout, (float4*)0);
    }
    k_appnp_s<true><<<AB, TB>>>((const uint4*)bufs[1], (uint4*)0, (float4*)out);
}

// round 9
// speedup vs baseline: 4.1308x; 1.0769x over previous
#include <cuda_runtime.h>
#include <cuda_fp16.h>
#include <cstdint>

#define NG 50000
#define NP 20000
#define NV 10000
#define NT 80000
#define HID 128
#define EPER 250000
#define ETOT (4*EPER + NT)
#define CDIV(a,b) (((a)+(b)-1)/(b))

#define OFF_TG 0
#define OFF_IN (NG)
#define OFF_CT (NG+NP)
#define OFF_II (2*NG+NP)
#define OFF_ALL (3*NG+NP)
#define CNTS_SZ (3*NG+NP)
#define CURZ_SZ (3*NG+NP+NT)

// ------------------------- device scratch -------------------------
__device__ float g_h0[NT*HID];                       // fp32 node features (hg|hp|hv)
__device__ __align__(16) __half g_h16[NT*HID];       // fp16 mirror (SAGE gathers)
__device__ __align__(16) __half g_z16a[NT*HID];      // APPNP scaled state ping
__device__ __align__(16) __half g_z16b[NT*HID];      // pong
__device__ __align__(16) __half g_hq[NT*HID];        // 0.1*dinv*h0 (fp16)
__device__ __align__(16) __half g_sg16[NG*512];      // gene staging (fp16)
__device__ __align__(16) __half g_sp16[NP*256];      // pathway staging (fp16)
__device__ __align__(16) __half g_wtin16[(256+128+64)*HID]; // input-proj W, [n][k] fp16
__device__ __align__(16) __half g_wtg16[512*HID];    // gene concat W, [n=128][k=512] fp16
__device__ __align__(16) __half g_wtp16[256*HID];    // pathway concat W, [n=128][k=256] fp16
__device__ float g_bg[HID];
__device__ int   g_degi[NT];
__device__ float g_dinv[NT];
__device__ int   g_off[NT+1];
__device__ int   g_cnts[CNTS_SZ];
__device__ int   g_curz[CURZ_SZ];
__device__ int   g_csrc[ETOT];
__device__ int   g_roff_tg[NG+1];
__device__ int   g_roff_in[NP+1];
__device__ int   g_roff_ct[NG+1];
__device__ int   g_roff_ii[NG+1];
__device__ int   g_rsrc[4*EPER];

__device__ __forceinline__ uint32_t h2u(__half2 h) {
    uint32_t u;
    memcpy(&u, &h, 4);
    return u;
}

// ------------------------- setup kernels -------------------------
__global__ void k_hist4(const int* __restrict__ e0, const int* __restrict__ e1,
                        const int* __restrict__ e2, const int* __restrict__ e3) {
    int t = blockIdx.x * blockDim.x + threadIdx.x;
    if (t >= 4 * EPER) return;
    int r = t / EPER, e = t - r * EPER;
    const int* ei = (r == 0) ? e0 : (r == 1) ? e1 : (r == 2) ? e2 : e3;
    int base = (r == 0) ? OFF_TG : (r == 1) ? OFF_IN : (r == 2) ? OFF_CT : OFF_II;
    atomicAdd(&g_cnts[base + ei[EPER + e]], 1);
}

__global__ void k_deg() {
    int i = blockIdx.x * blockDim.x + threadIdx.x;
    if (i >= NT) return;
    int d = 1;
    if (i < NG) d += g_cnts[OFF_TG + i] + g_cnts[OFF_CT + i] + g_cnts[OFF_II + i];
    else if (i < NG + NP) d += g_cnts[OFF_IN + (i - NG)];
    g_degi[i] = d;
    g_dinv[i] = rsqrtf((float)d);
}

__global__ void k_scan5() {
    __shared__ int part[1024];
    const int* cnt; int* off; int n;
    switch (blockIdx.x) {
        case 0: cnt = g_cnts + OFF_TG; off = g_roff_tg; n = NG; break;
        case 1: cnt = g_cnts + OFF_IN; off = g_roff_in; n = NP; break;
        case 2: cnt = g_cnts + OFF_CT; off = g_roff_ct; n = NG; break;
        case 3: cnt = g_cnts + OFF_II; off = g_roff_ii; n = NG; break;
        default: cnt = g_degi; off = g_off; n = NT; break;
    }
    int t = threadIdx.x;
    int chunk = (n + 1023) / 1024;
    int lo = t * chunk, hi = min(lo + chunk, n);
    int s = 0;
    for (int i = lo; i < hi; i++) s += cnt[i];
    part[t] = s;
    __syncthreads();
    for (int o = 1; o < 1024; o <<= 1) {
        int x = (t >= o) ? part[t - o] : 0;
        __syncthreads();
        part[t] += x;
        __syncthreads();
    }
    int run = part[t] - s;
    for (int i = lo; i < hi; i++) { off[i] = run; run += cnt[i]; }
    if (t == 1023) off[n] = part[1023];
}

__global__ void k_scatter_all(const int* __restrict__ e0, const int* __restrict__ e1,
                              const int* __restrict__ e2, const int* __restrict__ e3) {
    int t = blockIdx.x * blockDim.x + threadIdx.x;
    if (t < 4 * EPER) {
        int r = t / EPER, e = t - r * EPER;
        const int* ei; const int* roff; int cbase, osrc, odst;
        if (r == 0)      { ei = e0; roff = g_roff_tg; cbase = OFF_TG; osrc = NG + NP; odst = 0; }
        else if (r == 1) { ei = e1; roff = g_roff_in; cbase = OFF_IN; osrc = 0;       odst = NG; }
        else if (r == 2) { ei = e2; roff = g_roff_ct; cbase = OFF_CT; osrc = NG;      odst = 0; }
        else             { ei = e3; roff = g_roff_ii; cbase = OFF_II; osrc = 0;       odst = 0; }
        int s = ei[e], d = ei[EPER + e];
        int p = roff[d] + atomicAdd(&g_curz[cbase + d], 1);
        g_rsrc[r * EPER + p] = s;
        int gd = d + odst;
        int p2 = g_off[gd] + atomicAdd(&g_curz[OFF_ALL + gd], 1);
        g_csrc[p2] = s + osrc;
    } else if (t < 4 * EPER + NT) {
        int i = t - 4 * EPER;
        int p = g_off[i] + atomicAdd(&g_curz[OFF_ALL + i], 1);
        g_csrc[p] = i;
    }
}

// fused weight prep: input-proj fp16 copies + layer-l SAGE weight builds (all [n][k] layout)
__global__ void k_prep16(const float* __restrict__ wg, const float* __restrict__ wp,
                         const float* __restrict__ wv, const float* __restrict__ wsl,
                         const float* __restrict__ wsr, const float* __restrict__ bsl,
                         int l, int do_in) {
    int idx = blockIdx.x * blockDim.x + threadIdx.x;
    const int TIN = (256 + 128 + 64) * 128;           // flat input-proj copies
    const int WG  = 512 * 128;
    int base = do_in ? TIN : 0;
    if (do_in && idx < TIN) {
        float v;
        if (idx < 256 * 128) v = wg[idx];
        else if (idx < (256 + 128) * 128) v = wp[idx - 256 * 128];
        else v = wv[idx - (256 + 128) * 128];
        g_wtin16[idx] = __float2half(v);
        return;
    }
    int i = idx - base;
    if (i < 0) return;
    if (i < WG) {
        // wtg16[n][k], k blocks: wl0 | wl2 | wl3 | wr0+wr2+wr3
        int n = i >> 9, k = i & 511;
        int b = k >> 7, kk = k & 127;
        float v;
        if (b == 0)      v = wsl[((l * 4 + 0) * 128 + n) * 128 + kk];
        else if (b == 1) v = wsl[((l * 4 + 2) * 128 + n) * 128 + kk];
        else if (b == 2) v = wsl[((l * 4 + 3) * 128 + n) * 128 + kk];
        else             v = wsr[((l * 4 + 0) * 128 + n) * 128 + kk]
                           + wsr[((l * 4 + 2) * 128 + n) * 128 + kk]
                           + wsr[((l * 4 + 3) * 128 + n) * 128 + kk];
        g_wtg16[i] = __float2half(v);
        if (i < 128)
            g_bg[i] = bsl[(l * 4 + 0) * 128 + i] + bsl[(l * 4 + 2) * 128 + i]
                    + bsl[(l * 4 + 3) * 128 + i];
    } else if (i < WG + 256 * 128) {
        int j = i - WG;
        int n = j >> 8, k = j & 255;
        int b = k >> 7, kk = k & 127;
        float v = (b == 0) ? wsl[((l * 4 + 1) * 128 + n) * 128 + kk]
                           : wsr[((l * 4 + 1) * 128 + n) * 128 + kk];
        g_wtp16[j] = __float2half(v);
    }
}

// ------------------------- FP16 tensor-core GEMM (KTILE=32) -------------------------
__device__ __forceinline__ void mma_f16(float c[4], uint32_t a0, uint32_t a1,
                                        uint32_t a2, uint32_t a3,
                                        uint32_t b0, uint32_t b1) {
    asm volatile(
        "mma.sync.aligned.m16n8k16.row.col.f32.f16.f16.f32 "
        "{%0,%1,%2,%3}, {%4,%5,%6,%7}, {%8,%9}, {%0,%1,%2,%3};"
        : "+f"(c[0]), "+f"(c[1]), "+f"(c[2]), "+f"(c[3])
        : "r"(a0), "r"(a1), "r"(a2), "r"(a3), "r"(b0), "r"(b1));
}

#define SST 20               // smem row stride in words (16 data + 4 pad)
#define TBUF (128*SST)       // one A or B buffer (words)
#define GSMEM_BYTES (4*TBUF*4)

// A: [M,K]; AH: A is fp16 (else fp32, converted on load). B(W16): [128 n][K k] fp16.
// out = relu((A@W^T + bias)*scale + res); also h16out; optional zs=dinv*v, hq=0.1*dinv*v.
template<bool RES, bool AH>
__global__ __launch_bounds__(256)
void k_gemm16(const void* __restrict__ Araw, const __half* __restrict__ W16,
              const float* __restrict__ bias, const float* __restrict__ res,
              float* __restrict__ out, __half* __restrict__ h16out,
              __half* __restrict__ zs, __half* __restrict__ hqo,
              const float* __restrict__ dv,
              int M, int K, float scale)
{
    extern __shared__ uint32_t sm[];
    uint32_t* Asm = sm;              // [2][128][SST]
    uint32_t* Bsm = sm + 2 * TBUF;   // [2][128][SST]

    int tid  = threadIdx.x;
    int lane = tid & 31;
    int wid  = tid >> 5;
    int wm = wid >> 2;
    int wn = wid & 3;
    int g   = lane >> 2;
    int tig = lane & 3;

    int rowBase = blockIdx.x * 128;
    int r_ld  = tid >> 1;            // 0..127 (row for both A and B loads)
    int hsel  = (tid & 1);           // which 16-half chunk

    float acc[4][4][4];
#pragma unroll
    for (int mt = 0; mt < 4; mt++)
#pragma unroll
        for (int nt = 0; nt < 4; nt++)
#pragma unroll
            for (int r = 0; r < 4; r++) acc[mt][nt][r] = 0.f;

    int ntk = K >> 5;
    int gr = rowBase + r_ld;
    const __half* Ah = (const __half*)Araw;
    const float*  Af = (const float*)Araw;

    auto loadA = [&](int k0, uint4& u0, uint4& u1) {
        if (AH) {
            if (gr < M) {
                const uint4* p = (const uint4*)&Ah[(size_t)gr * K + k0 + hsel * 16];
                u0 = p[0]; u1 = p[1];
            } else { u0 = make_uint4(0,0,0,0); u1 = make_uint4(0,0,0,0); }
        } else {
            if (gr < M) {
                const float4* p = (const float4*)&Af[(size_t)gr * K + k0 + hsel * 16];
                float4 f0 = p[0], f1 = p[1], f2 = p[2], f3 = p[3];
                uint32_t* w0 = (uint32_t*)&u0;
                uint32_t* w1 = (uint32_t*)&u1;
                w0[0] = h2u(__floats2half2_rn(f0.x, f0.y));
                w0[1] = h2u(__floats2half2_rn(f0.z, f0.w));
                w0[2] = h2u(__floats2half2_rn(f1.x, f1.y));
                w0[3] = h2u(__floats2half2_rn(f1.z, f1.w));
                w1[0] = h2u(__floats2half2_rn(f2.x, f2.y));
                w1[1] = h2u(__floats2half2_rn(f2.z, f2.w));
                w1[2] = h2u(__floats2half2_rn(f3.x, f3.y));
                w1[3] = h2u(__floats2half2_rn(f3.z, f3.w));
            } else { u0 = make_uint4(0,0,0,0); u1 = make_uint4(0,0,0,0); }
        }
    };
    auto loadB = [&](int k0, uint4& u0, uint4& u1) {
        const uint4* p = (const uint4*)&W16[(size_t)r_ld * K + k0 + hsel * 16];
        u0 = p[0]; u1 = p[1];
    };
    auto store = [&](uint32_t* buf, uint4 u0, uint4 u1) {
        int base = r_ld * SST + hsel * 8;
        *(uint4*)&buf[base] = u0;
        *(uint4*)&buf[base + 4] = u1;
    };

    {   // preload tile 0
        uint4 a0, a1, b0, b1;
        loadA(0, a0, a1);
        loadB(0, b0, b1);
        store(Asm, a0, a1);
        store(Bsm, b0, b1);
    }
    __syncthreads();

    for (int t = 0; t < ntk; t++) {
        int buf = t & 1;
        bool more = (t + 1 < ntk);
        uint4 an0, an1, bn0, bn1;
        if (more) {
            int k0 = (t + 1) << 5;
            loadA(k0, an0, an1);
            loadB(k0, bn0, bn1);
        }
        const uint32_t* Ab = Asm + buf * TBUF;
        const uint32_t* Bb = Bsm + buf * TBUF;
#pragma unroll
        for (int ks2 = 0; ks2 < 16; ks2 += 8) {   // 2 k-steps of 16 halves (8 words)
            uint32_t af[4][4], bf[4][2];
#pragma unroll
            for (int mt = 0; mt < 4; mt++) {
                int r0 = wm * 64 + mt * 16 + g;
                af[mt][0] = Ab[r0 * SST + ks2 + tig];
                af[mt][1] = Ab[(r0 + 8) * SST + ks2 + tig];
                af[mt][2] = Ab[r0 * SST + ks2 + tig + 4];
                af[mt][3] = Ab[(r0 + 8) * SST + ks2 + tig + 4];
            }
#pragma unroll
            for (int nt = 0; nt < 4; nt++) {
                int c0 = wn * 32 + nt * 8 + g;
                bf[nt][0] = Bb[c0 * SST + ks2 + tig];
                bf[nt][1] = Bb[c0 * SST + ks2 + tig + 4];
            }
#pragma unroll
            for (int mt = 0; mt < 4; mt++)
#pragma unroll
                for (int nt = 0; nt < 4; nt++)
                    mma_f16(acc[mt][nt], af[mt][0], af[mt][1], af[mt][2], af[mt][3],
                            bf[nt][0], bf[nt][1]);
        }
        if (more) {
            int nb = buf ^ 1;
            store(Asm + nb * TBUF, an0, an1);
            store(Bsm + nb * TBUF, bn0, bn1);
        }
        __syncthreads();
    }

#pragma unroll
    for (int mt = 0; mt < 4; mt++) {
#pragma unroll
        for (int nt = 0; nt < 4; nt++) {
            int col = wn * 32 + nt * 8 + tig * 2;
            float b0 = bias[col], b1 = bias[col + 1];
#pragma unroll
            for (int h = 0; h < 2; h++) {
                int row = rowBase + wm * 64 + mt * 16 + g + h * 8;
                if (row >= M) continue;
                float v0 = acc[mt][nt][h * 2 + 0] + b0;
                float v1 = acc[mt][nt][h * 2 + 1] + b1;
                if (RES) {
                    float2 rv = *(const float2*)&res[(size_t)row * HID + col];
                    v0 = rv.x + v0 * scale;
                    v1 = rv.y + v1 * scale;
                }
                v0 = fmaxf(v0, 0.f);
                v1 = fmaxf(v1, 0.f);
                float2 o; o.x = v0; o.y = v1;
                *(float2*)&out[(size_t)row * HID + col] = o;
                *(__half2*)&h16out[(size_t)row * HID + col] = __floats2half2_rn(v0, v1);
                if (zs) {
                    float d = dv[row];
                    *(__half2*)&zs[(size_t)row * HID + col] =
                        __floats2half2_rn(v0 * d, v1 * d);
                    *(__half2*)&hqo[(size_t)row * HID + col] =
                        __floats2half2_rn(0.1f * d * v0, 0.1f * d * v1);
                }
            }
        }
    }
}

// ------------------------- fp16 helpers -------------------------
__device__ __forceinline__ void h8_add(uint4 v, float a[8]) {
    const __half2* h = (const __half2*)&v;
#pragma unroll
    for (int j = 0; j < 4; j++) {
        float2 f = __half22float2(h[j]);
        a[2 * j]     += f.x;
        a[2 * j + 1] += f.y;
    }
}
__device__ __forceinline__ uint4 pack8(const float r[8]) {
    uint4 pk;
    __half2* ph = (__half2*)&pk;
    ph[0] = __floats2half2_rn(r[0], r[1]);
    ph[1] = __floats2half2_rn(r[2], r[3]);
    ph[2] = __floats2half2_rn(r[4], r[5]);
    ph[3] = __floats2half2_rn(r[6], r[7]);
    return pk;
}

// ------------------------- fused SAGE gathers (fp16 staging out) -------------------------
__global__ void k_gather_all() {
    int t = blockIdx.x * blockDim.x + threadIdx.x;
    int lane = t & 15, slot = t >> 4;
    if (slot >= 3 * NG + NP) return;
    const __half* xs; const int* off; const int* es;
    __half* dst; int strideH, colH, node;
    const __half* cp = 0; int ccolH = 0;
    if (slot < NG) {
        node = slot; xs = g_h16 + (size_t)(NG + NP) * HID;
        off = g_roff_tg; es = g_rsrc; dst = g_sg16; strideH = 512; colH = 0;
    } else if (slot < 2 * NG) {
        node = slot - NG; xs = g_h16 + (size_t)NG * HID;
        off = g_roff_ct; es = g_rsrc + 2 * EPER; dst = g_sg16; strideH = 512; colH = 128;
    } else if (slot < 3 * NG) {
        node = slot - 2 * NG; xs = g_h16;
        off = g_roff_ii; es = g_rsrc + 3 * EPER; dst = g_sg16; strideH = 512; colH = 256;
        cp = g_h16; ccolH = 384;
    } else {
        node = slot - 3 * NG; xs = g_h16;
        off = g_roff_in; es = g_rsrc + 1 * EPER; dst = g_sp16; strideH = 256; colH = 0;
        cp = g_h16 + (size_t)NG * HID; ccolH = 128;
    }
    const uint4* x4 = (const uint4*)xs;
    int e0 = off[node], e1 = off[node + 1];
    float a[8] = {0.f, 0.f, 0.f, 0.f, 0.f, 0.f, 0.f, 0.f};
    int e = e0;
    for (; e + 2 <= e1; e += 2) {
        uint4 v0 = __ldg(&x4[(size_t)es[e] * 16 + lane]);
        uint4 v1 = __ldg(&x4[(size_t)es[e + 1] * 16 + lane]);
        h8_add(v0, a);
        h8_add(v1, a);
    }
    if (e < e1) {
        uint4 v = __ldg(&x4[(size_t)es[e] * 16 + lane]);
        h8_add(v, a);
    }
    float inv = 1.f / fmaxf((float)(e1 - e0), 1.f);
    float r[8];
#pragma unroll
    for (int j = 0; j < 8; j++) r[j] = a[j] * inv;
    *(uint4*)&dst[(size_t)node * strideH + colH + lane * 8] = pack8(r);
    if (cp)
        *(uint4*)&dst[(size_t)node * strideH + ccolH + lane * 8] =
            ((const uint4*)cp)[(size_t)node * 16 + lane];
}

// ------------------------- APPNP step on scaled state -------------------------
template<bool LAST>
__global__ void k_appnp_s(const uint4* __restrict__ z, uint4* __restrict__ zn,
                          float4* __restrict__ outf) {
    int t = blockIdx.x * blockDim.x + threadIdx.x;
    int lane = t & 15, node = t >> 4;
    if (node >= NT) return;
    int e0 = g_off[node], e1 = g_off[node + 1];
    float a[8] = {0.f, 0.f, 0.f, 0.f, 0.f, 0.f, 0.f, 0.f};
    int e = e0;
    for (; e + 4 <= e1; e += 4) {
        uint4 v0 = __ldg(&z[(size_t)g_csrc[e] * 16 + lane]);
        uint4 v1 = __ldg(&z[(size_t)g_csrc[e + 1] * 16 + lane]);
        uint4 v2 = __ldg(&z[(size_t)g_csrc[e + 2] * 16 + lane]);
        uint4 v3 = __ldg(&z[(size_t)g_csrc[e + 3] * 16 + lane]);
        h8_add(v0, a); h8_add(v1, a); h8_add(v2, a); h8_add(v3, a);
    }
    for (; e < e1; e++) {
        uint4 v = __ldg(&z[(size_t)g_csrc[e] * 16 + lane]);
        h8_add(v, a);
    }
    float d = g_dinv[node];
    if (LAST) {
        float c = 0.9f * d;
        const float4* h0p = (const float4*)g_h0;
        float4 ha = h0p[(size_t)node * 32 + lane * 2];
        float4 hb = h0p[(size_t)node * 32 + lane * 2 + 1];
        outf[(size_t)node * 32 + lane * 2] =
            make_float4(c * a[0] + 0.1f * ha.x, c * a[1] + 0.1f * ha.y,
                        c * a[2] + 0.1f * ha.z, c * a[3] + 0.1f * ha.w);
        outf[(size_t)node * 32 + lane * 2 + 1] =
            make_float4(c * a[4] + 0.1f * hb.x, c * a[5] + 0.1f * hb.y,
                        c * a[6] + 0.1f * hb.z, c * a[7] + 0.1f * hb.w);
    } else {
        float c1 = 0.9f * d * d;
        uint4 hqv = ((const uint4*)g_hq)[(size_t)node * 16 + lane];
        const __half2* hh = (const __half2*)&hqv;
        float r[8];
#pragma unroll
        for (int j = 0; j < 4; j++) {
            float2 f = __half22float2(hh[j]);
            r[2 * j]     = c1 * a[2 * j]     + f.x;
            r[2 * j + 1] = c1 * a[2 * j + 1] + f.y;
        }
        zn[(size_t)node * 16 + lane] = pack8(r);
    }
}

// ------------------------- host orchestration -------------------------
extern "C" void kernel_launch(void* const* d_in, const int* in_sizes, int n_in,
                              void* d_out, int out_size) {
    const float* x_gene  = (const float*)d_in[0];
    const float* x_path  = (const float*)d_in[1];
    const float* x_vacc  = (const float*)d_in[2];
    const float* win_g   = (const float*)d_in[3];
    const float* bin_g   = (const float*)d_in[4];
    const float* win_p   = (const float*)d_in[5];
    const float* bin_p   = (const float*)d_in[6];
    const float* win_v   = (const float*)d_in[7];
    const float* bin_v   = (const float*)d_in[8];
    const float* wsl     = (const float*)d_in[9];
    const float* bsl     = (const float*)d_in[10];
    const float* wsr     = (const float*)d_in[11];
    const int*   ei_t    = (const int*)d_in[12];
    const int*   ei_in   = (const int*)d_in[13];
    const int*   ei_ct   = (const int*)d_in[14];
    const int*   ei_ii   = (const int*)d_in[15];
    float* out = (float*)d_out;

    float *h0, *bg, *dinv;
    __half *h16, *z16a, *z16b, *hq, *sg16, *sp16, *wtin16, *wtg16, *wtp16;
    int *cnts, *curz;
    cudaGetSymbolAddress((void**)&h0, g_h0);
    cudaGetSymbolAddress((void**)&h16, g_h16);
    cudaGetSymbolAddress((void**)&z16a, g_z16a);
    cudaGetSymbolAddress((void**)&z16b, g_z16b);
    cudaGetSymbolAddress((void**)&hq, g_hq);
    cudaGetSymbolAddress((void**)&sg16, g_sg16);
    cudaGetSymbolAddress((void**)&sp16, g_sp16);
    cudaGetSymbolAddress((void**)&wtin16, g_wtin16);
    cudaGetSymbolAddress((void**)&wtg16, g_wtg16);
    cudaGetSymbolAddress((void**)&wtp16, g_wtp16);
    cudaGetSymbolAddress((void**)&bg,  g_bg);
    cudaGetSymbolAddress((void**)&dinv, g_dinv);
    cudaGetSymbolAddress((void**)&cnts, g_cnts);
    cudaGetSymbolAddress((void**)&curz, g_curz);

    float* hg = h0;
    float* hp = h0 + (size_t)NG * HID;
    float* hv = h0 + (size_t)(NG + NP) * HID;
    __half* hg16 = h16;
    __half* hp16 = h16 + (size_t)NG * HID;
    __half* hv16 = h16 + (size_t)(NG + NP) * HID;

    const int TB = 256;
    static bool inited = false;
    static cudaStream_t ss;                   // side stream (non-blocking)
    static cudaEvent_t evFork, evSetup, evG0, evP1;
    if (!inited) {
        cudaFuncSetAttribute(k_gemm16<false, false>, cudaFuncAttributeMaxDynamicSharedMemorySize, GSMEM_BYTES);
        cudaFuncSetAttribute(k_gemm16<true,  true>,  cudaFuncAttributeMaxDynamicSharedMemorySize, GSMEM_BYTES);
        cudaStreamCreateWithFlags(&ss, cudaStreamNonBlocking);
        cudaEventCreateWithFlags(&evFork,  cudaEventDisableTiming);
        cudaEventCreateWithFlags(&evSetup, cudaEventDisableTiming);
        cudaEventCreateWithFlags(&evG0,    cudaEventDisableTiming);
        cudaEventCreateWithFlags(&evP1,    cudaEventDisableTiming);
        inited = true;
    }

    // ---------- fork: CSR setup on side stream ----------
    cudaEventRecord(evFork, 0);
    cudaStreamWaitEvent(ss, evFork, 0);
    cudaMemsetAsync(cnts, 0, CNTS_SZ * sizeof(int), ss);
    cudaMemsetAsync(curz, 0, CURZ_SZ * sizeof(int), ss);
    k_hist4<<<CDIV(4 * EPER, TB), TB, 0, ss>>>(ei_t, ei_in, ei_ct, ei_ii);
    k_deg<<<CDIV(NT, TB), TB, 0, ss>>>();
    k_scan5<<<5, 1024, 0, ss>>>();
    k_scatter_all<<<CDIV(4 * EPER + NT, TB), TB, 0, ss>>>(ei_t, ei_in, ei_ct, ei_ii);
    cudaEventRecord(evSetup, ss);

    // ---------- main: weight prep + big projections (independent of setup) ----------
    const int PREP_N = (256 + 128 + 64) * 128 + 512 * 128 + 256 * 128;
    k_prep16<<<CDIV(PREP_N, TB), TB>>>(win_g, win_p, win_v, wsl, wsr, bsl, 0, 1);
    k_gemm16<false, false><<<CDIV(NP, 128), 256, GSMEM_BYTES>>>(
        x_path, wtin16 + 256 * 128, bin_p, (const float*)0, hp, hp16,
        (__half*)0, (__half*)0, (const float*)0, NP, 128, 1.f);
    k_gemm16<false, false><<<CDIV(NG, 128), 256, GSMEM_BYTES>>>(
        x_gene, wtin16, bin_g, (const float*)0, hg, hg16,
        (__half*)0, (__half*)0, (const float*)0, NG, 256, 1.f);

    // ---------- join: vaccine projection needs dinv (z-state emission) ----------
    cudaStreamWaitEvent(0, evSetup, 0);
    k_gemm16<false, false><<<CDIV(NV, 128), 256, GSMEM_BYTES>>>(
        x_vacc, wtin16 + (256 + 128) * 128, bin_v, (const float*)0, hv, hv16,
        z16a + (size_t)(NG + NP) * HID, hq + (size_t)(NG + NP) * HID,
        dinv + (NG + NP), NV, 64, 1.f);

    // ---------- SAGE layer 0 ----------
    const int GALL = CDIV((3 * NG + NP) * 16, TB);
    k_gather_all<<<GALL, TB>>>();
    k_gemm16<true, true><<<CDIV(NG, 128), 256, GSMEM_BYTES>>>(
        sg16, wtg16, bg, hg, hg, hg16, (__half*)0, (__half*)0, (const float*)0, NG, 512, 1.f / 3.f);
    k_gemm16<true, true><<<CDIV(NP, 128), 256, GSMEM_BYTES>>>(
        sp16, wtp16, bsl + 1 * 128, hp, hp, hp16, (__half*)0, (__half*)0, (const float*)0, NP, 256, 1.f);

    // layer-1 weight build on side stream, concurrent with layer-1 gather
    cudaEventRecord(evG0, 0);
    cudaStreamWaitEvent(ss, evG0, 0);
    k_prep16<<<CDIV(512 * 128 + 256 * 128, TB), TB, 0, ss>>>(win_g, win_p, win_v, wsl, wsr, bsl, 1, 0);
    cudaEventRecord(evP1, ss);

    // ---------- SAGE layer 1 (emit scaled APPNP state in epilogue) ----------
    k_gather_all<<<GALL, TB>>>();
    cudaStreamWaitEvent(0, evP1, 0);
    k_gemm16<true, true><<<CDIV(NG, 128), 256, GSMEM_BYTES>>>(
        sg16, wtg16, bg, hg, hg, hg16, z16a, hq, dinv, NG, 512, 1.f / 3.f);
    k_gemm16<true, true><<<CDIV(NP, 128), 256, GSMEM_BYTES>>>(
        sp16, wtp16, bsl + (4 + 1) * 128, hp, hp, hp16,
        z16a + (size_t)NG * HID, hq + (size_t)NG * HID, dinv + NG, NP, 256, 1.f);

    // ---------- 8 APPNP iterations on scaled state; last writes fp32 d_out ----------
    const int AB = CDIV(NT * 16, TB);
    __half* bufs[2] = {z16a, z16b};
    for (int k = 0; k < 7; k++) {
        const __half* zin = bufs[k & 1];
        __half* zout = bufs[(k & 1) ^ 1];
        k_appnp_s<false><<<AB, TB>>>((const uint4*)zin, (uint4*)zout, (float4*)0);
    }
    k_appnp_s<true><<<AB, TB>>>((const uint4*)bufs[1], (uint4*)0, (float4*)out);
}

// round 10
// speedup vs baseline: 4.3653x; 1.0568x over previous
#include <cuda_runtime.h>
#include <cuda_fp16.h>
#include <cstdint>

#define NG 50000
#define NP 20000
#define NV 10000
#define NT 80000
#define HID 128
#define EPER 250000
#define CDIV(a,b) (((a)+(b)-1)/(b))

#define OFF_TG 0
#define OFF_IN (NG)
#define OFF_CT (NG+NP)
#define OFF_II (2*NG+NP)
#define CNTS_SZ (3*NG+NP)
#define CURZ_SZ (3*NG+NP+NT)

// padded CSR region bases for relations (each EPER + 3*n_dst)
#define RB0 0
#define RB1 (EPER + 3*NG)
#define RB2 (RB1 + EPER + 3*NP)
#define RB3 (RB2 + EPER + 3*NG)
#define RSRC_SZ (RB3 + EPER + 3*NG)
#define CSRC_SZ (4*EPER + 4*NT)

// ------------------------- device scratch -------------------------
__device__ float g_h0[NT*HID];                            // fp32 node features (hg|hp|hv)
__device__ __align__(16) __half g_h16[(NT+1)*HID];        // fp16 mirror + zero row NT
__device__ __align__(16) __half g_z16a[(NT+1)*HID];       // APPNP scaled state ping + zero row
__device__ __align__(16) __half g_z16b[(NT+1)*HID];       // pong + zero row
__device__ __align__(16) __half g_hq[NT*HID];             // 0.1*dinv*h0 (fp16)
__device__ __align__(16) __half g_sg16[NG*512];
__device__ __align__(16) __half g_sp16[NP*256];
__device__ __align__(16) __half g_wtin16[(256+128+64)*HID];
__device__ __align__(16) __half g_wtg16[512*HID];
__device__ __align__(16) __half g_wtp16[256*HID];
__device__ float g_bg[HID];
__device__ int   g_degi[NT];
__device__ float g_dinv[NT];
__device__ int   g_off[NT+1];
__device__ int   g_cnts[CNTS_SZ];
__device__ int   g_curz[CURZ_SZ];
__device__ __align__(16) int g_csrc[CSRC_SZ];
__device__ int   g_roff_tg[NG+1];
__device__ int   g_roff_in[NP+1];
__device__ int   g_roff_ct[NG+1];
__device__ int   g_roff_ii[NG+1];
__device__ __align__(16) int g_rsrc[RSRC_SZ];

__device__ __forceinline__ uint32_t h2u(__half2 h) {
    uint32_t u;
    memcpy(&u, &h, 4);
    return u;
}

// ------------------------- setup kernels -------------------------
__global__ void k_hist4(const int* __restrict__ e0, const int* __restrict__ e1,
                        const int* __restrict__ e2, const int* __restrict__ e3) {
    int t = blockIdx.x * blockDim.x + threadIdx.x;
    if (t >= 4 * EPER) return;
    int r = t / EPER, e = t - r * EPER;
    const int* ei = (r == 0) ? e0 : (r == 1) ? e1 : (r == 2) ? e2 : e3;
    int base = (r == 0) ? OFF_TG : (r == 1) ? OFF_IN : (r == 2) ? OFF_CT : OFF_II;
    atomicAdd(&g_cnts[base + ei[EPER + e]], 1);
}

__global__ void k_deg() {
    int i = blockIdx.x * blockDim.x + threadIdx.x;
    if (i >= NT) return;
    int d = 1;
    if (i < NG) d += g_cnts[OFF_TG + i] + g_cnts[OFF_CT + i] + g_cnts[OFF_II + i];
    else if (i < NG + NP) d += g_cnts[OFF_IN + (i - NG)];
    g_degi[i] = d;
    g_dinv[i] = rsqrtf((float)d);
}

// 5 exclusive scans over PADDED counts (pad each count to multiple of 4)
__global__ void k_scan5() {
    __shared__ int part[1024];
    const int* cnt; int* off; int n;
    switch (blockIdx.x) {
        case 0: cnt = g_cnts + OFF_TG; off = g_roff_tg; n = NG; break;
        case 1: cnt = g_cnts + OFF_IN; off = g_roff_in; n = NP; break;
        case 2: cnt = g_cnts + OFF_CT; off = g_roff_ct; n = NG; break;
        case 3: cnt = g_cnts + OFF_II; off = g_roff_ii; n = NG; break;
        default: cnt = g_degi; off = g_off; n = NT; break;
    }
    int t = threadIdx.x;
    int chunk = (n + 1023) / 1024;
    int lo = t * chunk, hi = min(lo + chunk, n);
    int s = 0;
    for (int i = lo; i < hi; i++) s += (cnt[i] + 3) & ~3;
    part[t] = s;
    __syncthreads();
    for (int o = 1; o < 1024; o <<= 1) {
        int x = (t >= o) ? part[t - o] : 0;
        __syncthreads();
        part[t] += x;
        __syncthreads();
    }
    int run = part[t] - s;
    for (int i = lo; i < hi; i++) { off[i] = run; run += (cnt[i] + 3) & ~3; }
    if (t == 1023) off[n] = part[1023];
}

// scatter: relation CSRs (GLOBAL src indices) + combined APPNP CSR + self loops
__global__ void k_scatter_all(const int* __restrict__ e0, const int* __restrict__ e1,
                              const int* __restrict__ e2, const int* __restrict__ e3) {
    int t = blockIdx.x * blockDim.x + threadIdx.x;
    if (t < 4 * EPER) {
        int r = t / EPER, e = t - r * EPER;
        const int* ei; const int* roff; int cbase, osrc, odst, rb;
        if (r == 0)      { ei = e0; roff = g_roff_tg; cbase = OFF_TG; osrc = NG + NP; odst = 0;  rb = RB0; }
        else if (r == 1) { ei = e1; roff = g_roff_in; cbase = OFF_IN; osrc = 0;       odst = NG; rb = RB1; }
        else if (r == 2) { ei = e2; roff = g_roff_ct; cbase = OFF_CT; osrc = NG;      odst = 0;  rb = RB2; }
        else             { ei = e3; roff = g_roff_ii; cbase = OFF_II; osrc = 0;       odst = 0;  rb = RB3; }
        int s = ei[e], d = ei[EPER + e];
        int gs = s + osrc;
        int p = roff[d] + atomicAdd(&g_curz[cbase + d], 1);
        g_rsrc[rb + p] = gs;
        int gd = d + odst;
        int p2 = g_off[gd] + atomicAdd(&g_curz[CNTS_SZ + gd], 1);
        g_csrc[p2] = gs;
    } else if (t < 4 * EPER + NT) {
        int i = t - 4 * EPER;
        int p = g_off[i] + atomicAdd(&g_curz[CNTS_SZ + i], 1);
        g_csrc[p] = i;
    }
}

// fill pad slots (indices [real, pad) of each node's segment) with zero-row index NT
__global__ void k_padfill() {
    int i = blockIdx.x * blockDim.x + threadIdx.x;
    if (i >= 3 * NG + NP + NT) return;
    const int* offp; int node, real; int* arr; int rb;
    if (i < NG)               { node = i;                 offp = g_roff_tg; real = g_cnts[OFF_TG + node]; arr = g_rsrc; rb = RB0; }
    else if (i < NG + NP)     { node = i - NG;            offp = g_roff_in; real = g_cnts[OFF_IN + node]; arr = g_rsrc; rb = RB1; }
    else if (i < 2 * NG + NP) { node = i - (NG + NP);     offp = g_roff_ct; real = g_cnts[OFF_CT + node]; arr = g_rsrc; rb = RB2; }
    else if (i < 3 * NG + NP) { node = i - (2 * NG + NP); offp = g_roff_ii; real = g_cnts[OFF_II + node]; arr = g_rsrc; rb = RB3; }
    else                      { node = i - (3 * NG + NP); offp = g_off;     real = g_degi[node];          arr = g_csrc; rb = 0;   }
    int o = rb + offp[node];
    int pad = (real + 3) & ~3;
    for (int j = real; j < pad; j++) arr[o + j] = NT;
}

// fused weight prep: input-proj fp16 copies + layer-l SAGE weight builds ([n][k] layout)
__global__ void k_prep16(const float* __restrict__ wg, const float* __restrict__ wp,
                         const float* __restrict__ wv, const float* __restrict__ wsl,
                         const float* __restrict__ wsr, const float* __restrict__ bsl,
                         int l, int do_in) {
    int idx = blockIdx.x * blockDim.x + threadIdx.x;
    const int TIN = (256 + 128 + 64) * 128;
    const int WG  = 512 * 128;
    int base = do_in ? TIN : 0;
    if (do_in && idx < TIN) {
        float v;
        if (idx < 256 * 128) v = wg[idx];
        else if (idx < (256 + 128) * 128) v = wp[idx - 256 * 128];
        else v = wv[idx - (256 + 128) * 128];
        g_wtin16[idx] = __float2half(v);
        return;
    }
    int i = idx - base;
    if (i < 0) return;
    if (i < WG) {
        int n = i >> 9, k = i & 511;
        int b = k >> 7, kk = k & 127;
        float v;
        if (b == 0)      v = wsl[((l * 4 + 0) * 128 + n) * 128 + kk];
        else if (b == 1) v = wsl[((l * 4 + 2) * 128 + n) * 128 + kk];
        else if (b == 2) v = wsl[((l * 4 + 3) * 128 + n) * 128 + kk];
        else             v = wsr[((l * 4 + 0) * 128 + n) * 128 + kk]
                           + wsr[((l * 4 + 2) * 128 + n) * 128 + kk]
                           + wsr[((l * 4 + 3) * 128 + n) * 128 + kk];
        g_wtg16[i] = __float2half(v);
        if (i < 128)
            g_bg[i] = bsl[(l * 4 + 0) * 128 + i] + bsl[(l * 4 + 2) * 128 + i]
                    + bsl[(l * 4 + 3) * 128 + i];
    } else if (i < WG + 256 * 128) {
        int j = i - WG;
        int n = j >> 8, k = j & 255;
        int b = k >> 7, kk = k & 127;
        float v = (b == 0) ? wsl[((l * 4 + 1) * 128 + n) * 128 + kk]
                           : wsr[((l * 4 + 1) * 128 + n) * 128 + kk];
        g_wtp16[j] = __float2half(v);
    }
}

// ------------------------- FP16 tensor-core GEMM (KTILE=32) -------------------------
__device__ __forceinline__ void mma_f16(float c[4], uint32_t a0, uint32_t a1,
                                        uint32_t a2, uint32_t a3,
                                        uint32_t b0, uint32_t b1) {
    asm volatile(
        "mma.sync.aligned.m16n8k16.row.col.f32.f16.f16.f32 "
        "{%0,%1,%2,%3}, {%4,%5,%6,%7}, {%8,%9}, {%0,%1,%2,%3};"
        : "+f"(c[0]), "+f"(c[1]), "+f"(c[2]), "+f"(c[3])
        : "r"(a0), "r"(a1), "r"(a2), "r"(a3), "r"(b0), "r"(b1));
}

#define SST 20
#define TBUF (128*SST)
#define GSMEM_BYTES (4*TBUF*4)

template<bool RES, bool AH>
__global__ __launch_bounds__(256)
void k_gemm16(const void* __restrict__ Araw, const __half* __restrict__ W16,
              const float* __restrict__ bias, const float* __restrict__ res,
              float* __restrict__ out, __half* __restrict__ h16out,
              __half* __restrict__ zs, __half* __restrict__ hqo,
              const float* __restrict__ dv,
              int M, int K, float scale)
{
    extern __shared__ uint32_t sm[];
    uint32_t* Asm = sm;
    uint32_t* Bsm = sm + 2 * TBUF;

    int tid  = threadIdx.x;
    int lane = tid & 31;
    int wid  = tid >> 5;
    int wm = wid >> 2;
    int wn = wid & 3;
    int g   = lane >> 2;
    int tig = lane & 3;

    int rowBase = blockIdx.x * 128;
    int r_ld  = tid >> 1;
    int hsel  = (tid & 1);

    float acc[4][4][4];
#pragma unroll
    for (int mt = 0; mt < 4; mt++)
#pragma unroll
        for (int nt = 0; nt < 4; nt++)
#pragma unroll
            for (int r = 0; r < 4; r++) acc[mt][nt][r] = 0.f;

    int ntk = K >> 5;
    int gr = rowBase + r_ld;
    const __half* Ah = (const __half*)Araw;
    const float*  Af = (const float*)Araw;

    auto loadA = [&](int k0, uint4& u0, uint4& u1) {
        if (AH) {
            if (gr < M) {
                const uint4* p = (const uint4*)&Ah[(size_t)gr * K + k0 + hsel * 16];
                u0 = p[0]; u1 = p[1];
            } else { u0 = make_uint4(0,0,0,0); u1 = make_uint4(0,0,0,0); }
        } else {
            if (gr < M) {
                const float4* p = (const float4*)&Af[(size_t)gr * K + k0 + hsel * 16];
                float4 f0 = p[0], f1 = p[1], f2 = p[2], f3 = p[3];
                uint32_t* w0 = (uint32_t*)&u0;
                uint32_t* w1 = (uint32_t*)&u1;
                w0[0] = h2u(__floats2half2_rn(f0.x, f0.y));
                w0[1] = h2u(__floats2half2_rn(f0.z, f0.w));
                w0[2] = h2u(__floats2half2_rn(f1.x, f1.y));
                w0[3] = h2u(__floats2half2_rn(f1.z, f1.w));
                w1[0] = h2u(__floats2half2_rn(f2.x, f2.y));
                w1[1] = h2u(__floats2half2_rn(f2.z, f2.w));
                w1[2] = h2u(__floats2half2_rn(f3.x, f3.y));
                w1[3] = h2u(__floats2half2_rn(f3.z, f3.w));
            } else { u0 = make_uint4(0,0,0,0); u1 = make_uint4(0,0,0,0); }
        }
    };
    auto loadB = [&](int k0, uint4& u0, uint4& u1) {
        const uint4* p = (const uint4*)&W16[(size_t)r_ld * K + k0 + hsel * 16];
        u0 = p[0]; u1 = p[1];
    };
    auto store = [&](uint32_t* buf, uint4 u0, uint4 u1) {
        int base = r_ld * SST + hsel * 8;
        *(uint4*)&buf[base] = u0;
        *(uint4*)&buf[base + 4] = u1;
    };

    {
        uint4 a0, a1, b0, b1;
        loadA(0, a0, a1);
        loadB(0, b0, b1);
        store(Asm, a0, a1);
        store(Bsm, b0, b1);
    }
    __syncthreads();

    for (int t = 0; t < ntk; t++) {
        int buf = t & 1;
        bool more = (t + 1 < ntk);
        uint4 an0, an1, bn0, bn1;
        if (more) {
            int k0 = (t + 1) << 5;
            loadA(k0, an0, an1);
            loadB(k0, bn0, bn1);
        }
        const uint32_t* Ab = Asm + buf * TBUF;
        const uint32_t* Bb = Bsm + buf * TBUF;
#pragma unroll
        for (int ks2 = 0; ks2 < 16; ks2 += 8) {
            uint32_t af[4][4], bf[4][2];
#pragma unroll
            for (int mt = 0; mt < 4; mt++) {
                int r0 = wm * 64 + mt * 16 + g;
                af[mt][0] = Ab[r0 * SST + ks2 + tig];
                af[mt][1] = Ab[(r0 + 8) * SST + ks2 + tig];
                af[mt][2] = Ab[r0 * SST + ks2 + tig + 4];
                af[mt][3] = Ab[(r0 + 8) * SST + ks2 + tig + 4];
            }
#pragma unroll
            for (int nt = 0; nt < 4; nt++) {
                int c0 = wn * 32 + nt * 8 + g;
                bf[nt][0] = Bb[c0 * SST + ks2 + tig];
                bf[nt][1] = Bb[c0 * SST + ks2 + tig + 4];
            }
#pragma unroll
            for (int mt = 0; mt < 4; mt++)
#pragma unroll
                for (int nt = 0; nt < 4; nt++)
                    mma_f16(acc[mt][nt], af[mt][0], af[mt][1], af[mt][2], af[mt][3],
                            bf[nt][0], bf[nt][1]);
        }
        if (more) {
            int nb = buf ^ 1;
            store(Asm + nb * TBUF, an0, an1);
            store(Bsm + nb * TBUF, bn0, bn1);
        }
        __syncthreads();
    }

#pragma unroll
    for (int mt = 0; mt < 4; mt++) {
#pragma unroll
        for (int nt = 0; nt < 4; nt++) {
            int col = wn * 32 + nt * 8 + tig * 2;
            float b0 = bias[col], b1 = bias[col + 1];
#pragma unroll
            for (int h = 0; h < 2; h++) {
                int row = rowBase + wm * 64 + mt * 16 + g + h * 8;
                if (row >= M) continue;
                float v0 = acc[mt][nt][h * 2 + 0] + b0;
                float v1 = acc[mt][nt][h * 2 + 1] + b1;
                if (RES) {
                    float2 rv = *(const float2*)&res[(size_t)row * HID + col];
                    v0 = rv.x + v0 * scale;
                    v1 = rv.y + v1 * scale;
                }
                v0 = fmaxf(v0, 0.f);
                v1 = fmaxf(v1, 0.f);
                float2 o; o.x = v0; o.y = v1;
                *(float2*)&out[(size_t)row * HID + col] = o;
                *(__half2*)&h16out[(size_t)row * HID + col] = __floats2half2_rn(v0, v1);
                if (zs) {
                    float d = dv[row];
                    *(__half2*)&zs[(size_t)row * HID + col] =
                        __floats2half2_rn(v0 * d, v1 * d);
                    *(__half2*)&hqo[(size_t)row * HID + col] =
                        __floats2half2_rn(0.1f * d * v0, 0.1f * d * v1);
                }
            }
        }
    }
}

// ------------------------- fp16 helpers -------------------------
__device__ __forceinline__ void h8_add(uint4 v, float a[8]) {
    const __half2* h = (const __half2*)&v;
#pragma unroll
    for (int j = 0; j < 4; j++) {
        float2 f = __half22float2(h[j]);
        a[2 * j]     += f.x;
        a[2 * j + 1] += f.y;
    }
}
__device__ __forceinline__ uint4 pack8(const float r[8]) {
    uint4 pk;
    __half2* ph = (__half2*)&pk;
    ph[0] = __floats2half2_rn(r[0], r[1]);
    ph[1] = __floats2half2_rn(r[2], r[3]);
    ph[2] = __floats2half2_rn(r[4], r[5]);
    ph[3] = __floats2half2_rn(r[6], r[7]);
    return pk;
}

// ------------------------- fused SAGE gathers (global indices, padded CSR) -------------------------
__global__ void k_gather_all() {
    int t = blockIdx.x * blockDim.x + threadIdx.x;
    int lane = t & 15, slot = t >> 4;
    if (slot >= 3 * NG + NP) return;
    const int* offp; const int* es; int real, node;
    __half* dst; int strideH, colH;
    const __half* cp = 0; int ccolH = 0;
    if (slot < NG) {
        node = slot; offp = g_roff_tg; es = g_rsrc + RB0; real = g_cnts[OFF_TG + node];
        dst = g_sg16; strideH = 512; colH = 0;
    } else if (slot < 2 * NG) {
        node = slot - NG; offp = g_roff_ct; es = g_rsrc + RB2; real = g_cnts[OFF_CT + node];
        dst = g_sg16; strideH = 512; colH = 128;
    } else if (slot < 3 * NG) {
        node = slot - 2 * NG; offp = g_roff_ii; es = g_rsrc + RB3; real = g_cnts[OFF_II + node];
        dst = g_sg16; strideH = 512; colH = 256;
        cp = g_h16; ccolH = 384;
    } else {
        node = slot - 3 * NG; offp = g_roff_in; es = g_rsrc + RB1; real = g_cnts[OFF_IN + node];
        dst = g_sp16; strideH = 256; colH = 0;
        cp = g_h16 + (size_t)NG * HID; ccolH = 128;
    }
    const uint4* x4 = (const uint4*)g_h16;
    int e0 = offp[node], e1 = offp[node + 1];
    float a[8] = {0.f, 0.f, 0.f, 0.f, 0.f, 0.f, 0.f, 0.f};
    for (int e = e0; e < e1; e += 4) {
        int4 s4 = *(const int4*)&es[e];
        uint4 v0 = __ldg(&x4[(size_t)s4.x * 16 + lane]);
        uint4 v1 = __ldg(&x4[(size_t)s4.y * 16 + lane]);
        uint4 v2 = __ldg(&x4[(size_t)s4.z * 16 + lane]);
        uint4 v3 = __ldg(&x4[(size_t)s4.w * 16 + lane]);
        h8_add(v0, a); h8_add(v1, a); h8_add(v2, a); h8_add(v3, a);
    }
    float inv = 1.f / fmaxf((float)real, 1.f);
    float r[8];
#pragma unroll
    for (int j = 0; j < 8; j++) r[j] = a[j] * inv;
    *(uint4*)&dst[(size_t)node * strideH + colH + lane * 8] = pack8(r);
    if (cp)
        *(uint4*)&dst[(size_t)node * strideH + ccolH + lane * 8] =
            ((const uint4*)cp)[(size_t)node * 16 + lane];
}

// ------------------------- APPNP step on scaled state (padded CSR) -------------------------
template<bool LAST>
__global__ void k_appnp_s(const uint4* __restrict__ z, uint4* __restrict__ zn,
                          float4* __restrict__ outf) {
    int t = blockIdx.x * blockDim.x + threadIdx.x;
    int lane = t & 15, node = t >> 4;
    if (node >= NT) return;
    int e0 = g_off[node], e1 = g_off[node + 1];
    float a[8] = {0.f, 0.f, 0.f, 0.f, 0.f, 0.f, 0.f, 0.f};
    for (int e = e0; e < e1; e += 4) {
        int4 s4 = *(const int4*)&g_csrc[e];
        uint4 v0 = __ldg(&z[(size_t)s4.x * 16 + lane]);
        uint4 v1 = __ldg(&z[(size_t)s4.y * 16 + lane]);
        uint4 v2 = __ldg(&z[(size_t)s4.z * 16 + lane]);
        uint4 v3 = __ldg(&z[(size_t)s4.w * 16 + lane]);
        h8_add(v0, a); h8_add(v1, a); h8_add(v2, a); h8_add(v3, a);
    }
    float d = g_dinv[node];
    if (LAST) {
        float c = 0.9f * d;
        const float4* h0p = (const float4*)g_h0;
        float4 ha = h0p[(size_t)node * 32 + lane * 2];
        float4 hb = h0p[(size_t)node * 32 + lane * 2 + 1];
        outf[(size_t)node * 32 + lane * 2] =
            make_float4(c * a[0] + 0.1f * ha.x, c * a[1] + 0.1f * ha.y,
                        c * a[2] + 0.1f * ha.z, c * a[3] + 0.1f * ha.w);
        outf[(size_t)node * 32 + lane * 2 + 1] =
            make_float4(c * a[4] + 0.1f * hb.x, c * a[5] + 0.1f * hb.y,
                        c * a[6] + 0.1f * hb.z, c * a[7] + 0.1f * hb.w);
    } else {
        float c1 = 0.9f * d * d;
        uint4 hqv = ((const uint4*)g_hq)[(size_t)node * 16 + lane];
        const __half2* hh = (const __half2*)&hqv;
        float r[8];
#pragma unroll
        for (int j = 0; j < 4; j++) {
            float2 f = __half22float2(hh[j]);
            r[2 * j]     = c1 * a[2 * j]     + f.x;
            r[2 * j + 1] = c1 * a[2 * j + 1] + f.y;
        }
        zn[(size_t)node * 16 + lane] = pack8(r);
    }
}

// ------------------------- host orchestration -------------------------
extern "C" void kernel_launch(void* const* d_in, const int* in_sizes, int n_in,
                              void* d_out, int out_size) {
    const float* x_gene  = (const float*)d_in[0];
    const float* x_path  = (const float*)d_in[1];
    const float* x_vacc  = (const float*)d_in[2];
    const float* win_g   = (const float*)d_in[3];
    const float* bin_g   = (const float*)d_in[4];
    const float* win_p   = (const float*)d_in[5];
    const float* bin_p   = (const float*)d_in[6];
    const float* win_v   = (const float*)d_in[7];
    const float* bin_v   = (const float*)d_in[8];
    const float* wsl     = (const float*)d_in[9];
    const float* bsl     = (const float*)d_in[10];
    const float* wsr     = (const float*)d_in[11];
    const int*   ei_t    = (const int*)d_in[12];
    const int*   ei_in   = (const int*)d_in[13];
    const int*   ei_ct   = (const int*)d_in[14];
    const int*   ei_ii   = (const int*)d_in[15];
    float* out = (float*)d_out;

    float *h0, *bg, *dinv;
    __half *h16, *z16a, *z16b, *hq, *sg16, *sp16, *wtin16, *wtg16, *wtp16;
    int *cnts, *curz;
    cudaGetSymbolAddress((void**)&h0, g_h0);
    cudaGetSymbolAddress((void**)&h16, g_h16);
    cudaGetSymbolAddress((void**)&z16a, g_z16a);
    cudaGetSymbolAddress((void**)&z16b, g_z16b);
    cudaGetSymbolAddress((void**)&hq, g_hq);
    cudaGetSymbolAddress((void**)&sg16, g_sg16);
    cudaGetSymbolAddress((void**)&sp16, g_sp16);
    cudaGetSymbolAddress((void**)&wtin16, g_wtin16);
    cudaGetSymbolAddress((void**)&wtg16, g_wtg16);
    cudaGetSymbolAddress((void**)&wtp16, g_wtp16);
    cudaGetSymbolAddress((void**)&bg,  g_bg);
    cudaGetSymbolAddress((void**)&dinv, g_dinv);
    cudaGetSymbolAddress((void**)&cnts, g_cnts);
    cudaGetSymbolAddress((void**)&curz, g_curz);

    float* hg = h0;
    float* hp = h0 + (size_t)NG * HID;
    float* hv = h0 + (size_t)(NG + NP) * HID;
    __half* hg16 = h16;
    __half* hp16 = h16 + (size_t)NG * HID;
    __half* hv16 = h16 + (size_t)(NG + NP) * HID;

    const int TB = 256;
    static bool inited = false;
    static cudaStream_t ss;
    static cudaEvent_t evFork, evSetup, evPrep, evNPproj, evStage0, evGeneL0,
                       evNP0, evP1, evStage1, evNP1;
    if (!inited) {
        cudaFuncSetAttribute(k_gemm16<false, false>, cudaFuncAttributeMaxDynamicSharedMemorySize, GSMEM_BYTES);
        cudaFuncSetAttribute(k_gemm16<true,  true>,  cudaFuncAttributeMaxDynamicSharedMemorySize, GSMEM_BYTES);
        cudaStreamCreateWithFlags(&ss, cudaStreamNonBlocking);
        cudaEventCreateWithFlags(&evFork,   cudaEventDisableTiming);
        cudaEventCreateWithFlags(&evSetup,  cudaEventDisableTiming);
        cudaEventCreateWithFlags(&evPrep,   cudaEventDisableTiming);
        cudaEventCreateWithFlags(&evNPproj, cudaEventDisableTiming);
        cudaEventCreateWithFlags(&evStage0, cudaEventDisableTiming);
        cudaEventCreateWithFlags(&evGeneL0, cudaEventDisableTiming);
        cudaEventCreateWithFlags(&evNP0,    cudaEventDisableTiming);
        cudaEventCreateWithFlags(&evP1,     cudaEventDisableTiming);
        cudaEventCreateWithFlags(&evStage1, cudaEventDisableTiming);
        cudaEventCreateWithFlags(&evNP1,    cudaEventDisableTiming);
        inited = true;
    }

    // ---------- fork: CSR setup on side stream ----------
    cudaEventRecord(evFork, 0);
    cudaStreamWaitEvent(ss, evFork, 0);
    cudaMemsetAsync(cnts, 0, CNTS_SZ * sizeof(int), ss);
    cudaMemsetAsync(curz, 0, CURZ_SZ * sizeof(int), ss);
    cudaMemsetAsync(h16 + (size_t)NT * HID,  0, HID * sizeof(__half), ss);
    cudaMemsetAsync(z16a + (size_t)NT * HID, 0, HID * sizeof(__half), ss);
    cudaMemsetAsync(z16b + (size_t)NT * HID, 0, HID * sizeof(__half), ss);
    k_hist4<<<CDIV(4 * EPER, TB), TB, 0, ss>>>(ei_t, ei_in, ei_ct, ei_ii);
    k_deg<<<CDIV(NT, TB), TB, 0, ss>>>();
    k_scan5<<<5, 1024, 0, ss>>>();
    k_scatter_all<<<CDIV(4 * EPER + NT, TB), TB, 0, ss>>>(ei_t, ei_in, ei_ct, ei_ii);
    k_padfill<<<CDIV(3 * NG + NP + NT, TB), TB, 0, ss>>>();
    cudaEventRecord(evSetup, ss);

    // ---------- main: weight prep (l=0 + input) then gene projection ----------
    const int PREP_N = (256 + 128 + 64) * 128 + 512 * 128 + 256 * 128;
    k_prep16<<<CDIV(PREP_N, TB), TB>>>(win_g, win_p, win_v, wsl, wsr, bsl, 0, 1);
    cudaEventRecord(evPrep, 0);
    k_gemm16<false, false><<<CDIV(NG, 128), 256, GSMEM_BYTES>>>(
        x_gene, wtin16, bin_g, (const float*)0, hg, hg16,
        (__half*)0, (__half*)0, (const float*)0, NG, 256, 1.f);

    // side: pathway projection (needs wtin16)
    cudaStreamWaitEvent(ss, evPrep, 0);
    k_gemm16<false, false><<<CDIV(NP, 128), 256, GSMEM_BYTES, ss>>>(
        x_path, wtin16 + 256 * 128, bin_p, (const float*)0, hp, hp16,
        (__half*)0, (__half*)0, (const float*)0, NP, 128, 1.f);
    cudaEventRecord(evNPproj, ss);

    // main: vaccine projection needs dinv (z-state emission)
    cudaStreamWaitEvent(0, evSetup, 0);
    k_gemm16<false, false><<<CDIV(NV, 128), 256, GSMEM_BYTES>>>(
        x_vacc, wtin16 + (256 + 128) * 128, bin_v, (const float*)0, hv, hv16,
        z16a + (size_t)(NG + NP) * HID, hq + (size_t)(NG + NP) * HID,
        dinv + (NG + NP), NV, 64, 1.f);

    // ---------- SAGE layer 0 ----------
    const int GALL = CDIV((3 * NG + NP) * 16, TB);
    cudaStreamWaitEvent(0, evNPproj, 0);
    k_gather_all<<<GALL, TB>>>();
    cudaEventRecord(evStage0, 0);
    k_gemm16<true, true><<<CDIV(NG, 128), 256, GSMEM_BYTES>>>(
        sg16, wtg16, bg, hg, hg, hg16, (__half*)0, (__half*)0, (const float*)0, NG, 512, 1.f / 3.f);
    cudaEventRecord(evGeneL0, 0);

    // side: pathway L0 gemm, then layer-1 weight build
    cudaStreamWaitEvent(ss, evStage0, 0);
    k_gemm16<true, true><<<CDIV(NP, 128), 256, GSMEM_BYTES, ss>>>(
        sp16, wtp16, bsl + 1 * 128, hp, hp, hp16, (__half*)0, (__half*)0, (const float*)0, NP, 256, 1.f);
    cudaEventRecord(evNP0, ss);
    cudaStreamWaitEvent(ss, evGeneL0, 0);
    k_prep16<<<CDIV(512 * 128 + 256 * 128, TB), TB, 0, ss>>>(win_g, win_p, win_v, wsl, wsr, bsl, 1, 0);
    cudaEventRecord(evP1, ss);

    // ---------- SAGE layer 1 ----------
    cudaStreamWaitEvent(0, evNP0, 0);
    k_gather_all<<<GALL, TB>>>();
    cudaEventRecord(evStage1, 0);
    cudaStreamWaitEvent(0, evP1, 0);
    k_gemm16<true, true><<<CDIV(NG, 128), 256, GSMEM_BYTES>>>(
        sg16, wtg16, bg, hg, hg, hg16, z16a, hq, dinv, NG, 512, 1.f / 3.f);

    // side: pathway L1 gemm (emits z-state)
    cudaStreamWaitEvent(ss, evStage1, 0);
    k_gemm16<true, true><<<CDIV(NP, 128), 256, GSMEM_BYTES, ss>>>(
        sp16, wtp16, bsl + (4 + 1) * 128, hp, hp, hp16,
        z16a + (size_t)NG * HID, hq + (size_t)NG * HID, dinv + NG, NP, 256, 1.f);
    cudaEventRecord(evNP1, ss);

    // ---------- 8 APPNP iterations on scaled state; last writes fp32 d_out ----------
    cudaStreamWaitEvent(0, evNP1, 0);
    const int AB = CDIV(NT * 16, TB);
    __half* bufs[2] = {z16a, z16b};
    for (int k = 0; k < 7; k++) {
        const __half* zin = bufs[k & 1];
        __half* zout = bufs[(k & 1) ^ 1];
        k_appnp_s<false><<<AB, TB>>>((const uint4*)zin, (uint4*)zout, (float4*)0);
    }
    k_appnp_s<true><<<AB, TB>>>((const uint4*)bufs[1], (uint4*)0, (float4*)out);
}

// round 11
// speedup vs baseline: 4.3778x; 1.0029x over previous
#include <cuda_runtime.h>
#include <cuda_fp16.h>
#include <cstdint>

#define NG 50000
#define NP 20000
#define NV 10000
#define NT 80000
#define HID 128
#define EPER 250000
#define CDIV(a,b) (((a)+(b)-1)/(b))

#define OFF_TG 0
#define OFF_IN (NG)
#define OFF_CT (NG+NP)
#define OFF_II (2*NG+NP)
#define CNTS_SZ (3*NG+NP)
#define CURZ_SZ (3*NG+NP+NT)

#define RB0 0
#define RB1 (EPER + 3*NG)
#define RB2 (RB1 + EPER + 3*NP)
#define RB3 (RB2 + EPER + 3*NG)
#define RSRC_SZ (RB3 + EPER + 3*NG)
#define CSRC_SZ (4*EPER + 4*NT)

// ------------------------- device scratch -------------------------
__device__ float g_h0[NT*HID];
__device__ __align__(16) __half g_h16[(NT+1)*HID];
__device__ __align__(16) __half g_z16a[(NT+1)*HID];
__device__ __align__(16) __half g_z16b[(NT+1)*HID];
__device__ __align__(16) __half g_hq[NT*HID];
__device__ __align__(16) __half g_sg16[NG*512];
__device__ __align__(16) __half g_sp16[NP*256];
__device__ __align__(16) __half g_wtin16[(256+128+64)*HID];
__device__ __align__(16) __half g_wtg16[512*HID];
__device__ __align__(16) __half g_wtp16[256*HID];
__device__ float g_bg[HID];
__device__ int   g_degi[NT];
__device__ float g_dinv[NT];
__device__ int   g_off[NT+1];
__device__ int   g_cnts[CNTS_SZ];
__device__ int   g_curz[CURZ_SZ];
__device__ __align__(16) int g_csrc[CSRC_SZ];
__device__ int   g_roff_tg[NG+1];
__device__ int   g_roff_in[NP+1];
__device__ int   g_roff_ct[NG+1];
__device__ int   g_roff_ii[NG+1];
__device__ __align__(16) int g_rsrc[RSRC_SZ];

__device__ __forceinline__ uint32_t h2u(__half2 h) {
    uint32_t u;
    memcpy(&u, &h, 4);
    return u;
}

// ------------------------- setup kernels -------------------------
__global__ void k_hist4(const int* __restrict__ e0, const int* __restrict__ e1,
                        const int* __restrict__ e2, const int* __restrict__ e3) {
    int t = blockIdx.x * blockDim.x + threadIdx.x;
    if (t >= 4 * EPER) return;
    int r = t / EPER, e = t - r * EPER;
    const int* ei = (r == 0) ? e0 : (r == 1) ? e1 : (r == 2) ? e2 : e3;
    int base = (r == 0) ? OFF_TG : (r == 1) ? OFF_IN : (r == 2) ? OFF_CT : OFF_II;
    atomicAdd(&g_cnts[base + ei[EPER + e]], 1);
}

__global__ void k_deg() {
    int i = blockIdx.x * blockDim.x + threadIdx.x;
    if (i >= NT) return;
    int d = 1;
    if (i < NG) d += g_cnts[OFF_TG + i] + g_cnts[OFF_CT + i] + g_cnts[OFF_II + i];
    else if (i < NG + NP) d += g_cnts[OFF_IN + (i - NG)];
    g_degi[i] = d;
    g_dinv[i] = rsqrtf((float)d);
}

__global__ void k_scan5() {
    __shared__ int part[1024];
    const int* cnt; int* off; int n;
    switch (blockIdx.x) {
        case 0: cnt = g_cnts + OFF_TG; off = g_roff_tg; n = NG; break;
        case 1: cnt = g_cnts + OFF_IN; off = g_roff_in; n = NP; break;
        case 2: cnt = g_cnts + OFF_CT; off = g_roff_ct; n = NG; break;
        case 3: cnt = g_cnts + OFF_II; off = g_roff_ii; n = NG; break;
        default: cnt = g_degi; off = g_off; n = NT; break;
    }
    int t = threadIdx.x;
    int chunk = (n + 1023) / 1024;
    int lo = t * chunk, hi = min(lo + chunk, n);
    int s = 0;
    for (int i = lo; i < hi; i++) s += (cnt[i] + 3) & ~3;
    part[t] = s;
    __syncthreads();
    for (int o = 1; o < 1024; o <<= 1) {
        int x = (t >= o) ? part[t - o] : 0;
        __syncthreads();
        part[t] += x;
        __syncthreads();
    }
    int run = part[t] - s;
    for (int i = lo; i < hi; i++) { off[i] = run; run += (cnt[i] + 3) & ~3; }
    if (t == 1023) off[n] = part[1023];
}

__global__ void k_scatter_all(const int* __restrict__ e0, const int* __restrict__ e1,
                              const int* __restrict__ e2, const int* __restrict__ e3) {
    int t = blockIdx.x * blockDim.x + threadIdx.x;
    if (t < 4 * EPER) {
        int r = t / EPER, e = t - r * EPER;
        const int* ei; const int* roff; int cbase, osrc, odst, rb;
        if (r == 0)      { ei = e0; roff = g_roff_tg; cbase = OFF_TG; osrc = NG + NP; odst = 0;  rb = RB0; }
        else if (r == 1) { ei = e1; roff = g_roff_in; cbase = OFF_IN; osrc = 0;       odst = NG; rb = RB1; }
        else if (r == 2) { ei = e2; roff = g_roff_ct; cbase = OFF_CT; osrc = NG;      odst = 0;  rb = RB2; }
        else             { ei = e3; roff = g_roff_ii; cbase = OFF_II; osrc = 0;       odst = 0;  rb = RB3; }
        int s = ei[e], d = ei[EPER + e];
        int gs = s + osrc;
        int p = roff[d] + atomicAdd(&g_curz[cbase + d], 1);
        g_rsrc[rb + p] = gs;
        int gd = d + odst;
        int p2 = g_off[gd] + atomicAdd(&g_curz[CNTS_SZ + gd], 1);
        g_csrc[p2] = gs;
    } else if (t < 4 * EPER + NT) {
        int i = t - 4 * EPER;
        int p = g_off[i] + atomicAdd(&g_curz[CNTS_SZ + i], 1);
        g_csrc[p] = i;
    }
}

__global__ void k_padfill() {
    int i = blockIdx.x * blockDim.x + threadIdx.x;
    if (i >= 3 * NG + NP + NT) return;
    const int* offp; int node, real; int* arr; int rb;
    if (i < NG)               { node = i;                 offp = g_roff_tg; real = g_cnts[OFF_TG + node]; arr = g_rsrc; rb = RB0; }
    else if (i < NG + NP)     { node = i - NG;            offp = g_roff_in; real = g_cnts[OFF_IN + node]; arr = g_rsrc; rb = RB1; }
    else if (i < 2 * NG + NP) { node = i - (NG + NP);     offp = g_roff_ct; real = g_cnts[OFF_CT + node]; arr = g_rsrc; rb = RB2; }
    else if (i < 3 * NG + NP) { node = i - (2 * NG + NP); offp = g_roff_ii; real = g_cnts[OFF_II + node]; arr = g_rsrc; rb = RB3; }
    else                      { node = i - (3 * NG + NP); offp = g_off;     real = g_degi[node];          arr = g_csrc; rb = 0;   }
    int o = rb + offp[node];
    int pad = (real + 3) & ~3;
    for (int j = real; j < pad; j++) arr[o + j] = NT;
}

__global__ void k_prep16(const float* __restrict__ wg, const float* __restrict__ wp,
                         const float* __restrict__ wv, const float* __restrict__ wsl,
                         const float* __restrict__ wsr, const float* __restrict__ bsl,
                         int l, int do_in) {
    int idx = blockIdx.x * blockDim.x + threadIdx.x;
    const int TIN = (256 + 128 + 64) * 128;
    const int WG  = 512 * 128;
    int base = do_in ? TIN : 0;
    if (do_in && idx < TIN) {
        float v;
        if (idx < 256 * 128) v = wg[idx];
        else if (idx < (256 + 128) * 128) v = wp[idx - 256 * 128];
        else v = wv[idx - (256 + 128) * 128];
        g_wtin16[idx] = __float2half(v);
        return;
    }
    int i = idx - base;
    if (i < 0) return;
    if (i < WG) {
        int n = i >> 9, k = i & 511;
        int b = k >> 7, kk = k & 127;
        float v;
        if (b == 0)      v = wsl[((l * 4 + 0) * 128 + n) * 128 + kk];
        else if (b == 1) v = wsl[((l * 4 + 2) * 128 + n) * 128 + kk];
        else if (b == 2) v = wsl[((l * 4 + 3) * 128 + n) * 128 + kk];
        else             v = wsr[((l * 4 + 0) * 128 + n) * 128 + kk]
                           + wsr[((l * 4 + 2) * 128 + n) * 128 + kk]
                           + wsr[((l * 4 + 3) * 128 + n) * 128 + kk];
        g_wtg16[i] = __float2half(v);
        if (i < 128)
            g_bg[i] = bsl[(l * 4 + 0) * 128 + i] + bsl[(l * 4 + 2) * 128 + i]
                    + bsl[(l * 4 + 3) * 128 + i];
    } else if (i < WG + 256 * 128) {
        int j = i - WG;
        int n = j >> 8, k = j & 255;
        int b = k >> 7, kk = k & 127;
        float v = (b == 0) ? wsl[((l * 4 + 1) * 128 + n) * 128 + kk]
                           : wsr[((l * 4 + 1) * 128 + n) * 128 + kk];
        g_wtp16[j] = __float2half(v);
    }
}

// ------------------------- FP16 tensor-core GEMM (KTILE=32) -------------------------
__device__ __forceinline__ void mma_f16(float c[4], uint32_t a0, uint32_t a1,
                                        uint32_t a2, uint32_t a3,
                                        uint32_t b0, uint32_t b1) {
    asm volatile(
        "mma.sync.aligned.m16n8k16.row.col.f32.f16.f16.f32 "
        "{%0,%1,%2,%3}, {%4,%5,%6,%7}, {%8,%9}, {%0,%1,%2,%3};"
        : "+f"(c[0]), "+f"(c[1]), "+f"(c[2]), "+f"(c[3])
        : "r"(a0), "r"(a1), "r"(a2), "r"(a3), "r"(b0), "r"(b1));
}

#define SST 20
#define TBUF (128*SST)
#define GSMEM_BYTES (4*TBUF*4)

template<bool RES, bool AH>
__global__ __launch_bounds__(256)
void k_gemm16(const void* __restrict__ Araw, const __half* __restrict__ W16,
              const float* __restrict__ bias, const float* __restrict__ res,
              float* __restrict__ out, __half* __restrict__ h16out,
              __half* __restrict__ zs, __half* __restrict__ hqo,
              const float* __restrict__ dv,
              int M, int K, float scale)
{
    extern __shared__ uint32_t sm[];
    uint32_t* Asm = sm;
    uint32_t* Bsm = sm + 2 * TBUF;

    int tid  = threadIdx.x;
    int lane = tid & 31;
    int wid  = tid >> 5;
    int wm = wid >> 2;
    int wn = wid & 3;
    int g   = lane >> 2;
    int tig = lane & 3;

    int rowBase = blockIdx.x * 128;
    int r_ld  = tid >> 1;
    int hsel  = (tid & 1);

    float acc[4][4][4];
#pragma unroll
    for (int mt = 0; mt < 4; mt++)
#pragma unroll
        for (int nt = 0; nt < 4; nt++)
#pragma unroll
            for (int r = 0; r < 4; r++) acc[mt][nt][r] = 0.f;

    int ntk = K >> 5;
    int gr = rowBase + r_ld;
    const __half* Ah = (const __half*)Araw;
    const float*  Af = (const float*)Araw;

    auto loadA = [&](int k0, uint4& u0, uint4& u1) {
        if (AH) {
            if (gr < M) {
                const uint4* p = (const uint4*)&Ah[(size_t)gr * K + k0 + hsel * 16];
                u0 = p[0]; u1 = p[1];
            } else { u0 = make_uint4(0,0,0,0); u1 = make_uint4(0,0,0,0); }
        } else {
            if (gr < M) {
                const float4* p = (const float4*)&Af[(size_t)gr * K + k0 + hsel * 16];
                float4 f0 = p[0], f1 = p[1], f2 = p[2], f3 = p[3];
                uint32_t* w0 = (uint32_t*)&u0;
                uint32_t* w1 = (uint32_t*)&u1;
                w0[0] = h2u(__floats2half2_rn(f0.x, f0.y));
                w0[1] = h2u(__floats2half2_rn(f0.z, f0.w));
                w0[2] = h2u(__floats2half2_rn(f1.x, f1.y));
                w0[3] = h2u(__floats2half2_rn(f1.z, f1.w));
                w1[0] = h2u(__floats2half2_rn(f2.x, f2.y));
                w1[1] = h2u(__floats2half2_rn(f2.z, f2.w));
                w1[2] = h2u(__floats2half2_rn(f3.x, f3.y));
                w1[3] = h2u(__floats2half2_rn(f3.z, f3.w));
            } else { u0 = make_uint4(0,0,0,0); u1 = make_uint4(0,0,0,0); }
        }
    };
    auto loadB = [&](int k0, uint4& u0, uint4& u1) {
        const uint4* p = (const uint4*)&W16[(size_t)r_ld * K + k0 + hsel * 16];
        u0 = p[0]; u1 = p[1];
    };
    auto store = [&](uint32_t* buf, uint4 u0, uint4 u1) {
        int base = r_ld * SST + hsel * 8;
        *(uint4*)&buf[base] = u0;
        *(uint4*)&buf[base + 4] = u1;
    };

    {
        uint4 a0, a1, b0, b1;
        loadA(0, a0, a1);
        loadB(0, b0, b1);
        store(Asm, a0, a1);
        store(Bsm, b0, b1);
    }
    __syncthreads();

    for (int t = 0; t < ntk; t++) {
        int buf = t & 1;
        bool more = (t + 1 < ntk);
        uint4 an0, an1, bn0, bn1;
        if (more) {
            int k0 = (t + 1) << 5;
            loadA(k0, an0, an1);
            loadB(k0, bn0, bn1);
        }
        const uint32_t* Ab = Asm + buf * TBUF;
        const uint32_t* Bb = Bsm + buf * TBUF;
#pragma unroll
        for (int ks2 = 0; ks2 < 16; ks2 += 8) {
            uint32_t af[4][4], bf[4][2];
#pragma unroll
            for (int mt = 0; mt < 4; mt++) {
                int r0 = wm * 64 + mt * 16 + g;
                af[mt][0] = Ab[r0 * SST + ks2 + tig];
                af[mt][1] = Ab[(r0 + 8) * SST + ks2 + tig];
                af[mt][2] = Ab[r0 * SST + ks2 + tig + 4];
                af[mt][3] = Ab[(r0 + 8) * SST + ks2 + tig + 4];
            }
#pragma unroll
            for (int nt = 0; nt < 4; nt++) {
                int c0 = wn * 32 + nt * 8 + g;
                bf[nt][0] = Bb[c0 * SST + ks2 + tig];
                bf[nt][1] = Bb[c0 * SST + ks2 + tig + 4];
            }
#pragma unroll
            for (int mt = 0; mt < 4; mt++)
#pragma unroll
                for (int nt = 0; nt < 4; nt++)
                    mma_f16(acc[mt][nt], af[mt][0], af[mt][1], af[mt][2], af[mt][3],
                            bf[nt][0], bf[nt][1]);
        }
        if (more) {
            int nb = buf ^ 1;
            store(Asm + nb * TBUF, an0, an1);
            store(Bsm + nb * TBUF, bn0, bn1);
        }
        __syncthreads();
    }

#pragma unroll
    for (int mt = 0; mt < 4; mt++) {
#pragma unroll
        for (int nt = 0; nt < 4; nt++) {
            int col = wn * 32 + nt * 8 + tig * 2;
            float b0 = bias[col], b1 = bias[col + 1];
#pragma unroll
            for (int h = 0; h < 2; h++) {
                int row = rowBase + wm * 64 + mt * 16 + g + h * 8;
                if (row >= M) continue;
                float v0 = acc[mt][nt][h * 2 + 0] + b0;
                float v1 = acc[mt][nt][h * 2 + 1] + b1;
                if (RES) {
                    float2 rv = *(const float2*)&res[(size_t)row * HID + col];
                    v0 = rv.x + v0 * scale;
                    v1 = rv.y + v1 * scale;
                }
                v0 = fmaxf(v0, 0.f);
                v1 = fmaxf(v1, 0.f);
                float2 o; o.x = v0; o.y = v1;
                *(float2*)&out[(size_t)row * HID + col] = o;
                *(__half2*)&h16out[(size_t)row * HID + col] = __floats2half2_rn(v0, v1);
                if (zs) {
                    float d = dv[row];
                    *(__half2*)&zs[(size_t)row * HID + col] =
                        __floats2half2_rn(v0 * d, v1 * d);
                    *(__half2*)&hqo[(size_t)row * HID + col] =
                        __floats2half2_rn(0.1f * d * v0, 0.1f * d * v1);
                }
            }
        }
    }
}

// ------------------------- fp16 helpers -------------------------
__device__ __forceinline__ void h8_add(uint4 v, float a[8]) {
    const __half2* h = (const __half2*)&v;
#pragma unroll
    for (int j = 0; j < 4; j++) {
        float2 f = __half22float2(h[j]);
        a[2 * j]     += f.x;
        a[2 * j + 1] += f.y;
    }
}
// packed half2 add of two uint4 (8 halves): 4 HADD2
__device__ __forceinline__ uint4 hadd4(uint4 a, uint4 b) {
    const __half2* x = (const __half2*)&a;
    const __half2* y = (const __half2*)&b;
    uint4 r;
    __half2* z = (__half2*)&r;
    z[0] = __hadd2(x[0], y[0]);
    z[1] = __hadd2(x[1], y[1]);
    z[2] = __hadd2(x[2], y[2]);
    z[3] = __hadd2(x[3], y[3]);
    return r;
}
__device__ __forceinline__ uint4 pack8(const float r[8]) {
    uint4 pk;
    __half2* ph = (__half2*)&pk;
    ph[0] = __floats2half2_rn(r[0], r[1]);
    ph[1] = __floats2half2_rn(r[2], r[3]);
    ph[2] = __floats2half2_rn(r[4], r[5]);
    ph[3] = __floats2half2_rn(r[6], r[7]);
    return pk;
}

// ------------------------- fused SAGE gathers (padded CSR, fp16 tree-add) -------------------------
__global__ void k_gather_all() {
    int t = blockIdx.x * blockDim.x + threadIdx.x;
    int lane = t & 15, slot = t >> 4;
    if (slot >= 3 * NG + NP) return;
    const int* offp; const int* es; int real, node;
    __half* dst; int strideH, colH;
    const __half* cp = 0; int ccolH = 0;
    if (slot < NG) {
        node = slot; offp = g_roff_tg; es = g_rsrc + RB0; real = g_cnts[OFF_TG + node];
        dst = g_sg16; strideH = 512; colH = 0;
    } else if (slot < 2 * NG) {
        node = slot - NG; offp = g_roff_ct; es = g_rsrc + RB2; real = g_cnts[OFF_CT + node];
        dst = g_sg16; strideH = 512; colH = 128;
    } else if (slot < 3 * NG) {
        node = slot - 2 * NG; offp = g_roff_ii; es = g_rsrc + RB3; real = g_cnts[OFF_II + node];
        dst = g_sg16; strideH = 512; colH = 256;
        cp = g_h16; ccolH = 384;
    } else {
        node = slot - 3 * NG; offp = g_roff_in; es = g_rsrc + RB1; real = g_cnts[OFF_IN + node];
        dst = g_sp16; strideH = 256; colH = 0;
        cp = g_h16 + (size_t)NG * HID; ccolH = 128;
    }
    const uint4* x4 = (const uint4*)g_h16;
    int e0 = offp[node], e1 = offp[node + 1];
    float a[8] = {0.f, 0.f, 0.f, 0.f, 0.f, 0.f, 0.f, 0.f};
    for (int e = e0; e < e1; e += 4) {
        int4 s4 = *(const int4*)&es[e];
        uint4 v0 = __ldg(&x4[(size_t)s4.x * 16 + lane]);
        uint4 v1 = __ldg(&x4[(size_t)s4.y * 16 + lane]);
        uint4 v2 = __ldg(&x4[(size_t)s4.z * 16 + lane]);
        uint4 v3 = __ldg(&x4[(size_t)s4.w * 16 + lane]);
        uint4 h = hadd4(hadd4(v0, v1), hadd4(v2, v3));
        h8_add(h, a);
    }
    float inv = 1.f / fmaxf((float)real, 1.f);
    float r[8];
#pragma unroll
    for (int j = 0; j < 8; j++) r[j] = a[j] * inv;
    *(uint4*)&dst[(size_t)node * strideH + colH + lane * 8] = pack8(r);
    if (cp)
        *(uint4*)&dst[(size_t)node * strideH + ccolH + lane * 8] =
            ((const uint4*)cp)[(size_t)node * 16 + lane];
}

// ------------------------- APPNP step (padded CSR, fp16 tree-add) -------------------------
template<bool LAST>
__global__ void k_appnp_s(const uint4* __restrict__ z, uint4* __restrict__ zn,
                          float4* __restrict__ outf) {
    int t = blockIdx.x * blockDim.x + threadIdx.x;
    int lane = t & 15, node = t >> 4;
    if (node >= NT) return;
    int e0 = g_off[node], e1 = g_off[node + 1];
    float a[8] = {0.f, 0.f, 0.f, 0.f, 0.f, 0.f, 0.f, 0.f};
    for (int e = e0; e < e1; e += 4) {
        int4 s4 = *(const int4*)&g_csrc[e];
        uint4 v0 = __ldg(&z[(size_t)s4.x * 16 + lane]);
        uint4 v1 = __ldg(&z[(size_t)s4.y * 16 + lane]);
        uint4 v2 = __ldg(&z[(size_t)s4.z * 16 + lane]);
        uint4 v3 = __ldg(&z[(size_t)s4.w * 16 + lane]);
        uint4 h = hadd4(hadd4(v0, v1), hadd4(v2, v3));
        h8_add(h, a);
    }
    float d = g_dinv[node];
    if (LAST) {
        float c = 0.9f * d;
        const float4* h0p = (const float4*)g_h0;
        float4 ha = h0p[(size_t)node * 32 + lane * 2];
        float4 hb = h0p[(size_t)node * 32 + lane * 2 + 1];
        outf[(size_t)node * 32 + lane * 2] =
            make_float4(c * a[0] + 0.1f * ha.x, c * a[1] + 0.1f * ha.y,
                        c * a[2] + 0.1f * ha.z, c * a[3] + 0.1f * ha.w);
        outf[(size_t)node * 32 + lane * 2 + 1] =
            make_float4(c * a[4] + 0.1f * hb.x, c * a[5] + 0.1f * hb.y,
                        c * a[6] + 0.1f * hb.z, c * a[7] + 0.1f * hb.w);
    } else {
        float c1 = 0.9f * d * d;
        uint4 hqv = ((const uint4*)g_hq)[(size_t)node * 16 + lane];
        const __half2* hh = (const __half2*)&hqv;
        float r[8];
#pragma unroll
        for (int j = 0; j < 4; j++) {
            float2 f = __half22float2(hh[j]);
            r[2 * j]     = c1 * a[2 * j]     + f.x;
            r[2 * j + 1] = c1 * a[2 * j + 1] + f.y;
        }
        zn[(size_t)node * 16 + lane] = pack8(r);
    }
}

// ------------------------- host orchestration -------------------------
extern "C" void kernel_launch(void* const* d_in, const int* in_sizes, int n_in,
                              void* d_out, int out_size) {
    const float* x_gene  = (const float*)d_in[0];
    const float* x_path  = (const float*)d_in[1];
    const float* x_vacc  = (const float*)d_in[2];
    const float* win_g   = (const float*)d_in[3];
    const float* bin_g   = (const float*)d_in[4];
    const float* win_p   = (const float*)d_in[5];
    const float* bin_p   = (const float*)d_in[6];
    const float* win_v   = (const float*)d_in[7];
    const float* bin_v   = (const float*)d_in[8];
    const float* wsl     = (const float*)d_in[9];
    const float* bsl     = (const float*)d_in[10];
    const float* wsr     = (const float*)d_in[11];
    const int*   ei_t    = (const int*)d_in[12];
    const int*   ei_in   = (const int*)d_in[13];
    const int*   ei_ct   = (const int*)d_in[14];
    const int*   ei_ii   = (const int*)d_in[15];
    float* out = (float*)d_out;

    float *h0, *bg, *dinv;
    __half *h16, *z16a, *z16b, *hq, *sg16, *sp16, *wtin16, *wtg16, *wtp16;
    int *cnts, *curz;
    cudaGetSymbolAddress((void**)&h0, g_h0);
    cudaGetSymbolAddress((void**)&h16, g_h16);
    cudaGetSymbolAddress((void**)&z16a, g_z16a);
    cudaGetSymbolAddress((void**)&z16b, g_z16b);
    cudaGetSymbolAddress((void**)&hq, g_hq);
    cudaGetSymbolAddress((void**)&sg16, g_sg16);
    cudaGetSymbolAddress((void**)&sp16, g_sp16);
    cudaGetSymbolAddress((void**)&wtin16, g_wtin16);
    cudaGetSymbolAddress((void**)&wtg16, g_wtg16);
    cudaGetSymbolAddress((void**)&wtp16, g_wtp16);
    cudaGetSymbolAddress((void**)&bg,  g_bg);
    cudaGetSymbolAddress((void**)&dinv, g_dinv);
    cudaGetSymbolAddress((void**)&cnts, g_cnts);
    cudaGetSymbolAddress((void**)&curz, g_curz);

    float* hg = h0;
    float* hp = h0 + (size_t)NG * HID;
    float* hv = h0 + (size_t)(NG + NP) * HID;
    __half* hg16 = h16;
    __half* hp16 = h16 + (size_t)NG * HID;
    __half* hv16 = h16 + (size_t)(NG + NP) * HID;

    const int TB = 256;
    static bool inited = false;
    static cudaStream_t ss;
    static cudaEvent_t evFork, evSetup, evPrep, evNPproj, evStage0, evGeneL0,
                       evNP0, evP1, evStage1, evNP1;
    if (!inited) {
        cudaFuncSetAttribute(k_gemm16<false, false>, cudaFuncAttributeMaxDynamicSharedMemorySize, GSMEM_BYTES);
        cudaFuncSetAttribute(k_gemm16<true,  true>,  cudaFuncAttributeMaxDynamicSharedMemorySize, GSMEM_BYTES);
        cudaStreamCreateWithFlags(&ss, cudaStreamNonBlocking);
        cudaEventCreateWithFlags(&evFork,   cudaEventDisableTiming);
        cudaEventCreateWithFlags(&evSetup,  cudaEventDisableTiming);
        cudaEventCreateWithFlags(&evPrep,   cudaEventDisableTiming);
        cudaEventCreateWithFlags(&evNPproj, cudaEventDisableTiming);
        cudaEventCreateWithFlags(&evStage0, cudaEventDisableTiming);
        cudaEventCreateWithFlags(&evGeneL0, cudaEventDisableTiming);
        cudaEventCreateWithFlags(&evNP0,    cudaEventDisableTiming);
        cudaEventCreateWithFlags(&evP1,     cudaEventDisableTiming);
        cudaEventCreateWithFlags(&evStage1, cudaEventDisableTiming);
        cudaEventCreateWithFlags(&evNP1,    cudaEventDisableTiming);
        inited = true;
    }

    // ---------- fork: CSR setup on side stream ----------
    cudaEventRecord(evFork, 0);
    cudaStreamWaitEvent(ss, evFork, 0);
    cudaMemsetAsync(cnts, 0, CNTS_SZ * sizeof(int), ss);
    cudaMemsetAsync(curz, 0, CURZ_SZ * sizeof(int), ss);
    cudaMemsetAsync(h16 + (size_t)NT * HID,  0, HID * sizeof(__half), ss);
    cudaMemsetAsync(z16a + (size_t)NT * HID, 0, HID * sizeof(__half), ss);
    cudaMemsetAsync(z16b + (size_t)NT * HID, 0, HID * sizeof(__half), ss);
    k_hist4<<<CDIV(4 * EPER, TB), TB, 0, ss>>>(ei_t, ei_in, ei_ct, ei_ii);
    k_deg<<<CDIV(NT, TB), TB, 0, ss>>>();
    k_scan5<<<5, 1024, 0, ss>>>();
    k_scatter_all<<<CDIV(4 * EPER + NT, TB), TB, 0, ss>>>(ei_t, ei_in, ei_ct, ei_ii);
    k_padfill<<<CDIV(3 * NG + NP + NT, TB), TB, 0, ss>>>();
    cudaEventRecord(evSetup, ss);

    // ---------- main: weight prep (l=0 + input) then gene projection ----------
    const int PREP_N = (256 + 128 + 64) * 128 + 512 * 128 + 256 * 128;
    k_prep16<<<CDIV(PREP_N, TB), TB>>>(win_g, win_p, win_v, wsl, wsr, bsl, 0, 1);
    cudaEventRecord(evPrep, 0);
    k_gemm16<false, false><<<CDIV(NG, 128), 256, GSMEM_BYTES>>>(
        x_gene, wtin16, bin_g, (const float*)0, hg, hg16,
        (__half*)0, (__half*)0, (const float*)0, NG, 256, 1.f);

    // side: pathway projection (needs wtin16)
    cudaStreamWaitEvent(ss, evPrep, 0);
    k_gemm16<false, false><<<CDIV(NP, 128), 256, GSMEM_BYTES, ss>>>(
        x_path, wtin16 + 256 * 128, bin_p, (const float*)0, hp, hp16,
        (__half*)0, (__half*)0, (const float*)0, NP, 128, 1.f);
    cudaEventRecord(evNPproj, ss);

    // main: vaccine projection needs dinv (z-state emission)
    cudaStreamWaitEvent(0, evSetup, 0);
    k_gemm16<false, false><<<CDIV(NV, 128), 256, GSMEM_BYTES>>>(
        x_vacc, wtin16 + (256 + 128) * 128, bin_v, (const float*)0, hv, hv16,
        z16a + (size_t)(NG + NP) * HID, hq + (size_t)(NG + NP) * HID,
        dinv + (NG + NP), NV, 64, 1.f);

    // ---------- SAGE layer 0 ----------
    const int GALL = CDIV((3 * NG + NP) * 16, TB);
    cudaStreamWaitEvent(0, evNPproj, 0);
    k_gather_all<<<GALL, TB>>>();
    cudaEventRecord(evStage0, 0);
    k_gemm16<true, true><<<CDIV(NG, 128), 256, GSMEM_BYTES>>>(
        sg16, wtg16, bg, hg, hg, hg16, (__half*)0, (__half*)0, (const float*)0, NG, 512, 1.f / 3.f);
    cudaEventRecord(evGeneL0, 0);

    // side: pathway L0 gemm, then layer-1 weight build
    cudaStreamWaitEvent(ss, evStage0, 0);
    k_gemm16<true, true><<<CDIV(NP, 128), 256, GSMEM_BYTES, ss>>>(
        sp16, wtp16, bsl + 1 * 128, hp, hp, hp16, (__half*)0, (__half*)0, (const float*)0, NP, 256, 1.f);
    cudaEventRecord(evNP0, ss);
    cudaStreamWaitEvent(ss, evGeneL0, 0);
    k_prep16<<<CDIV(512 * 128 + 256 * 128, TB), TB, 0, ss>>>(win_g, win_p, win_v, wsl, wsr, bsl, 1, 0);
    cudaEventRecord(evP1, ss);

    // ---------- SAGE layer 1 ----------
    cudaStreamWaitEvent(0, evNP0, 0);
    k_gather_all<<<GALL, TB>>>();
    cudaEventRecord(evStage1, 0);
    cudaStreamWaitEvent(0, evP1, 0);
    k_gemm16<true, true><<<CDIV(NG, 128), 256, GSMEM_BYTES>>>(
        sg16, wtg16, bg, hg, hg, hg16, z16a, hq, dinv, NG, 512, 1.f / 3.f);

    // side: pathway L1 gemm (emits z-state)
    cudaStreamWaitEvent(ss, evStage1, 0);
    k_gemm16<true, true><<<CDIV(NP, 128), 256, GSMEM_BYTES, ss>>>(
        sp16, wtp16, bsl + (4 + 1) * 128, hp, hp, hp16,
        z16a + (size_t)NG * HID, hq + (size_t)NG * HID, dinv + NG, NP, 256, 1.f);
    cudaEventRecord(evNP1, ss);

    // ---------- 8 APPNP iterations on scaled state; last writes fp32 d_out ----------
    cudaStreamWaitEvent(0, evNP1, 0);
    const int AB = CDIV(NT * 16, TB);
    __half* bufs[2] = {z16a, z16b};
    for (int k = 0; k < 7; k++) {
        const __half* zin = bufs[k & 1];
        __half* zout = bufs[(k & 1) ^ 1];
        k_appnp_s<false><<<AB, TB>>>((const uint4*)zin, (uint4*)zout, (float4*)0);
    }
    k_appnp_s<true><<<AB, TB>>>((const uint4*)bufs[1], (uint4*)0, (float4*)out);
}